// round 2
// baseline (speedup 1.0000x reference)
#include <cuda_runtime.h>
#include <math.h>

// ---------------------------------------------------------------------------
// SwinBlock: B=8, H=W=256, C=96, WS=8, SS=4, NH=3, hd=32, DFF=384
// rows (window-token order) M = 8*256*256 = 524288
// ---------------------------------------------------------------------------

#define MROWS 524288

// scratch (static device allocations are the sanctioned workaround)
// g_qkv: qkv projections (288 wide); after attention consumes it, its first
//        96-wide stripe region is reused for x1 (residual-1, pixel order).
// g_a  : LN1+window-partition output; reused for LN2 output after QKV GEMM.
// g_b  : attention output (window order).
// g_h1 : fc1+gelu output.
__device__ float g_qkv[MROWS * 288];
__device__ float g_x1 [MROWS *  96];
__device__ float g_a  [MROWS *  96];
__device__ float g_b  [MROWS *  96];
__device__ float g_h1 [MROWS * 384];

// ---------------------------------------------------------------------------
// LayerNorm over C=96: one warp per row. REMAP=true applies the cyclic shift
// (-SS,-SS) + window partition gather (reads pixel order, writes window order).
// ---------------------------------------------------------------------------
template<bool REMAP>
__global__ void __launch_bounds__(256) ln_kernel(
    const float* __restrict__ x, const float* __restrict__ w,
    const float* __restrict__ b, float* __restrict__ out)
{
    int row  = blockIdx.x * 8 + (threadIdx.x >> 5);
    int lane = threadIdx.x & 31;

    size_t src;
    if (REMAP) {
        int b_ = row >> 6, n = row & 63;
        int bb = b_ >> 10, wh = (b_ >> 5) & 31, ww = b_ & 31;
        int i = n >> 3, j = n & 7;
        int hh = (wh * 8 + i + 4) & 255;     // roll(-4): src = dst+4 mod 256
        int wp = (ww * 8 + j + 4) & 255;
        src = ((size_t)bb * 65536 + (size_t)hh * 256 + wp) * 96;
    } else {
        src = (size_t)row * 96;
    }

    float v0 = x[src + lane], v1 = x[src + lane + 32], v2 = x[src + lane + 64];
    float s = v0 + v1 + v2;
    #pragma unroll
    for (int o = 16; o > 0; o >>= 1) s += __shfl_xor_sync(0xffffffffu, s, o);
    float mean = s * (1.0f / 96.0f);
    float d0 = v0 - mean, d1 = v1 - mean, d2 = v2 - mean;
    float vv = d0 * d0 + d1 * d1 + d2 * d2;
    #pragma unroll
    for (int o = 16; o > 0; o >>= 1) vv += __shfl_xor_sync(0xffffffffu, vv, o);
    float rstd = rsqrtf(vv * (1.0f / 96.0f) + 1e-5f);

    size_t dst = (size_t)row * 96;
    out[dst + lane]      = d0 * rstd * w[lane]      + b[lane];
    out[dst + lane + 32] = d1 * rstd * w[lane + 32] + b[lane + 32];
    out[dst + lane + 64] = d2 * rstd * w[lane + 64] + b[lane + 64];
}

// ---------------------------------------------------------------------------
// SGEMM: C[M,N] = A[M,K] @ B[N,K]^T + bias, with fused epilogues.
// BM=64, BN=96, BK=32, 256 threads, 4x6 per-thread tile. All dims divide.
// EPI 0: store            (qkv)
// EPI 1: gelu (exact)     (fc1)
// EPI 2: scatter window-reverse + roll(+4) + residual from res (=x)  (proj)
// EPI 3: residual from res (=x1), C = final out                      (fc2)
// ---------------------------------------------------------------------------
constexpr int BM = 64, BN = 96, BK = 32, TM = 4, TN = 6;

__device__ __forceinline__ size_t dest_pixel(int r)
{
    int b_ = r >> 6, n = r & 63;
    int bb = b_ >> 10, wh = (b_ >> 5) & 31, ww = b_ & 31;
    int i = n >> 3, j = n & 7;
    int hh = (wh * 8 + i + 4) & 255;         // window reverse then roll(+4)
    int wp = (ww * 8 + j + 4) & 255;
    return (size_t)bb * 65536 + (size_t)hh * 256 + wp;
}

template<int EPI>
__global__ void __launch_bounds__(256) sgemm_kernel(
    const float* __restrict__ A, const float* __restrict__ B,
    const float* __restrict__ bias, float* __restrict__ C,
    const float* __restrict__ res, int K, int N)
{
    __shared__ __align__(16) float As[BK][BM];
    __shared__ __align__(16) float Bs[BK][BN];

    const int tid = threadIdx.x;
    const int tr = tid >> 4, tc = tid & 15;
    const long long rowBase = (long long)blockIdx.x * BM;
    const int colBase = blockIdx.y * BN;

    float acc[TM][TN];
    #pragma unroll
    for (int i = 0; i < TM; i++)
        #pragma unroll
        for (int j = 0; j < TN; j++) acc[i][j] = 0.0f;

    for (int k0 = 0; k0 < K; k0 += BK) {
        // A tile: 64 rows x 32 k = 512 float4 slots
        #pragma unroll
        for (int q = 0; q < 2; q++) {
            int slot = tid + q * 256;
            int m = slot >> 3, kq = slot & 7;
            float4 v = *reinterpret_cast<const float4*>(
                A + (rowBase + m) * K + k0 + kq * 4);
            As[kq * 4 + 0][m] = v.x; As[kq * 4 + 1][m] = v.y;
            As[kq * 4 + 2][m] = v.z; As[kq * 4 + 3][m] = v.w;
        }
        // B tile: 96 rows x 32 k = 768 float4 slots
        #pragma unroll
        for (int q = 0; q < 3; q++) {
            int slot = tid + q * 256;
            int nn = slot >> 3, kq = slot & 7;
            float4 v = *reinterpret_cast<const float4*>(
                B + (size_t)(colBase + nn) * K + k0 + kq * 4);
            Bs[kq * 4 + 0][nn] = v.x; Bs[kq * 4 + 1][nn] = v.y;
            Bs[kq * 4 + 2][nn] = v.z; Bs[kq * 4 + 3][nn] = v.w;
        }
        __syncthreads();

        #pragma unroll
        for (int kk = 0; kk < BK; kk++) {
            float4 a4 = *reinterpret_cast<const float4*>(&As[kk][tr * TM]);
            float a[TM] = {a4.x, a4.y, a4.z, a4.w};
            float bv[TN];
            #pragma unroll
            for (int j = 0; j < TN; j++) bv[j] = Bs[kk][tc * TN + j];
            #pragma unroll
            for (int i = 0; i < TM; i++)
                #pragma unroll
                for (int j = 0; j < TN; j++)
                    acc[i][j] = fmaf(a[i], bv[j], acc[i][j]);
        }
        __syncthreads();
    }

    #pragma unroll
    for (int i = 0; i < TM; i++) {
        long long m = rowBase + tr * TM + i;
        size_t drow = 0;
        if (EPI == 2) drow = dest_pixel((int)m) * 96;
        #pragma unroll
        for (int j = 0; j < TN; j++) {
            int nn = colBase + tc * TN + j;
            float v = acc[i][j] + bias[nn];
            if (EPI == 0) {
                C[m * N + nn] = v;
            } else if (EPI == 1) {
                C[m * N + nn] = 0.5f * v * (1.0f + erff(v * 0.70710678118654752f));
            } else if (EPI == 2) {
                size_t d = drow + nn;
                C[d] = res[d] + v;
            } else {
                size_t d = (size_t)m * 96 + nn;
                C[d] = res[d] + v;
            }
        }
    }
}

// ---------------------------------------------------------------------------
// Window attention: one block per (window b_, head h). 64 threads = one
// softmax row per lane. K/V in smem (float4 broadcast reads), scores kept in
// smem column-per-thread. Relative-position bias gathered from table; shift
// mask computed analytically from window coordinates.
// ---------------------------------------------------------------------------
__device__ __forceinline__ int regid(int g)
{
    return g < 248 ? 0 : (g < 252 ? 1 : 2);
}

__global__ void __launch_bounds__(64) attn_kernel(
    const float* __restrict__ qkv, const float* __restrict__ rpb,
    float* __restrict__ ow)
{
    __shared__ __align__(16) float ks[64][32];
    __shared__ __align__(16) float vs[64][32];
    __shared__ float ss[64][64];
    __shared__ float rpbs[225];
    __shared__ int   ids[64];

    const int b_ = blockIdx.x;   // 0..8191
    const int h  = blockIdx.y;   // 0..2
    const int n  = threadIdx.x;  // 0..63

    for (int t = n; t < 225; t += 64) rpbs[t] = rpb[t * 3 + h];

    const int wh = (b_ >> 5) & 31, ww = b_ & 31;
    const int i_n = n >> 3, j_n = n & 7;
    const int id_n = regid(wh * 8 + i_n) * 3 + regid(ww * 8 + j_n);
    ids[n] = id_n;

    const float* base = qkv + (size_t)b_ * 64 * 288;
    float q[32];
    {
        const float4* qp = reinterpret_cast<const float4*>(base + n * 288 + h * 32);
        #pragma unroll
        for (int t = 0; t < 8; t++) {
            float4 v = qp[t];
            q[4*t] = v.x; q[4*t+1] = v.y; q[4*t+2] = v.z; q[4*t+3] = v.w;
        }
        const float4* kp = reinterpret_cast<const float4*>(base + n * 288 + 96 + h * 32);
        float4* kd = reinterpret_cast<float4*>(&ks[n][0]);
        #pragma unroll
        for (int t = 0; t < 8; t++) kd[t] = kp[t];
        const float4* vp = reinterpret_cast<const float4*>(base + n * 288 + 192 + h * 32);
        float4* vd = reinterpret_cast<float4*>(&vs[n][0]);
        #pragma unroll
        for (int t = 0; t < 8; t++) vd[t] = vp[t];
    }
    __syncthreads();

    const float scale = 0.17677669529663687f;  // 1/sqrt(32)

    float mx = -1e30f;
    for (int j = 0; j < 64; j++) {
        const float4* kr = reinterpret_cast<const float4*>(&ks[j][0]);
        float acc = 0.0f;
        #pragma unroll
        for (int t = 0; t < 8; t++) {
            float4 kv = kr[t];
            acc = fmaf(q[4*t],   kv.x, acc);
            acc = fmaf(q[4*t+1], kv.y, acc);
            acc = fmaf(q[4*t+2], kv.z, acc);
            acc = fmaf(q[4*t+3], kv.w, acc);
        }
        int i_j = j >> 3, j_j = j & 7;
        float bias = rpbs[(i_n - i_j + 7) * 15 + (j_n - j_j + 7)];
        float s = fmaf(acc, scale, bias) + (ids[j] == id_n ? 0.0f : -100.0f);
        ss[j][n] = s;
        mx = fmaxf(mx, s);
    }
    // each lane only touches its own ss column -> no block sync required
    float sum = 0.0f;
    for (int j = 0; j < 64; j++) {
        float p = expf(ss[j][n] - mx);
        ss[j][n] = p;
        sum += p;
    }
    float inv = 1.0f / sum;

    float o[32];
    #pragma unroll
    for (int d = 0; d < 32; d++) o[d] = 0.0f;
    for (int j = 0; j < 64; j++) {
        float p = ss[j][n];
        const float4* vr = reinterpret_cast<const float4*>(&vs[j][0]);
        #pragma unroll
        for (int t = 0; t < 8; t++) {
            float4 vv = vr[t];
            o[4*t]   = fmaf(p, vv.x, o[4*t]);
            o[4*t+1] = fmaf(p, vv.y, o[4*t+1]);
            o[4*t+2] = fmaf(p, vv.z, o[4*t+2]);
            o[4*t+3] = fmaf(p, vv.w, o[4*t+3]);
        }
    }

    float4* o4 = reinterpret_cast<float4*>(ow + ((size_t)b_ * 64 + n) * 96 + h * 32);
    #pragma unroll
    for (int t = 0; t < 8; t++) {
        float4 v;
        v.x = o[4*t] * inv; v.y = o[4*t+1] * inv;
        v.z = o[4*t+2] * inv; v.w = o[4*t+3] * inv;
        o4[t] = v;
    }
}

// ---------------------------------------------------------------------------
// launch
// ---------------------------------------------------------------------------
extern "C" void kernel_launch(void* const* d_in, const int* in_sizes, int n_in,
                              void* d_out, int out_size)
{
    const float* x      = (const float*)d_in[0];
    const float* n1w    = (const float*)d_in[1];
    const float* n1b    = (const float*)d_in[2];
    const float* qkv_w  = (const float*)d_in[3];
    const float* qkv_b  = (const float*)d_in[4];
    const float* rpb    = (const float*)d_in[5];
    const float* proj_w = (const float*)d_in[6];
    const float* proj_b = (const float*)d_in[7];
    const float* n2w    = (const float*)d_in[8];
    const float* n2b    = (const float*)d_in[9];
    const float* w1     = (const float*)d_in[10];
    const float* b1     = (const float*)d_in[11];
    const float* w2     = (const float*)d_in[12];
    const float* b2     = (const float*)d_in[13];
    float* out = (float*)d_out;

    float *qkvp, *x1p, *ap, *bp, *h1p;
    cudaGetSymbolAddress((void**)&qkvp, g_qkv);
    cudaGetSymbolAddress((void**)&x1p,  g_x1);
    cudaGetSymbolAddress((void**)&ap,   g_a);
    cudaGetSymbolAddress((void**)&bp,   g_b);
    cudaGetSymbolAddress((void**)&h1p,  g_h1);

    // 1. LN1 + shift + window partition          -> g_a
    ln_kernel<true><<<65536, 256>>>(x, n1w, n1b, ap);
    // 2. QKV projection                          g_a -> g_qkv
    sgemm_kernel<0><<<dim3(8192, 3), 256>>>(ap, qkv_w, qkv_b, qkvp, nullptr, 96, 288);
    // 3. windowed attention                      g_qkv -> g_b
    attn_kernel<<<dim3(8192, 3), 64>>>(qkvp, rpb, bp);
    // 4. proj + window-reverse + roll + residual g_b -> g_x1 (pixel order)
    sgemm_kernel<2><<<dim3(8192, 1), 256>>>(bp, proj_w, proj_b, x1p, x, 96, 96);
    // 5. LN2                                     g_x1 -> g_a (reuse)
    ln_kernel<false><<<65536, 256>>>(x1p, n2w, n2b, ap);
    // 6. fc1 + gelu                              g_a -> g_h1
    sgemm_kernel<1><<<dim3(8192, 4), 256>>>(ap, w1, b1, h1p, nullptr, 96, 384);
    // 7. fc2 + residual                          g_h1 + g_x1 -> out
    sgemm_kernel<3><<<dim3(8192, 1), 256>>>(h1p, w2, b2, out, x1p, 384, 96);
}

// round 3
// speedup vs baseline: 1.0004x; 1.0004x over previous
#include <cuda_runtime.h>
#include <math.h>

// ---------------------------------------------------------------------------
// SwinBlock: B=8, H=W=256, C=96, WS=8, SS=4, NH=3, hd=32, DFF=384
// rows (window-token order) M = 8*256*256 = 524288
// ---------------------------------------------------------------------------

#define MROWS 524288

// scratch (static device allocations are the sanctioned workaround)
// g_qkv: qkv projections (288 wide); after attention consumes it, its first
//        96-wide stripe region is reused for x1 (residual-1, pixel order).
// g_a  : LN1+window-partition output; reused for LN2 output after QKV GEMM.
// g_b  : attention output (window order).
// g_h1 : fc1+gelu output.
__device__ float g_qkv[MROWS * 288];
__device__ float g_x1 [MROWS *  96];
__device__ float g_a  [MROWS *  96];
__device__ float g_b  [MROWS *  96];
__device__ float g_h1 [MROWS * 384];

// ---------------------------------------------------------------------------
// LayerNorm over C=96: one warp per row. REMAP=true applies the cyclic shift
// (-SS,-SS) + window partition gather (reads pixel order, writes window order).
// ---------------------------------------------------------------------------
template<bool REMAP>
__global__ void __launch_bounds__(256) ln_kernel(
    const float* __restrict__ x, const float* __restrict__ w,
    const float* __restrict__ b, float* __restrict__ out)
{
    int row  = blockIdx.x * 8 + (threadIdx.x >> 5);
    int lane = threadIdx.x & 31;

    size_t src;
    if (REMAP) {
        int b_ = row >> 6, n = row & 63;
        int bb = b_ >> 10, wh = (b_ >> 5) & 31, ww = b_ & 31;
        int i = n >> 3, j = n & 7;
        int hh = (wh * 8 + i + 4) & 255;     // roll(-4): src = dst+4 mod 256
        int wp = (ww * 8 + j + 4) & 255;
        src = ((size_t)bb * 65536 + (size_t)hh * 256 + wp) * 96;
    } else {
        src = (size_t)row * 96;
    }

    float v0 = x[src + lane], v1 = x[src + lane + 32], v2 = x[src + lane + 64];
    float s = v0 + v1 + v2;
    #pragma unroll
    for (int o = 16; o > 0; o >>= 1) s += __shfl_xor_sync(0xffffffffu, s, o);
    float mean = s * (1.0f / 96.0f);
    float d0 = v0 - mean, d1 = v1 - mean, d2 = v2 - mean;
    float vv = d0 * d0 + d1 * d1 + d2 * d2;
    #pragma unroll
    for (int o = 16; o > 0; o >>= 1) vv += __shfl_xor_sync(0xffffffffu, vv, o);
    float rstd = rsqrtf(vv * (1.0f / 96.0f) + 1e-5f);

    size_t dst = (size_t)row * 96;
    out[dst + lane]      = d0 * rstd * w[lane]      + b[lane];
    out[dst + lane + 32] = d1 * rstd * w[lane + 32] + b[lane + 32];
    out[dst + lane + 64] = d2 * rstd * w[lane + 64] + b[lane + 64];
}

// ---------------------------------------------------------------------------
// SGEMM: C[M,N] = A[M,K] @ B[N,K]^T + bias, with fused epilogues.
// BM=64, BN=96, BK=32, 256 threads, 4x6 per-thread tile. All dims divide.
// EPI 0: store            (qkv)
// EPI 1: gelu (exact)     (fc1)
// EPI 2: scatter window-reverse + roll(+4) + residual from res (=x)  (proj)
// EPI 3: residual from res (=x1), C = final out                      (fc2)
// ---------------------------------------------------------------------------
constexpr int BM = 64, BN = 96, BK = 32, TM = 4, TN = 6;

__device__ __forceinline__ size_t dest_pixel(int r)
{
    int b_ = r >> 6, n = r & 63;
    int bb = b_ >> 10, wh = (b_ >> 5) & 31, ww = b_ & 31;
    int i = n >> 3, j = n & 7;
    int hh = (wh * 8 + i + 4) & 255;         // window reverse then roll(+4)
    int wp = (ww * 8 + j + 4) & 255;
    return (size_t)bb * 65536 + (size_t)hh * 256 + wp;
}

template<int EPI>
__global__ void __launch_bounds__(256) sgemm_kernel(
    const float* __restrict__ A, const float* __restrict__ B,
    const float* __restrict__ bias, float* __restrict__ C,
    const float* __restrict__ res, int K, int N)
{
    __shared__ __align__(16) float As[BK][BM];
    __shared__ __align__(16) float Bs[BK][BN];

    const int tid = threadIdx.x;
    const int tr = tid >> 4, tc = tid & 15;
    const long long rowBase = (long long)blockIdx.x * BM;
    const int colBase = blockIdx.y * BN;

    float acc[TM][TN];
    #pragma unroll
    for (int i = 0; i < TM; i++)
        #pragma unroll
        for (int j = 0; j < TN; j++) acc[i][j] = 0.0f;

    for (int k0 = 0; k0 < K; k0 += BK) {
        // A tile: 64 rows x 32 k = 512 float4 slots
        #pragma unroll
        for (int q = 0; q < 2; q++) {
            int slot = tid + q * 256;
            int m = slot >> 3, kq = slot & 7;
            float4 v = *reinterpret_cast<const float4*>(
                A + (rowBase + m) * K + k0 + kq * 4);
            As[kq * 4 + 0][m] = v.x; As[kq * 4 + 1][m] = v.y;
            As[kq * 4 + 2][m] = v.z; As[kq * 4 + 3][m] = v.w;
        }
        // B tile: 96 rows x 32 k = 768 float4 slots
        #pragma unroll
        for (int q = 0; q < 3; q++) {
            int slot = tid + q * 256;
            int nn = slot >> 3, kq = slot & 7;
            float4 v = *reinterpret_cast<const float4*>(
                B + (size_t)(colBase + nn) * K + k0 + kq * 4);
            Bs[kq * 4 + 0][nn] = v.x; Bs[kq * 4 + 1][nn] = v.y;
            Bs[kq * 4 + 2][nn] = v.z; Bs[kq * 4 + 3][nn] = v.w;
        }
        __syncthreads();

        #pragma unroll
        for (int kk = 0; kk < BK; kk++) {
            float4 a4 = *reinterpret_cast<const float4*>(&As[kk][tr * TM]);
            float a[TM] = {a4.x, a4.y, a4.z, a4.w};
            float bv[TN];
            #pragma unroll
            for (int j = 0; j < TN; j++) bv[j] = Bs[kk][tc * TN + j];
            #pragma unroll
            for (int i = 0; i < TM; i++)
                #pragma unroll
                for (int j = 0; j < TN; j++)
                    acc[i][j] = fmaf(a[i], bv[j], acc[i][j]);
        }
        __syncthreads();
    }

    #pragma unroll
    for (int i = 0; i < TM; i++) {
        long long m = rowBase + tr * TM + i;
        size_t drow = 0;
        if (EPI == 2) drow = dest_pixel((int)m) * 96;
        #pragma unroll
        for (int j = 0; j < TN; j++) {
            int nn = colBase + tc * TN + j;
            float v = acc[i][j] + bias[nn];
            if (EPI == 0) {
                C[m * N + nn] = v;
            } else if (EPI == 1) {
                C[m * N + nn] = 0.5f * v * (1.0f + erff(v * 0.70710678118654752f));
            } else if (EPI == 2) {
                size_t d = drow + nn;
                C[d] = res[d] + v;
            } else {
                size_t d = (size_t)m * 96 + nn;
                C[d] = res[d] + v;
            }
        }
    }
}

// ---------------------------------------------------------------------------
// Window attention: one block per (window b_, head h). 64 threads = one
// softmax row per lane. K/V in smem (float4 broadcast reads), scores kept in
// smem column-per-thread. Relative-position bias gathered from table; shift
// mask computed analytically from window coordinates.
// ---------------------------------------------------------------------------
__device__ __forceinline__ int regid(int g)
{
    return g < 248 ? 0 : (g < 252 ? 1 : 2);
}

__global__ void __launch_bounds__(64) attn_kernel(
    const float* __restrict__ qkv, const float* __restrict__ rpb,
    float* __restrict__ ow)
{
    __shared__ __align__(16) float ks[64][32];
    __shared__ __align__(16) float vs[64][32];
    __shared__ float ss[64][64];
    __shared__ float rpbs[225];
    __shared__ int   ids[64];

    const int b_ = blockIdx.x;   // 0..8191
    const int h  = blockIdx.y;   // 0..2
    const int n  = threadIdx.x;  // 0..63

    for (int t = n; t < 225; t += 64) rpbs[t] = rpb[t * 3 + h];

    const int wh = (b_ >> 5) & 31, ww = b_ & 31;
    const int i_n = n >> 3, j_n = n & 7;
    const int id_n = regid(wh * 8 + i_n) * 3 + regid(ww * 8 + j_n);
    ids[n] = id_n;

    const float* base = qkv + (size_t)b_ * 64 * 288;
    float q[32];
    {
        const float4* qp = reinterpret_cast<const float4*>(base + n * 288 + h * 32);
        #pragma unroll
        for (int t = 0; t < 8; t++) {
            float4 v = qp[t];
            q[4*t] = v.x; q[4*t+1] = v.y; q[4*t+2] = v.z; q[4*t+3] = v.w;
        }
        const float4* kp = reinterpret_cast<const float4*>(base + n * 288 + 96 + h * 32);
        float4* kd = reinterpret_cast<float4*>(&ks[n][0]);
        #pragma unroll
        for (int t = 0; t < 8; t++) kd[t] = kp[t];
        const float4* vp = reinterpret_cast<const float4*>(base + n * 288 + 192 + h * 32);
        float4* vd = reinterpret_cast<float4*>(&vs[n][0]);
        #pragma unroll
        for (int t = 0; t < 8; t++) vd[t] = vp[t];
    }
    __syncthreads();

    const float scale = 0.17677669529663687f;  // 1/sqrt(32)

    float mx = -1e30f;
    for (int j = 0; j < 64; j++) {
        const float4* kr = reinterpret_cast<const float4*>(&ks[j][0]);
        float acc = 0.0f;
        #pragma unroll
        for (int t = 0; t < 8; t++) {
            float4 kv = kr[t];
            acc = fmaf(q[4*t],   kv.x, acc);
            acc = fmaf(q[4*t+1], kv.y, acc);
            acc = fmaf(q[4*t+2], kv.z, acc);
            acc = fmaf(q[4*t+3], kv.w, acc);
        }
        int i_j = j >> 3, j_j = j & 7;
        float bias = rpbs[(i_n - i_j + 7) * 15 + (j_n - j_j + 7)];
        float s = fmaf(acc, scale, bias) + (ids[j] == id_n ? 0.0f : -100.0f);
        ss[j][n] = s;
        mx = fmaxf(mx, s);
    }
    // each lane only touches its own ss column -> no block sync required
    float sum = 0.0f;
    for (int j = 0; j < 64; j++) {
        float p = expf(ss[j][n] - mx);
        ss[j][n] = p;
        sum += p;
    }
    float inv = 1.0f / sum;

    float o[32];
    #pragma unroll
    for (int d = 0; d < 32; d++) o[d] = 0.0f;
    for (int j = 0; j < 64; j++) {
        float p = ss[j][n];
        const float4* vr = reinterpret_cast<const float4*>(&vs[j][0]);
        #pragma unroll
        for (int t = 0; t < 8; t++) {
            float4 vv = vr[t];
            o[4*t]   = fmaf(p, vv.x, o[4*t]);
            o[4*t+1] = fmaf(p, vv.y, o[4*t+1]);
            o[4*t+2] = fmaf(p, vv.z, o[4*t+2]);
            o[4*t+3] = fmaf(p, vv.w, o[4*t+3]);
        }
    }

    float4* o4 = reinterpret_cast<float4*>(ow + ((size_t)b_ * 64 + n) * 96 + h * 32);
    #pragma unroll
    for (int t = 0; t < 8; t++) {
        float4 v;
        v.x = o[4*t] * inv; v.y = o[4*t+1] * inv;
        v.z = o[4*t+2] * inv; v.w = o[4*t+3] * inv;
        o4[t] = v;
    }
}

// ---------------------------------------------------------------------------
// launch
// ---------------------------------------------------------------------------
extern "C" void kernel_launch(void* const* d_in, const int* in_sizes, int n_in,
                              void* d_out, int out_size)
{
    const float* x      = (const float*)d_in[0];
    const float* n1w    = (const float*)d_in[1];
    const float* n1b    = (const float*)d_in[2];
    const float* qkv_w  = (const float*)d_in[3];
    const float* qkv_b  = (const float*)d_in[4];
    const float* rpb    = (const float*)d_in[5];
    const float* proj_w = (const float*)d_in[6];
    const float* proj_b = (const float*)d_in[7];
    const float* n2w    = (const float*)d_in[8];
    const float* n2b    = (const float*)d_in[9];
    const float* w1     = (const float*)d_in[10];
    const float* b1     = (const float*)d_in[11];
    const float* w2     = (const float*)d_in[12];
    const float* b2     = (const float*)d_in[13];
    float* out = (float*)d_out;

    float *qkvp, *x1p, *ap, *bp, *h1p;
    cudaGetSymbolAddress((void**)&qkvp, g_qkv);
    cudaGetSymbolAddress((void**)&x1p,  g_x1);
    cudaGetSymbolAddress((void**)&ap,   g_a);
    cudaGetSymbolAddress((void**)&bp,   g_b);
    cudaGetSymbolAddress((void**)&h1p,  g_h1);

    // 1. LN1 + shift + window partition          -> g_a
    ln_kernel<true><<<65536, 256>>>(x, n1w, n1b, ap);
    // 2. QKV projection                          g_a -> g_qkv
    sgemm_kernel<0><<<dim3(8192, 3), 256>>>(ap, qkv_w, qkv_b, qkvp, nullptr, 96, 288);
    // 3. windowed attention                      g_qkv -> g_b
    attn_kernel<<<dim3(8192, 3), 64>>>(qkvp, rpb, bp);
    // 4. proj + window-reverse + roll + residual g_b -> g_x1 (pixel order)
    sgemm_kernel<2><<<dim3(8192, 1), 256>>>(bp, proj_w, proj_b, x1p, x, 96, 96);
    // 5. LN2                                     g_x1 -> g_a (reuse)
    ln_kernel<false><<<65536, 256>>>(x1p, n2w, n2b, ap);
    // 6. fc1 + gelu                              g_a -> g_h1
    sgemm_kernel<1><<<dim3(8192, 4), 256>>>(ap, w1, b1, h1p, nullptr, 96, 384);
    // 7. fc2 + residual                          g_h1 + g_x1 -> out
    sgemm_kernel<3><<<dim3(8192, 1), 256>>>(h1p, w2, b2, out, x1p, 384, 96);
}

// round 7
// speedup vs baseline: 1.1452x; 1.1447x over previous
#include <cuda_runtime.h>
#include <math.h>

// ---------------------------------------------------------------------------
// SwinBlock: B=8, H=W=256, C=96, WS=8, SS=4, NH=3, hd=32, DFF=384
// rows (window-token order) M = 8*256*256 = 524288
// ---------------------------------------------------------------------------

#define MROWS 524288

__device__ float g_qkv[MROWS * 288];
__device__ float g_x1 [MROWS *  96];
__device__ float g_a  [MROWS *  96];
__device__ float g_b  [MROWS *  96];
__device__ float g_h1 [MROWS * 384];

// ---------------------------------------------------------------------------
// cp.async helpers
// ---------------------------------------------------------------------------
__device__ __forceinline__ void cp_async16(void* smem_dst, const void* gmem_src)
{
    unsigned s = (unsigned)__cvta_generic_to_shared(smem_dst);
    asm volatile("cp.async.cg.shared.global [%0], [%1], 16;\n" :: "r"(s), "l"(gmem_src));
}
__device__ __forceinline__ void cp_commit()
{
    asm volatile("cp.async.commit_group;\n");
}
template<int N>
__device__ __forceinline__ void cp_wait()
{
    asm volatile("cp.async.wait_group %0;\n" :: "n"(N));
}

// ---------------------------------------------------------------------------
// LayerNorm over C=96: one warp per row. REMAP=true applies the cyclic shift
// (-SS,-SS) + window partition gather (reads pixel order, writes window order).
// ---------------------------------------------------------------------------
template<bool REMAP>
__global__ void __launch_bounds__(256) ln_kernel(
    const float* __restrict__ x, const float* __restrict__ w,
    const float* __restrict__ b, float* __restrict__ out)
{
    int row  = blockIdx.x * 8 + (threadIdx.x >> 5);
    int lane = threadIdx.x & 31;

    size_t src;
    if (REMAP) {
        int b_ = row >> 6, n = row & 63;
        int bb = b_ >> 10, wh = (b_ >> 5) & 31, ww = b_ & 31;
        int i = n >> 3, j = n & 7;
        int hh = (wh * 8 + i + 4) & 255;     // roll(-4): src = dst+4 mod 256
        int wp = (ww * 8 + j + 4) & 255;
        src = ((size_t)bb * 65536 + (size_t)hh * 256 + wp) * 96;
    } else {
        src = (size_t)row * 96;
    }

    float v0 = x[src + lane], v1 = x[src + lane + 32], v2 = x[src + lane + 64];
    float s = v0 + v1 + v2;
    #pragma unroll
    for (int o = 16; o > 0; o >>= 1) s += __shfl_xor_sync(0xffffffffu, s, o);
    float mean = s * (1.0f / 96.0f);
    float d0 = v0 - mean, d1 = v1 - mean, d2 = v2 - mean;
    float vv = d0 * d0 + d1 * d1 + d2 * d2;
    #pragma unroll
    for (int o = 16; o > 0; o >>= 1) vv += __shfl_xor_sync(0xffffffffu, vv, o);
    float rstd = rsqrtf(vv * (1.0f / 96.0f) + 1e-5f);

    size_t dst = (size_t)row * 96;
    out[dst + lane]      = d0 * rstd * w[lane]      + b[lane];
    out[dst + lane + 32] = d1 * rstd * w[lane + 32] + b[lane + 32];
    out[dst + lane + 64] = d2 * rstd * w[lane + 64] + b[lane + 64];
}

// ---------------------------------------------------------------------------
// SGEMM: C[M,N] = A[M,K] @ B[N,K]^T + bias, with fused epilogues.
// BM=128, BN=96, BK=16, 256 threads (16x16), 8x6 per-thread register tile.
// Both smem tiles are k-major ([row][k], stride 20 floats: 16B-aligned rows,
// conflict-padded), filled by cp.async with double buffering. Inner loop is
// k-vectorized: LDS.128 on both operands (14 loads per 192 FFMA).
// Static smem: 2*(128+96)*20*4 = 35840 B  (< 48 KB static limit).
// EPI 0: store            (qkv)
// EPI 1: gelu (exact)     (fc1)
// EPI 2: scatter window-reverse + roll(+4) + residual from res (=x)  (proj)
// EPI 3: residual from res (=x1), C = final out                      (fc2)
// ---------------------------------------------------------------------------
constexpr int BM = 128, BN = 96, BK = 16, TM = 8, TN = 6;
constexpr int KS = BK + 4;   // 20 floats

__device__ __forceinline__ size_t dest_pixel(int r)
{
    int b_ = r >> 6, n = r & 63;
    int bb = b_ >> 10, wh = (b_ >> 5) & 31, ww = b_ & 31;
    int i = n >> 3, j = n & 7;
    int hh = (wh * 8 + i + 4) & 255;         // window reverse then roll(+4)
    int wp = (ww * 8 + j + 4) & 255;
    return (size_t)bb * 65536 + (size_t)hh * 256 + wp;
}

template<int EPI>
__global__ void __launch_bounds__(256, 2) sgemm_kernel(
    const float* __restrict__ A, const float* __restrict__ B,
    const float* __restrict__ bias, float* __restrict__ C,
    const float* __restrict__ res, int K, int N)
{
    __shared__ __align__(16) float As[2][BM][KS];
    __shared__ __align__(16) float Bs[2][BN][KS];

    const int tid = threadIdx.x;
    const int tr = tid >> 4, tc = tid & 15;          // 16x16 thread grid
    const long long rowBase = (long long)blockIdx.x * BM;
    const int colBase = blockIdx.y * BN;

    const int arow = tid >> 2;          // 0..63
    const int akq  = (tid & 3) * 4;     // 0,4,8,12
    const int nK = K / BK;

    float acc[TM][TN];
    #pragma unroll
    for (int i = 0; i < TM; i++)
        #pragma unroll
        for (int j = 0; j < TN; j++) acc[i][j] = 0.0f;

    // ---- stage loader: A tile 128x16 (2 float4/thread), B tile 96x16 (1.5)
    {
        const int k0 = 0;
        cp_async16(&As[0][arow][akq],      A + (rowBase + arow) * K + k0 + akq);
        cp_async16(&As[0][arow + 64][akq], A + (rowBase + arow + 64) * K + k0 + akq);
        cp_async16(&Bs[0][arow][akq],      B + (size_t)(colBase + arow) * K + k0 + akq);
        if (tid < 128)
            cp_async16(&Bs[0][arow + 64][akq],
                       B + (size_t)(colBase + arow + 64) * K + k0 + akq);
        cp_commit();
    }

    for (int it = 0; it < nK; it++) {
        if (it + 1 < nK) {
            const int s = (it + 1) & 1;
            const int k0 = (it + 1) * BK;
            cp_async16(&As[s][arow][akq],      A + (rowBase + arow) * K + k0 + akq);
            cp_async16(&As[s][arow + 64][akq], A + (rowBase + arow + 64) * K + k0 + akq);
            cp_async16(&Bs[s][arow][akq],      B + (size_t)(colBase + arow) * K + k0 + akq);
            if (tid < 128)
                cp_async16(&Bs[s][arow + 64][akq],
                           B + (size_t)(colBase + arow + 64) * K + k0 + akq);
            cp_commit();
            cp_wait<1>();
        } else {
            cp_wait<0>();
        }
        __syncthreads();

        const int s = it & 1;
        #pragma unroll
        for (int kk = 0; kk < BK; kk += 4) {
            float4 a[TM], b[TN];
            #pragma unroll
            for (int i = 0; i < TM; i++)
                a[i] = *reinterpret_cast<const float4*>(&As[s][tr * TM + i][kk]);
            #pragma unroll
            for (int j = 0; j < TN; j++)
                b[j] = *reinterpret_cast<const float4*>(&Bs[s][tc * TN + j][kk]);
            #pragma unroll
            for (int i = 0; i < TM; i++)
                #pragma unroll
                for (int j = 0; j < TN; j++) {
                    float t = fmaf(a[i].x, b[j].x, acc[i][j]);
                    t = fmaf(a[i].y, b[j].y, t);
                    t = fmaf(a[i].z, b[j].z, t);
                    acc[i][j] = fmaf(a[i].w, b[j].w, t);
                }
        }
        __syncthreads();
    }

    float bb[TN];
    #pragma unroll
    for (int j = 0; j < TN; j++) bb[j] = bias[colBase + tc * TN + j];

    #pragma unroll
    for (int i = 0; i < TM; i++) {
        long long m = rowBase + tr * TM + i;
        size_t drow = 0;
        if (EPI == 2) drow = dest_pixel((int)m) * 96;
        #pragma unroll
        for (int j = 0; j < TN; j++) {
            int nn = colBase + tc * TN + j;
            float v = acc[i][j] + bb[j];
            if (EPI == 0) {
                C[m * N + nn] = v;
            } else if (EPI == 1) {
                C[m * N + nn] = 0.5f * v * (1.0f + erff(v * 0.70710678118654752f));
            } else if (EPI == 2) {
                size_t d = drow + nn;
                C[d] = res[d] + v;
            } else {
                size_t d = (size_t)m * 96 + nn;
                C[d] = res[d] + v;
            }
        }
    }
}

// ---------------------------------------------------------------------------
// Window attention: one block per (window b_, head h). 64 threads = one
// softmax row per lane.
// ---------------------------------------------------------------------------
__device__ __forceinline__ int regid(int g)
{
    return g < 248 ? 0 : (g < 252 ? 1 : 2);
}

__global__ void __launch_bounds__(64) attn_kernel(
    const float* __restrict__ qkv, const float* __restrict__ rpb,
    float* __restrict__ ow)
{
    __shared__ __align__(16) float ks[64][32];
    __shared__ __align__(16) float vs[64][32];
    __shared__ float ss[64][64];
    __shared__ float rpbs[225];
    __shared__ int   ids[64];

    const int b_ = blockIdx.x;   // 0..8191
    const int h  = blockIdx.y;   // 0..2
    const int n  = threadIdx.x;  // 0..63

    for (int t = n; t < 225; t += 64) rpbs[t] = rpb[t * 3 + h];

    const int wh = (b_ >> 5) & 31, ww = b_ & 31;
    const int i_n = n >> 3, j_n = n & 7;
    const int id_n = regid(wh * 8 + i_n) * 3 + regid(ww * 8 + j_n);
    ids[n] = id_n;

    const float* base = qkv + (size_t)b_ * 64 * 288;
    float q[32];
    {
        const float4* qp = reinterpret_cast<const float4*>(base + n * 288 + h * 32);
        #pragma unroll
        for (int t = 0; t < 8; t++) {
            float4 v = qp[t];
            q[4*t] = v.x; q[4*t+1] = v.y; q[4*t+2] = v.z; q[4*t+3] = v.w;
        }
        const float4* kp = reinterpret_cast<const float4*>(base + n * 288 + 96 + h * 32);
        float4* kd = reinterpret_cast<float4*>(&ks[n][0]);
        #pragma unroll
        for (int t = 0; t < 8; t++) kd[t] = kp[t];
        const float4* vp = reinterpret_cast<const float4*>(base + n * 288 + 192 + h * 32);
        float4* vd = reinterpret_cast<float4*>(&vs[n][0]);
        #pragma unroll
        for (int t = 0; t < 8; t++) vd[t] = vp[t];
    }
    __syncthreads();

    const float scale = 0.17677669529663687f;  // 1/sqrt(32)

    float mx = -1e30f;
    for (int j = 0; j < 64; j++) {
        const float4* kr = reinterpret_cast<const float4*>(&ks[j][0]);
        float acc = 0.0f;
        #pragma unroll
        for (int t = 0; t < 8; t++) {
            float4 kv = kr[t];
            acc = fmaf(q[4*t],   kv.x, acc);
            acc = fmaf(q[4*t+1], kv.y, acc);
            acc = fmaf(q[4*t+2], kv.z, acc);
            acc = fmaf(q[4*t+3], kv.w, acc);
        }
        int i_j = j >> 3, j_j = j & 7;
        float bias = rpbs[(i_n - i_j + 7) * 15 + (j_n - j_j + 7)];
        float s = fmaf(acc, scale, bias) + (ids[j] == id_n ? 0.0f : -100.0f);
        ss[j][n] = s;
        mx = fmaxf(mx, s);
    }
    // each lane only touches its own ss column -> no block sync required
    float sum = 0.0f;
    for (int j = 0; j < 64; j++) {
        float p = expf(ss[j][n] - mx);
        ss[j][n] = p;
        sum += p;
    }
    float inv = 1.0f / sum;

    float o[32];
    #pragma unroll
    for (int d = 0; d < 32; d++) o[d] = 0.0f;
    for (int j = 0; j < 64; j++) {
        float p = ss[j][n];
        const float4* vr = reinterpret_cast<const float4*>(&vs[j][0]);
        #pragma unroll
        for (int t = 0; t < 8; t++) {
            float4 vv = vr[t];
            o[4*t]   = fmaf(p, vv.x, o[4*t]);
            o[4*t+1] = fmaf(p, vv.y, o[4*t+1]);
            o[4*t+2] = fmaf(p, vv.z, o[4*t+2]);
            o[4*t+3] = fmaf(p, vv.w, o[4*t+3]);
        }
    }

    float4* o4 = reinterpret_cast<float4*>(ow + ((size_t)b_ * 64 + n) * 96 + h * 32);
    #pragma unroll
    for (int t = 0; t < 8; t++) {
        float4 v;
        v.x = o[4*t] * inv; v.y = o[4*t+1] * inv;
        v.z = o[4*t+2] * inv; v.w = o[4*t+3] * inv;
        o4[t] = v;
    }
}

// ---------------------------------------------------------------------------
// launch
// ---------------------------------------------------------------------------
extern "C" void kernel_launch(void* const* d_in, const int* in_sizes, int n_in,
                              void* d_out, int out_size)
{
    const float* x      = (const float*)d_in[0];
    const float* n1w    = (const float*)d_in[1];
    const float* n1b    = (const float*)d_in[2];
    const float* qkv_w  = (const float*)d_in[3];
    const float* qkv_b  = (const float*)d_in[4];
    const float* rpb    = (const float*)d_in[5];
    const float* proj_w = (const float*)d_in[6];
    const float* proj_b = (const float*)d_in[7];
    const float* n2w    = (const float*)d_in[8];
    const float* n2b    = (const float*)d_in[9];
    const float* w1     = (const float*)d_in[10];
    const float* b1     = (const float*)d_in[11];
    const float* w2     = (const float*)d_in[12];
    const float* b2     = (const float*)d_in[13];
    float* out = (float*)d_out;

    float *qkvp, *x1p, *ap, *bp, *h1p;
    cudaGetSymbolAddress((void**)&qkvp, g_qkv);
    cudaGetSymbolAddress((void**)&x1p,  g_x1);
    cudaGetSymbolAddress((void**)&ap,   g_a);
    cudaGetSymbolAddress((void**)&bp,   g_b);
    cudaGetSymbolAddress((void**)&h1p,  g_h1);

    // 1. LN1 + shift + window partition          -> g_a
    ln_kernel<true><<<65536, 256>>>(x, n1w, n1b, ap);
    // 2. QKV projection                          g_a -> g_qkv
    sgemm_kernel<0><<<dim3(4096, 3), 256>>>(ap, qkv_w, qkv_b, qkvp, nullptr, 96, 288);
    // 3. windowed attention                      g_qkv -> g_b
    attn_kernel<<<dim3(8192, 3), 64>>>(qkvp, rpb, bp);
    // 4. proj + window-reverse + roll + residual g_b -> g_x1 (pixel order)
    sgemm_kernel<2><<<dim3(4096, 1), 256>>>(bp, proj_w, proj_b, x1p, x, 96, 96);
    // 5. LN2                                     g_x1 -> g_a (reuse)
    ln_kernel<false><<<65536, 256>>>(x1p, n2w, n2b, ap);
    // 6. fc1 + gelu                              g_a -> g_h1
    sgemm_kernel<1><<<dim3(4096, 4), 256>>>(ap, w1, b1, h1p, nullptr, 96, 384);
    // 7. fc2 + residual                          g_h1 + g_x1 -> out
    sgemm_kernel<3><<<dim3(4096, 1), 256>>>(h1p, w2, b2, out, x1p, 384, 96);
}

// round 10
// speedup vs baseline: 2.2263x; 1.9441x over previous
#include <cuda_runtime.h>
#include <math.h>

// ---------------------------------------------------------------------------
// SwinBlock: B=8, H=W=256, C=96, WS=8, SS=4, NH=3, hd=32, DFF=384
// rows (window-token order) M = 8*256*256 = 524288
// (Round 10 = audited resubmission of the tf32 tensor-core kernel. Rounds 8/9
//  died to "container failed twice" with no compile/runtime evidence; source
//  audit found no defect: smem 35.8KB<48KB, mma.sync tf32 legal on sm_100,
//  fragment maps verified against PTX ISA. Contingency: third failure => port
//  GEMM to tcgen05.)
// ---------------------------------------------------------------------------

#define MROWS 524288

__device__ float g_qkv[MROWS * 288];
__device__ float g_x1 [MROWS *  96];
__device__ float g_a  [MROWS *  96];
__device__ float g_b  [MROWS *  96];
__device__ float g_h1 [MROWS * 384];

// ---------------------------------------------------------------------------
// cp.async / mma helpers
// ---------------------------------------------------------------------------
__device__ __forceinline__ void cp_async16(void* smem_dst, const void* gmem_src)
{
    unsigned s = (unsigned)__cvta_generic_to_shared(smem_dst);
    asm volatile("cp.async.cg.shared.global [%0], [%1], 16;\n" :: "r"(s), "l"(gmem_src));
}
__device__ __forceinline__ void cp_commit()
{
    asm volatile("cp.async.commit_group;\n");
}
template<int N>
__device__ __forceinline__ void cp_wait()
{
    asm volatile("cp.async.wait_group %0;\n" :: "n"(N));
}

__device__ __forceinline__ unsigned f2tf32(float f)
{
    unsigned r;
    asm("cvt.rna.tf32.f32 %0, %1;" : "=r"(r) : "f"(f));
    return r;
}

__device__ __forceinline__ void mma_tf32(
    float& c0, float& c1, float& c2, float& c3,
    unsigned a0, unsigned a1, unsigned a2, unsigned a3,
    unsigned b0, unsigned b1)
{
    asm volatile(
        "mma.sync.aligned.m16n8k8.row.col.f32.tf32.tf32.f32 "
        "{%0,%1,%2,%3}, {%4,%5,%6,%7}, {%8,%9}, {%0,%1,%2,%3};\n"
        : "+f"(c0), "+f"(c1), "+f"(c2), "+f"(c3)
        : "r"(a0), "r"(a1), "r"(a2), "r"(a3), "r"(b0), "r"(b1));
}

// ---------------------------------------------------------------------------
// LayerNorm over C=96: one warp per row. REMAP=true applies the cyclic shift
// (-SS,-SS) + window partition gather (reads pixel order, writes window order).
// ---------------------------------------------------------------------------
template<bool REMAP>
__global__ void __launch_bounds__(256) ln_kernel(
    const float* __restrict__ x, const float* __restrict__ w,
    const float* __restrict__ b, float* __restrict__ out)
{
    int row  = blockIdx.x * 8 + (threadIdx.x >> 5);
    int lane = threadIdx.x & 31;

    size_t src;
    if (REMAP) {
        int b_ = row >> 6, n = row & 63;
        int bb = b_ >> 10, wh = (b_ >> 5) & 31, ww = b_ & 31;
        int i = n >> 3, j = n & 7;
        int hh = (wh * 8 + i + 4) & 255;     // roll(-4): src = dst+4 mod 256
        int wp = (ww * 8 + j + 4) & 255;
        src = ((size_t)bb * 65536 + (size_t)hh * 256 + wp) * 96;
    } else {
        src = (size_t)row * 96;
    }

    float v0 = x[src + lane], v1 = x[src + lane + 32], v2 = x[src + lane + 64];
    float s = v0 + v1 + v2;
    #pragma unroll
    for (int o = 16; o > 0; o >>= 1) s += __shfl_xor_sync(0xffffffffu, s, o);
    float mean = s * (1.0f / 96.0f);
    float d0 = v0 - mean, d1 = v1 - mean, d2 = v2 - mean;
    float vv = d0 * d0 + d1 * d1 + d2 * d2;
    #pragma unroll
    for (int o = 16; o > 0; o >>= 1) vv += __shfl_xor_sync(0xffffffffu, vv, o);
    float rstd = rsqrtf(vv * (1.0f / 96.0f) + 1e-5f);

    size_t dst = (size_t)row * 96;
    out[dst + lane]      = d0 * rstd * w[lane]      + b[lane];
    out[dst + lane + 32] = d1 * rstd * w[lane + 32] + b[lane + 32];
    out[dst + lane + 64] = d2 * rstd * w[lane + 64] + b[lane + 64];
}

// ---------------------------------------------------------------------------
// TF32 tensor-core GEMM: C[M,N] = A[M,K] @ B[N,K]^T + bias, fused epilogues.
// BM=128, BN=96, BK=16, 256 threads = 8 warps in 4(m) x 2(n) grid.
// Warp tile 32x48 = 2 x 6 m16n8k8 fragments, fp32 accumulate.
// smem tiles k-major [row][k], stride KS=20 floats.
// EPI 0: store            (qkv)
// EPI 1: gelu (exact)     (fc1)
// EPI 2: scatter window-reverse + roll(+4) + residual from res (=x)  (proj)
// EPI 3: residual from res (=x1), C = final out                      (fc2)
// ---------------------------------------------------------------------------
constexpr int BM = 128, BN = 96, BK = 16;
constexpr int KS = BK + 4;   // 20 floats

__device__ __forceinline__ size_t dest_pixel(int r)
{
    int b_ = r >> 6, n = r & 63;
    int bb = b_ >> 10, wh = (b_ >> 5) & 31, ww = b_ & 31;
    int i = n >> 3, j = n & 7;
    int hh = (wh * 8 + i + 4) & 255;         // window reverse then roll(+4)
    int wp = (ww * 8 + j + 4) & 255;
    return (size_t)bb * 65536 + (size_t)hh * 256 + wp;
}

__device__ __forceinline__ float gelu_exact(float v)
{
    return 0.5f * v * (1.0f + erff(v * 0.70710678118654752f));
}

template<int EPI>
__global__ void __launch_bounds__(256, 2) tgemm_kernel(
    const float* __restrict__ A, const float* __restrict__ B,
    const float* __restrict__ bias, float* __restrict__ C,
    const float* __restrict__ res, int K, int N)
{
    __shared__ __align__(16) float As[2][BM][KS];
    __shared__ __align__(16) float Bs[2][BN][KS];

    const int tid  = threadIdx.x;
    const int wid  = tid >> 5;
    const int lane = tid & 31;
    const int wm   = wid >> 1;          // 0..3  (m position)
    const int wn   = wid & 1;           // 0..1  (n position)
    const int lr   = lane >> 2;         // fragment group  0..7
    const int lc   = lane & 3;          // thread-in-group 0..3

    const long long rowBase = (long long)blockIdx.x * BM;
    const int colBase = blockIdx.y * BN;

    const int arow = tid >> 2;          // 0..63
    const int akq  = (tid & 3) * 4;     // 0,4,8,12
    const int nK = K / BK;

    float acc[2][6][4];
    #pragma unroll
    for (int mt = 0; mt < 2; mt++)
        #pragma unroll
        for (int nt = 0; nt < 6; nt++)
            #pragma unroll
            for (int e = 0; e < 4; e++) acc[mt][nt][e] = 0.0f;

    // ---- stage 0
    {
        cp_async16(&As[0][arow][akq],      A + (rowBase + arow) * K + akq);
        cp_async16(&As[0][arow + 64][akq], A + (rowBase + arow + 64) * K + akq);
        cp_async16(&Bs[0][arow][akq],      B + (size_t)(colBase + arow) * K + akq);
        if (tid < 128)
            cp_async16(&Bs[0][arow + 64][akq],
                       B + (size_t)(colBase + arow + 64) * K + akq);
        cp_commit();
    }

    for (int it = 0; it < nK; it++) {
        if (it + 1 < nK) {
            const int s = (it + 1) & 1;
            const int k0 = (it + 1) * BK;
            cp_async16(&As[s][arow][akq],      A + (rowBase + arow) * K + k0 + akq);
            cp_async16(&As[s][arow + 64][akq], A + (rowBase + arow + 64) * K + k0 + akq);
            cp_async16(&Bs[s][arow][akq],      B + (size_t)(colBase + arow) * K + k0 + akq);
            if (tid < 128)
                cp_async16(&Bs[s][arow + 64][akq],
                           B + (size_t)(colBase + arow + 64) * K + k0 + akq);
            cp_commit();
            cp_wait<1>();
        } else {
            cp_wait<0>();
        }
        __syncthreads();

        const int s = it & 1;
        #pragma unroll
        for (int kk = 0; kk < BK; kk += 8) {
            unsigned a[2][4];
            #pragma unroll
            for (int mt = 0; mt < 2; mt++) {
                int r0 = wm * 32 + mt * 16 + lr;
                a[mt][0] = f2tf32(As[s][r0][kk + lc]);
                a[mt][1] = f2tf32(As[s][r0 + 8][kk + lc]);
                a[mt][2] = f2tf32(As[s][r0][kk + lc + 4]);
                a[mt][3] = f2tf32(As[s][r0 + 8][kk + lc + 4]);
            }
            unsigned bf[6][2];
            #pragma unroll
            for (int nt = 0; nt < 6; nt++) {
                int n0 = wn * 48 + nt * 8 + lr;
                bf[nt][0] = f2tf32(Bs[s][n0][kk + lc]);
                bf[nt][1] = f2tf32(Bs[s][n0][kk + lc + 4]);
            }
            #pragma unroll
            for (int mt = 0; mt < 2; mt++)
                #pragma unroll
                for (int nt = 0; nt < 6; nt++)
                    mma_tf32(acc[mt][nt][0], acc[mt][nt][1],
                             acc[mt][nt][2], acc[mt][nt][3],
                             a[mt][0], a[mt][1], a[mt][2], a[mt][3],
                             bf[nt][0], bf[nt][1]);
        }
        __syncthreads();
    }

    // ---- epilogue (c0:(r,c) c1:(r,c+1) c2:(r+8,c) c3:(r+8,c+1))
    #pragma unroll
    for (int mt = 0; mt < 2; mt++) {
        long long row0 = rowBase + wm * 32 + mt * 16 + lr;
        long long row1 = row0 + 8;
        size_t d0 = 0, d1 = 0;
        if (EPI == 2) {
            d0 = dest_pixel((int)row0) * 96;
            d1 = dest_pixel((int)row1) * 96;
        }
        #pragma unroll
        for (int nt = 0; nt < 6; nt++) {
            int col = colBase + wn * 48 + nt * 8 + 2 * lc;
            float2 bb = *reinterpret_cast<const float2*>(&bias[col]);
            float v00 = acc[mt][nt][0] + bb.x;
            float v01 = acc[mt][nt][1] + bb.y;
            float v10 = acc[mt][nt][2] + bb.x;
            float v11 = acc[mt][nt][3] + bb.y;
            if (EPI == 0) {
                *reinterpret_cast<float2*>(&C[row0 * N + col]) = make_float2(v00, v01);
                *reinterpret_cast<float2*>(&C[row1 * N + col]) = make_float2(v10, v11);
            } else if (EPI == 1) {
                *reinterpret_cast<float2*>(&C[row0 * N + col]) =
                    make_float2(gelu_exact(v00), gelu_exact(v01));
                *reinterpret_cast<float2*>(&C[row1 * N + col]) =
                    make_float2(gelu_exact(v10), gelu_exact(v11));
            } else if (EPI == 2) {
                float2 r0v = *reinterpret_cast<const float2*>(&res[d0 + col]);
                float2 r1v = *reinterpret_cast<const float2*>(&res[d1 + col]);
                *reinterpret_cast<float2*>(&C[d0 + col]) =
                    make_float2(r0v.x + v00, r0v.y + v01);
                *reinterpret_cast<float2*>(&C[d1 + col]) =
                    make_float2(r1v.x + v10, r1v.y + v11);
            } else {
                float2 r0v = *reinterpret_cast<const float2*>(&res[row0 * 96 + col]);
                float2 r1v = *reinterpret_cast<const float2*>(&res[row1 * 96 + col]);
                *reinterpret_cast<float2*>(&C[row0 * 96 + col]) =
                    make_float2(r0v.x + v00, r0v.y + v01);
                *reinterpret_cast<float2*>(&C[row1 * 96 + col]) =
                    make_float2(r1v.x + v10, r1v.y + v11);
            }
        }
    }
}

// ---------------------------------------------------------------------------
// Window attention: one block per (window b_, head h). 64 threads = one
// softmax row per lane. (fp32 exact; tensorize in a later round)
// ---------------------------------------------------------------------------
__device__ __forceinline__ int regid(int g)
{
    return g < 248 ? 0 : (g < 252 ? 1 : 2);
}

__global__ void __launch_bounds__(64) attn_kernel(
    const float* __restrict__ qkv, const float* __restrict__ rpb,
    float* __restrict__ ow)
{
    __shared__ __align__(16) float ks[64][32];
    __shared__ __align__(16) float vs[64][32];
    __shared__ float ss[64][64];
    __shared__ float rpbs[225];
    __shared__ int   ids[64];

    const int b_ = blockIdx.x;   // 0..8191
    const int h  = blockIdx.y;   // 0..2
    const int n  = threadIdx.x;  // 0..63

    for (int t = n; t < 225; t += 64) rpbs[t] = rpb[t * 3 + h];

    const int wh = (b_ >> 5) & 31, ww = b_ & 31;
    const int i_n = n >> 3, j_n = n & 7;
    const int id_n = regid(wh * 8 + i_n) * 3 + regid(ww * 8 + j_n);
    ids[n] = id_n;

    const float* base = qkv + (size_t)b_ * 64 * 288;
    float q[32];
    {
        const float4* qp = reinterpret_cast<const float4*>(base + n * 288 + h * 32);
        #pragma unroll
        for (int t = 0; t < 8; t++) {
            float4 v = qp[t];
            q[4*t] = v.x; q[4*t+1] = v.y; q[4*t+2] = v.z; q[4*t+3] = v.w;
        }
        const float4* kp = reinterpret_cast<const float4*>(base + n * 288 + 96 + h * 32);
        float4* kd = reinterpret_cast<float4*>(&ks[n][0]);
        #pragma unroll
        for (int t = 0; t < 8; t++) kd[t] = kp[t];
        const float4* vp = reinterpret_cast<const float4*>(base + n * 288 + 192 + h * 32);
        float4* vd = reinterpret_cast<float4*>(&vs[n][0]);
        #pragma unroll
        for (int t = 0; t < 8; t++) vd[t] = vp[t];
    }
    __syncthreads();

    const float scale = 0.17677669529663687f;  // 1/sqrt(32)

    float mx = -1e30f;
    for (int j = 0; j < 64; j++) {
        const float4* kr = reinterpret_cast<const float4*>(&ks[j][0]);
        float acc = 0.0f;
        #pragma unroll
        for (int t = 0; t < 8; t++) {
            float4 kv = kr[t];
            acc = fmaf(q[4*t],   kv.x, acc);
            acc = fmaf(q[4*t+1], kv.y, acc);
            acc = fmaf(q[4*t+2], kv.z, acc);
            acc = fmaf(q[4*t+3], kv.w, acc);
        }
        int i_j = j >> 3, j_j = j & 7;
        float bias = rpbs[(i_n - i_j + 7) * 15 + (j_n - j_j + 7)];
        float s = fmaf(acc, scale, bias) + (ids[j] == id_n ? 0.0f : -100.0f);
        ss[j][n] = s;
        mx = fmaxf(mx, s);
    }
    // each lane only touches its own ss column -> no block sync required
    float sum = 0.0f;
    for (int j = 0; j < 64; j++) {
        float p = expf(ss[j][n] - mx);
        ss[j][n] = p;
        sum += p;
    }
    float inv = 1.0f / sum;

    float o[32];
    #pragma unroll
    for (int d = 0; d < 32; d++) o[d] = 0.0f;
    for (int j = 0; j < 64; j++) {
        float p = ss[j][n];
        const float4* vr = reinterpret_cast<const float4*>(&vs[j][0]);
        #pragma unroll
        for (int t = 0; t < 8; t++) {
            float4 vv = vr[t];
            o[4*t]   = fmaf(p, vv.x, o[4*t]);
            o[4*t+1] = fmaf(p, vv.y, o[4*t+1]);
            o[4*t+2] = fmaf(p, vv.z, o[4*t+2]);
            o[4*t+3] = fmaf(p, vv.w, o[4*t+3]);
        }
    }

    float4* o4 = reinterpret_cast<float4*>(ow + ((size_t)b_ * 64 + n) * 96 + h * 32);
    #pragma unroll
    for (int t = 0; t < 8; t++) {
        float4 v;
        v.x = o[4*t] * inv; v.y = o[4*t+1] * inv;
        v.z = o[4*t+2] * inv; v.w = o[4*t+3] * inv;
        o4[t] = v;
    }
}

// ---------------------------------------------------------------------------
// launch
// ---------------------------------------------------------------------------
extern "C" void kernel_launch(void* const* d_in, const int* in_sizes, int n_in,
                              void* d_out, int out_size)
{
    const float* x      = (const float*)d_in[0];
    const float* n1w    = (const float*)d_in[1];
    const float* n1b    = (const float*)d_in[2];
    const float* qkv_w  = (const float*)d_in[3];
    const float* qkv_b  = (const float*)d_in[4];
    const float* rpb    = (const float*)d_in[5];
    const float* proj_w = (const float*)d_in[6];
    const float* proj_b = (const float*)d_in[7];
    const float* n2w    = (const float*)d_in[8];
    const float* n2b    = (const float*)d_in[9];
    const float* w1     = (const float*)d_in[10];
    const float* b1     = (const float*)d_in[11];
    const float* w2     = (const float*)d_in[12];
    const float* b2     = (const float*)d_in[13];
    float* out = (float*)d_out;

    float *qkvp, *x1p, *ap, *bp, *h1p;
    cudaGetSymbolAddress((void**)&qkvp, g_qkv);
    cudaGetSymbolAddress((void**)&x1p,  g_x1);
    cudaGetSymbolAddress((void**)&ap,   g_a);
    cudaGetSymbolAddress((void**)&bp,   g_b);
    cudaGetSymbolAddress((void**)&h1p,  g_h1);

    // 1. LN1 + shift + window partition          -> g_a
    ln_kernel<true><<<65536, 256>>>(x, n1w, n1b, ap);
    // 2. QKV projection                          g_a -> g_qkv
    tgemm_kernel<0><<<dim3(4096, 3), 256>>>(ap, qkv_w, qkv_b, qkvp, nullptr, 96, 288);
    // 3. windowed attention                      g_qkv -> g_b
    attn_kernel<<<dim3(8192, 3), 64>>>(qkvp, rpb, bp);
    // 4. proj + window-reverse + roll + residual g_b -> g_x1 (pixel order)
    tgemm_kernel<2><<<dim3(4096, 1), 256>>>(bp, proj_w, proj_b, x1p, x, 96, 96);
    // 5. LN2                                     g_x1 -> g_a (reuse)
    ln_kernel<false><<<65536, 256>>>(x1p, n2w, n2b, ap);
    // 6. fc1 + gelu                              g_a -> g_h1
    tgemm_kernel<1><<<dim3(4096, 4), 256>>>(ap, w1, b1, h1p, nullptr, 96, 384);
    // 7. fc2 + residual                          g_h1 + g_x1 -> out
    tgemm_kernel<3><<<dim3(4096, 1), 256>>>(h1p, w2, b2, out, x1p, 384, 96);
}

// round 11
// speedup vs baseline: 2.8792x; 1.2933x over previous
#include <cuda_runtime.h>
#include <cuda_bf16.h>
#include <math.h>

// ---------------------------------------------------------------------------
// SwinBlock: B=8, H=W=256, C=96, WS=8, SS=4, NH=3, hd=32, DFF=384
// rows (window-token order) M = 8*256*256 = 524288
// Round 11: bf16 storage for all big intermediates + bf16 m16n8k16 MMA.
// Residual path (x, x1, out) stays fp32. Error model calibrated from round 10
// (tf32 delta 5e-4 -> 1.7e-5 observed); bf16 delta 4e-3 -> ~1.5e-4 expected.
// ---------------------------------------------------------------------------

#define MROWS 524288

__device__ __nv_bfloat16 g_qkv[MROWS * 288];
__device__ __nv_bfloat16 g_a  [MROWS *  96];
__device__ __nv_bfloat16 g_b  [MROWS *  96];
__device__ __nv_bfloat16 g_h1 [MROWS * 384];
__device__ float         g_x1 [MROWS *  96];

// bf16 weight copies
__device__ __nv_bfloat16 g_wq[288 * 96];
__device__ __nv_bfloat16 g_wp[ 96 * 96];
__device__ __nv_bfloat16 g_w1[384 * 96];
__device__ __nv_bfloat16 g_w2[ 96 * 384];

// ---------------------------------------------------------------------------
// helpers
// ---------------------------------------------------------------------------
__device__ __forceinline__ void cp_async16(void* smem_dst, const void* gmem_src)
{
    unsigned s = (unsigned)__cvta_generic_to_shared(smem_dst);
    asm volatile("cp.async.cg.shared.global [%0], [%1], 16;\n" :: "r"(s), "l"(gmem_src));
}
__device__ __forceinline__ void cp_commit()
{
    asm volatile("cp.async.commit_group;\n");
}
template<int N>
__device__ __forceinline__ void cp_wait()
{
    asm volatile("cp.async.wait_group %0;\n" :: "n"(N));
}

__device__ __forceinline__ void mma_bf16(
    float& c0, float& c1, float& c2, float& c3,
    unsigned a0, unsigned a1, unsigned a2, unsigned a3,
    unsigned b0, unsigned b1)
{
    asm volatile(
        "mma.sync.aligned.m16n8k16.row.col.f32.bf16.bf16.f32 "
        "{%0,%1,%2,%3}, {%4,%5,%6,%7}, {%8,%9}, {%0,%1,%2,%3};\n"
        : "+f"(c0), "+f"(c1), "+f"(c2), "+f"(c3)
        : "r"(a0), "r"(a1), "r"(a2), "r"(a3), "r"(b0), "r"(b1));
}

__global__ void __launch_bounds__(256) cvt_kernel(
    const float* __restrict__ src, __nv_bfloat16* __restrict__ dst, int n)
{
    int i = blockIdx.x * 256 + threadIdx.x;
    if (i < n) dst[i] = __float2bfloat16(src[i]);
}

// ---------------------------------------------------------------------------
// LayerNorm over C=96: one warp per row; bf16 output. REMAP=true applies the
// cyclic shift (-SS,-SS) + window-partition gather (pixel order -> window order)
// ---------------------------------------------------------------------------
template<bool REMAP>
__global__ void __launch_bounds__(256) ln_kernel(
    const float* __restrict__ x, const float* __restrict__ w,
    const float* __restrict__ b, __nv_bfloat16* __restrict__ out)
{
    int row  = blockIdx.x * 8 + (threadIdx.x >> 5);
    int lane = threadIdx.x & 31;

    size_t src;
    if (REMAP) {
        int b_ = row >> 6, n = row & 63;
        int bb = b_ >> 10, wh = (b_ >> 5) & 31, ww = b_ & 31;
        int i = n >> 3, j = n & 7;
        int hh = (wh * 8 + i + 4) & 255;     // roll(-4): src = dst+4 mod 256
        int wp = (ww * 8 + j + 4) & 255;
        src = ((size_t)bb * 65536 + (size_t)hh * 256 + wp) * 96;
    } else {
        src = (size_t)row * 96;
    }

    float v0 = x[src + lane], v1 = x[src + lane + 32], v2 = x[src + lane + 64];
    float s = v0 + v1 + v2;
    #pragma unroll
    for (int o = 16; o > 0; o >>= 1) s += __shfl_xor_sync(0xffffffffu, s, o);
    float mean = s * (1.0f / 96.0f);
    float d0 = v0 - mean, d1 = v1 - mean, d2 = v2 - mean;
    float vv = d0 * d0 + d1 * d1 + d2 * d2;
    #pragma unroll
    for (int o = 16; o > 0; o >>= 1) vv += __shfl_xor_sync(0xffffffffu, vv, o);
    float rstd = rsqrtf(vv * (1.0f / 96.0f) + 1e-5f);

    size_t dst = (size_t)row * 96;
    out[dst + lane]      = __float2bfloat16(d0 * rstd * w[lane]      + b[lane]);
    out[dst + lane + 32] = __float2bfloat16(d1 * rstd * w[lane + 32] + b[lane + 32]);
    out[dst + lane + 64] = __float2bfloat16(d2 * rstd * w[lane + 64] + b[lane + 64]);
}

// ---------------------------------------------------------------------------
// bf16 tensor-core GEMM: C[M,N] = A[M,K] @ B[N,K]^T + bias, fused epilogues.
// BM=128, BN=96, BK=32(halves), 256 threads = 8 warps in 4(m) x 2(n).
// Warp tile 32x48 = 2 x 6 m16n8k16 fragments, fp32 accumulate.
// smem k-major [row][k], stride KS=40 halves (80 B rows, bank-conflict-free:
// word index = r*20 + lc mod 32, all distinct within a warp phase).
// EPI 0: store bf16        (qkv)
// EPI 1: gelu -> bf16      (fc1)
// EPI 2: scatter window-reverse + roll(+4) + residual(x) -> fp32     (proj)
// EPI 3: residual(x1) -> fp32 final out                              (fc2)
// ---------------------------------------------------------------------------
constexpr int BM = 128, BN = 96, BK = 32;
constexpr int KS = BK + 8;   // 40 halves

__device__ __forceinline__ size_t dest_pixel(int r)
{
    int b_ = r >> 6, n = r & 63;
    int bb = b_ >> 10, wh = (b_ >> 5) & 31, ww = b_ & 31;
    int i = n >> 3, j = n & 7;
    int hh = (wh * 8 + i + 4) & 255;         // window reverse then roll(+4)
    int wp = (ww * 8 + j + 4) & 255;
    return (size_t)bb * 65536 + (size_t)hh * 256 + wp;
}

__device__ __forceinline__ float gelu_exact(float v)
{
    return 0.5f * v * (1.0f + erff(v * 0.70710678118654752f));
}

template<int EPI>
__global__ void __launch_bounds__(256, 2) hgemm_kernel(
    const __nv_bfloat16* __restrict__ A, const __nv_bfloat16* __restrict__ B,
    const float* __restrict__ bias, void* __restrict__ Cv,
    const float* __restrict__ res, int K, int N)
{
    __shared__ __align__(16) __nv_bfloat16 As[2][BM][KS];
    __shared__ __align__(16) __nv_bfloat16 Bs[2][BN][KS];

    const int tid  = threadIdx.x;
    const int wid  = tid >> 5;
    const int lane = tid & 31;
    const int wm   = wid >> 1;          // 0..3  (m)
    const int wn   = wid & 1;           // 0..1  (n)
    const int lr   = lane >> 2;         // 0..7
    const int lc   = lane & 3;          // 0..3

    const long long rowBase = (long long)blockIdx.x * BM;
    const int colBase = blockIdx.y * BN;

    // loaders: 16B = 8 halves per cp. A: 128 rows x 4 chunks = 512 slots.
    const int rA0 = tid >> 2,            cA0 = (tid & 3) * 8;
    const int rA1 = (tid + 256) >> 2,    cA1 = cA0;            // slot tid+256
    // B: 96 rows x 4 chunks = 384 slots (tid, plus tid+256 for tid<128)
    const int rB0 = rA0,                 cB0 = cA0;
    const int rB1 = rA1,                 cB1 = cA0;
    const int nK = K / BK;

    float acc[2][6][4];
    #pragma unroll
    for (int mt = 0; mt < 2; mt++)
        #pragma unroll
        for (int nt = 0; nt < 6; nt++)
            #pragma unroll
            for (int e = 0; e < 4; e++) acc[mt][nt][e] = 0.0f;

    // ---- stage 0
    {
        cp_async16(&As[0][rA0][cA0], A + (rowBase + rA0) * K + cA0);
        cp_async16(&As[0][rA1][cA1], A + (rowBase + rA1) * K + cA1);
        cp_async16(&Bs[0][rB0][cB0], B + (size_t)(colBase + rB0) * K + cB0);
        if (tid < 128)
            cp_async16(&Bs[0][rB1][cB1], B + (size_t)(colBase + rB1) * K + cB1);
        cp_commit();
    }

    for (int it = 0; it < nK; it++) {
        if (it + 1 < nK) {
            const int s = (it + 1) & 1;
            const int k0 = (it + 1) * BK;
            cp_async16(&As[s][rA0][cA0], A + (rowBase + rA0) * K + k0 + cA0);
            cp_async16(&As[s][rA1][cA1], A + (rowBase + rA1) * K + k0 + cA1);
            cp_async16(&Bs[s][rB0][cB0], B + (size_t)(colBase + rB0) * K + k0 + cB0);
            if (tid < 128)
                cp_async16(&Bs[s][rB1][cB1], B + (size_t)(colBase + rB1) * K + k0 + cB1);
            cp_commit();
            cp_wait<1>();
        } else {
            cp_wait<0>();
        }
        __syncthreads();

        const int s = it & 1;
        #pragma unroll
        for (int kb = 0; kb < BK; kb += 16) {
            unsigned a[2][4];
            #pragma unroll
            for (int mt = 0; mt < 2; mt++) {
                int r0 = wm * 32 + mt * 16 + lr;
                a[mt][0] = *reinterpret_cast<const unsigned*>(&As[s][r0][kb + 2 * lc]);
                a[mt][1] = *reinterpret_cast<const unsigned*>(&As[s][r0 + 8][kb + 2 * lc]);
                a[mt][2] = *reinterpret_cast<const unsigned*>(&As[s][r0][kb + 2 * lc + 8]);
                a[mt][3] = *reinterpret_cast<const unsigned*>(&As[s][r0 + 8][kb + 2 * lc + 8]);
            }
            unsigned bf[6][2];
            #pragma unroll
            for (int nt = 0; nt < 6; nt++) {
                int n0 = wn * 48 + nt * 8 + lr;
                bf[nt][0] = *reinterpret_cast<const unsigned*>(&Bs[s][n0][kb + 2 * lc]);
                bf[nt][1] = *reinterpret_cast<const unsigned*>(&Bs[s][n0][kb + 2 * lc + 8]);
            }
            #pragma unroll
            for (int mt = 0; mt < 2; mt++)
                #pragma unroll
                for (int nt = 0; nt < 6; nt++)
                    mma_bf16(acc[mt][nt][0], acc[mt][nt][1],
                             acc[mt][nt][2], acc[mt][nt][3],
                             a[mt][0], a[mt][1], a[mt][2], a[mt][3],
                             bf[nt][0], bf[nt][1]);
        }
        __syncthreads();
    }

    // ---- epilogue (c0:(r,c) c1:(r,c+1) c2:(r+8,c) c3:(r+8,c+1))
    __nv_bfloat16* Cb = reinterpret_cast<__nv_bfloat16*>(Cv);
    float*         Cf = reinterpret_cast<float*>(Cv);

    #pragma unroll
    for (int mt = 0; mt < 2; mt++) {
        long long row0 = rowBase + wm * 32 + mt * 16 + lr;
        long long row1 = row0 + 8;
        size_t d0 = 0, d1 = 0;
        if (EPI == 2) {
            d0 = dest_pixel((int)row0) * 96;
            d1 = dest_pixel((int)row1) * 96;
        }
        #pragma unroll
        for (int nt = 0; nt < 6; nt++) {
            int col = colBase + wn * 48 + nt * 8 + 2 * lc;
            float2 bb = *reinterpret_cast<const float2*>(&bias[col]);
            float v00 = acc[mt][nt][0] + bb.x;
            float v01 = acc[mt][nt][1] + bb.y;
            float v10 = acc[mt][nt][2] + bb.x;
            float v11 = acc[mt][nt][3] + bb.y;
            if (EPI == 0) {
                *reinterpret_cast<__nv_bfloat162*>(&Cb[row0 * N + col]) =
                    __floats2bfloat162_rn(v00, v01);
                *reinterpret_cast<__nv_bfloat162*>(&Cb[row1 * N + col]) =
                    __floats2bfloat162_rn(v10, v11);
            } else if (EPI == 1) {
                *reinterpret_cast<__nv_bfloat162*>(&Cb[row0 * N + col]) =
                    __floats2bfloat162_rn(gelu_exact(v00), gelu_exact(v01));
                *reinterpret_cast<__nv_bfloat162*>(&Cb[row1 * N + col]) =
                    __floats2bfloat162_rn(gelu_exact(v10), gelu_exact(v11));
            } else if (EPI == 2) {
                float2 r0v = *reinterpret_cast<const float2*>(&res[d0 + col]);
                float2 r1v = *reinterpret_cast<const float2*>(&res[d1 + col]);
                *reinterpret_cast<float2*>(&Cf[d0 + col]) =
                    make_float2(r0v.x + v00, r0v.y + v01);
                *reinterpret_cast<float2*>(&Cf[d1 + col]) =
                    make_float2(r1v.x + v10, r1v.y + v11);
            } else {
                float2 r0v = *reinterpret_cast<const float2*>(&res[row0 * 96 + col]);
                float2 r1v = *reinterpret_cast<const float2*>(&res[row1 * 96 + col]);
                *reinterpret_cast<float2*>(&Cf[row0 * 96 + col]) =
                    make_float2(r0v.x + v00, r0v.y + v01);
                *reinterpret_cast<float2*>(&Cf[row1 * 96 + col]) =
                    make_float2(r1v.x + v10, r1v.y + v11);
            }
        }
    }
}

// ---------------------------------------------------------------------------
// Window attention: one block per (window b_, head h). 64 threads = one
// softmax row per lane. bf16 in/out, fp32 math.
// ---------------------------------------------------------------------------
__device__ __forceinline__ int regid(int g)
{
    return g < 248 ? 0 : (g < 252 ? 1 : 2);
}

__device__ __forceinline__ void load32bf(const __nv_bfloat16* p, float* dst)
{
    const uint4* p4 = reinterpret_cast<const uint4*>(p);
    #pragma unroll
    for (int t = 0; t < 4; t++) {
        uint4 u = p4[t];
        unsigned arr[4] = {u.x, u.y, u.z, u.w};
        #pragma unroll
        for (int e = 0; e < 4; e++) {
            __nv_bfloat162 h = *reinterpret_cast<__nv_bfloat162*>(&arr[e]);
            float2 f = __bfloat1622float2(h);
            dst[t * 8 + e * 2]     = f.x;
            dst[t * 8 + e * 2 + 1] = f.y;
        }
    }
}

__global__ void __launch_bounds__(64) attn_kernel(
    const __nv_bfloat16* __restrict__ qkv, const float* __restrict__ rpb,
    __nv_bfloat16* __restrict__ ow)
{
    __shared__ __align__(16) float ks[64][32];
    __shared__ __align__(16) float vs[64][32];
    __shared__ float ss[64][64];
    __shared__ float rpbs[225];
    __shared__ int   ids[64];

    const int b_ = blockIdx.x;   // 0..8191
    const int h  = blockIdx.y;   // 0..2
    const int n  = threadIdx.x;  // 0..63

    for (int t = n; t < 225; t += 64) rpbs[t] = rpb[t * 3 + h];

    const int wh = (b_ >> 5) & 31, ww = b_ & 31;
    const int i_n = n >> 3, j_n = n & 7;
    const int id_n = regid(wh * 8 + i_n) * 3 + regid(ww * 8 + j_n);
    ids[n] = id_n;

    const __nv_bfloat16* base = qkv + (size_t)b_ * 64 * 288;
    float q[32];
    load32bf(base + n * 288 + h * 32, q);
    load32bf(base + n * 288 + 96 + h * 32, &ks[n][0]);
    load32bf(base + n * 288 + 192 + h * 32, &vs[n][0]);
    __syncthreads();

    const float scale = 0.17677669529663687f;  // 1/sqrt(32)

    float mx = -1e30f;
    for (int j = 0; j < 64; j++) {
        const float4* kr = reinterpret_cast<const float4*>(&ks[j][0]);
        float acc = 0.0f;
        #pragma unroll
        for (int t = 0; t < 8; t++) {
            float4 kv = kr[t];
            acc = fmaf(q[4*t],   kv.x, acc);
            acc = fmaf(q[4*t+1], kv.y, acc);
            acc = fmaf(q[4*t+2], kv.z, acc);
            acc = fmaf(q[4*t+3], kv.w, acc);
        }
        int i_j = j >> 3, j_j = j & 7;
        float bias = rpbs[(i_n - i_j + 7) * 15 + (j_n - j_j + 7)];
        float s = fmaf(acc, scale, bias) + (ids[j] == id_n ? 0.0f : -100.0f);
        ss[j][n] = s;
        mx = fmaxf(mx, s);
    }
    // each lane only touches its own ss column -> no block sync required
    float sum = 0.0f;
    for (int j = 0; j < 64; j++) {
        float p = expf(ss[j][n] - mx);
        ss[j][n] = p;
        sum += p;
    }
    float inv = 1.0f / sum;

    float o[32];
    #pragma unroll
    for (int d = 0; d < 32; d++) o[d] = 0.0f;
    for (int j = 0; j < 64; j++) {
        float p = ss[j][n];
        const float4* vr = reinterpret_cast<const float4*>(&vs[j][0]);
        #pragma unroll
        for (int t = 0; t < 8; t++) {
            float4 vv = vr[t];
            o[4*t]   = fmaf(p, vv.x, o[4*t]);
            o[4*t+1] = fmaf(p, vv.y, o[4*t+1]);
            o[4*t+2] = fmaf(p, vv.z, o[4*t+2]);
            o[4*t+3] = fmaf(p, vv.w, o[4*t+3]);
        }
    }

    __nv_bfloat162* o2 = reinterpret_cast<__nv_bfloat162*>(
        ow + ((size_t)b_ * 64 + n) * 96 + h * 32);
    #pragma unroll
    for (int t = 0; t < 16; t++)
        o2[t] = __floats2bfloat162_rn(o[2*t] * inv, o[2*t+1] * inv);
}

// ---------------------------------------------------------------------------
// launch
// ---------------------------------------------------------------------------
extern "C" void kernel_launch(void* const* d_in, const int* in_sizes, int n_in,
                              void* d_out, int out_size)
{
    const float* x      = (const float*)d_in[0];
    const float* n1w    = (const float*)d_in[1];
    const float* n1b    = (const float*)d_in[2];
    const float* qkv_w  = (const float*)d_in[3];
    const float* qkv_b  = (const float*)d_in[4];
    const float* rpb    = (const float*)d_in[5];
    const float* proj_w = (const float*)d_in[6];
    const float* proj_b = (const float*)d_in[7];
    const float* n2w    = (const float*)d_in[8];
    const float* n2b    = (const float*)d_in[9];
    const float* w1     = (const float*)d_in[10];
    const float* b1     = (const float*)d_in[11];
    const float* w2     = (const float*)d_in[12];
    const float* b2     = (const float*)d_in[13];
    float* out = (float*)d_out;

    __nv_bfloat16 *qkvp, *ap, *bp, *h1p, *wq, *wp, *w1b, *w2b;
    float *x1p;
    cudaGetSymbolAddress((void**)&qkvp, g_qkv);
    cudaGetSymbolAddress((void**)&ap,   g_a);
    cudaGetSymbolAddress((void**)&bp,   g_b);
    cudaGetSymbolAddress((void**)&h1p,  g_h1);
    cudaGetSymbolAddress((void**)&x1p,  g_x1);
    cudaGetSymbolAddress((void**)&wq,   g_wq);
    cudaGetSymbolAddress((void**)&wp,   g_wp);
    cudaGetSymbolAddress((void**)&w1b,  g_w1);
    cudaGetSymbolAddress((void**)&w2b,  g_w2);

    // 0. weights -> bf16
    cvt_kernel<<<108, 256>>>(qkv_w,  wq,  288 * 96);
    cvt_kernel<<< 36, 256>>>(proj_w, wp,   96 * 96);
    cvt_kernel<<<144, 256>>>(w1,     w1b, 384 * 96);
    cvt_kernel<<<144, 256>>>(w2,     w2b,  96 * 384);

    // 1. LN1 + shift + window partition          -> g_a (bf16)
    ln_kernel<true><<<65536, 256>>>(x, n1w, n1b, ap);
    // 2. QKV projection                          g_a -> g_qkv (bf16)
    hgemm_kernel<0><<<dim3(4096, 3), 256>>>(ap, wq, qkv_b, qkvp, nullptr, 96, 288);
    // 3. windowed attention                      g_qkv -> g_b (bf16)
    attn_kernel<<<dim3(8192, 3), 64>>>(qkvp, rpb, bp);
    // 4. proj + window-reverse + roll + residual g_b -> g_x1 (fp32, pixel order)
    hgemm_kernel<2><<<dim3(4096, 1), 256>>>(bp, wp, proj_b, x1p, x, 96, 96);
    // 5. LN2                                     g_x1 -> g_a (bf16)
    ln_kernel<false><<<65536, 256>>>(x1p, n2w, n2b, ap);
    // 6. fc1 + gelu                              g_a -> g_h1 (bf16)
    hgemm_kernel<1><<<dim3(4096, 4), 256>>>(ap, w1b, b1, h1p, nullptr, 96, 384);
    // 7. fc2 + residual                          g_h1 + g_x1 -> out (fp32)
    hgemm_kernel<3><<<dim3(4096, 1), 256>>>(h1p, w2b, b2, out, x1p, 384, 96);
}

// round 13
// speedup vs baseline: 4.4565x; 1.5478x over previous
#include <cuda_runtime.h>
#include <cuda_bf16.h>
#include <math.h>

// ---------------------------------------------------------------------------
// SwinBlock: B=8, H=W=256, C=96, WS=8, SS=4, NH=3, hd=32, DFF=384
// M = 524288 window-order token rows.
// Round 13 = round 12 + bugfix: rpbs table load was guarded by tid<675 in a
// 384-thread block, leaving heads 1/2 partially unloaded. Now a strided loop.
// Everything else re-audited (smem 47.5KB<48KB, alignment, fragment maps).
// ---------------------------------------------------------------------------

#define MROWS 524288

__device__ __nv_bfloat16 g_qkv[MROWS * 288];
__device__ __nv_bfloat16 g_a  [MROWS *  96];
__device__ __nv_bfloat16 g_b  [MROWS *  96];
__device__ __nv_bfloat16 g_h1 [MROWS * 384];
__device__ float         g_x1 [MROWS *  96];

__device__ __nv_bfloat16 g_wq[288 * 96];
__device__ __nv_bfloat16 g_wp[ 96 * 96];
__device__ __nv_bfloat16 g_w1[384 * 96];
__device__ __nv_bfloat16 g_w2[ 96 * 384];

// ---------------------------------------------------------------------------
// helpers
// ---------------------------------------------------------------------------
__device__ __forceinline__ void cp_async16(void* smem_dst, const void* gmem_src)
{
    unsigned s = (unsigned)__cvta_generic_to_shared(smem_dst);
    asm volatile("cp.async.cg.shared.global [%0], [%1], 16;\n" :: "r"(s), "l"(gmem_src));
}
__device__ __forceinline__ void cp_commit()
{
    asm volatile("cp.async.commit_group;\n");
}
template<int N>
__device__ __forceinline__ void cp_wait()
{
    asm volatile("cp.async.wait_group %0;\n" :: "n"(N));
}

__device__ __forceinline__ void mma_bf16(
    float& c0, float& c1, float& c2, float& c3,
    unsigned a0, unsigned a1, unsigned a2, unsigned a3,
    unsigned b0, unsigned b1)
{
    asm volatile(
        "mma.sync.aligned.m16n8k16.row.col.f32.bf16.bf16.f32 "
        "{%0,%1,%2,%3}, {%4,%5,%6,%7}, {%8,%9}, {%0,%1,%2,%3};\n"
        : "+f"(c0), "+f"(c1), "+f"(c2), "+f"(c3)
        : "r"(a0), "r"(a1), "r"(a2), "r"(a3), "r"(b0), "r"(b1));
}

__device__ __forceinline__ unsigned pack_bf162(float lo, float hi)
{
    __nv_bfloat162 h = __floats2bfloat162_rn(lo, hi);
    return *reinterpret_cast<unsigned*>(&h);
}

// e^x for x <= 0 (down to ~-120), FMA-only (no MUFU).
__device__ __forceinline__ float fast_exp(float x)
{
    float t = fmaxf(x * 1.44269504089f, -124.0f);
    float ti = rintf(t);
    float tf = t - ti;                       // [-0.5, 0.5]
    float p = fmaf(tf, 0.00961812911f, 0.0555041087f);
    p = fmaf(tf, p, 0.240226507f);
    p = fmaf(tf, p, 0.693147181f);
    p = fmaf(tf, p, 1.0f);
    return __int_as_float(__float_as_int(p) + (((int)ti) << 23));
}

// one-shot fp32 -> bf16 weight convert (all four weight mats)
__global__ void __launch_bounds__(256) cvt_all(
    const float* __restrict__ a, const float* __restrict__ b,
    const float* __restrict__ c, const float* __restrict__ d)
{
    int i = blockIdx.x * 256 + threadIdx.x;
    if (i < 288 * 96) g_wq[i] = __float2bfloat16(a[i]);
    if (i <  96 * 96) g_wp[i] = __float2bfloat16(b[i]);
    if (i < 384 * 96) { g_w1[i] = __float2bfloat16(c[i]);
                        g_w2[i] = __float2bfloat16(d[i]); }
}

// ---------------------------------------------------------------------------
// LN1 over C=96: one warp per row; bf16 out; shift+window-partition gather.
// ---------------------------------------------------------------------------
__global__ void __launch_bounds__(256) ln1_kernel(
    const float* __restrict__ x, const float* __restrict__ w,
    const float* __restrict__ b, __nv_bfloat16* __restrict__ out)
{
    int row  = blockIdx.x * 8 + (threadIdx.x >> 5);
    int lane = threadIdx.x & 31;

    int b_ = row >> 6, n = row & 63;
    int bb = b_ >> 10, wh = (b_ >> 5) & 31, ww = b_ & 31;
    int i = n >> 3, j = n & 7;
    int hh = (wh * 8 + i + 4) & 255;
    int wp = (ww * 8 + j + 4) & 255;
    size_t src = ((size_t)bb * 65536 + (size_t)hh * 256 + wp) * 96;

    float v0 = x[src + lane], v1 = x[src + lane + 32], v2 = x[src + lane + 64];
    float s = v0 + v1 + v2;
    #pragma unroll
    for (int o = 16; o > 0; o >>= 1) s += __shfl_xor_sync(0xffffffffu, s, o);
    float mean = s * (1.0f / 96.0f);
    float d0 = v0 - mean, d1 = v1 - mean, d2 = v2 - mean;
    float vv = d0 * d0 + d1 * d1 + d2 * d2;
    #pragma unroll
    for (int o = 16; o > 0; o >>= 1) vv += __shfl_xor_sync(0xffffffffu, vv, o);
    float rstd = rsqrtf(vv * (1.0f / 96.0f) + 1e-5f);

    size_t dst = (size_t)row * 96;
    out[dst + lane]      = __float2bfloat16(d0 * rstd * w[lane]      + b[lane]);
    out[dst + lane + 32] = __float2bfloat16(d1 * rstd * w[lane + 32] + b[lane + 32]);
    out[dst + lane + 64] = __float2bfloat16(d2 * rstd * w[lane + 64] + b[lane + 64]);
}

// ---------------------------------------------------------------------------
// bf16 GEMM with fused epilogues.
// EPI 0: store bf16 (qkv) | 1: gelu bf16 (fc1) | 3: +res -> fp32 (fc2/out)
// EPI 2 (proj): scatter + residual -> x1 fp32, PLUS fused LN2 -> bf16 lnout.
// ---------------------------------------------------------------------------
constexpr int BM = 128, BN = 96, BK = 32;
constexpr int KS = BK + 8;   // 40 halves (80B rows -> cp.async 16B-aligned)

__device__ __forceinline__ size_t dest_pixel(int r)
{
    int b_ = r >> 6, n = r & 63;
    int bb = b_ >> 10, wh = (b_ >> 5) & 31, ww = b_ & 31;
    int i = n >> 3, j = n & 7;
    int hh = (wh * 8 + i + 4) & 255;
    int wp = (ww * 8 + j + 4) & 255;
    return (size_t)bb * 65536 + (size_t)hh * 256 + wp;
}

__device__ __forceinline__ float gelu_exact(float v)
{
    return 0.5f * v * (1.0f + erff(v * 0.70710678118654752f));
}

template<int EPI>
__global__ void __launch_bounds__(256, 2) hgemm_kernel(
    const __nv_bfloat16* __restrict__ A, const __nv_bfloat16* __restrict__ B,
    const float* __restrict__ bias, void* __restrict__ Cv,
    const float* __restrict__ res, int K, int N,
    const float* __restrict__ lnw, const float* __restrict__ lnb,
    __nv_bfloat16* __restrict__ lnout)
{
    __shared__ __align__(16) __nv_bfloat16 As[2][BM][KS];
    __shared__ __align__(16) __nv_bfloat16 Bs[2][BN][KS];

    const int tid  = threadIdx.x;
    const int wid  = tid >> 5;
    const int lane = tid & 31;
    const int wm   = wid >> 1;
    const int wn   = wid & 1;
    const int lr   = lane >> 2;
    const int lc   = lane & 3;

    const long long rowBase = (long long)blockIdx.x * BM;
    const int colBase = blockIdx.y * BN;

    const int rA0 = tid >> 2,         cA0 = (tid & 3) * 8;
    const int rA1 = (tid + 256) >> 2;
    const int nK = K / BK;

    float acc[2][6][4];
    #pragma unroll
    for (int mt = 0; mt < 2; mt++)
        #pragma unroll
        for (int nt = 0; nt < 6; nt++)
            #pragma unroll
            for (int e = 0; e < 4; e++) acc[mt][nt][e] = 0.0f;

    {
        cp_async16(&As[0][rA0][cA0], A + (rowBase + rA0) * K + cA0);
        cp_async16(&As[0][rA1][cA0], A + (rowBase + rA1) * K + cA0);
        cp_async16(&Bs[0][rA0][cA0], B + (size_t)(colBase + rA0) * K + cA0);
        if (tid < 128)
            cp_async16(&Bs[0][rA1][cA0], B + (size_t)(colBase + rA1) * K + cA0);
        cp_commit();
    }

    for (int it = 0; it < nK; it++) {
        if (it + 1 < nK) {
            const int s = (it + 1) & 1;
            const int k0 = (it + 1) * BK;
            cp_async16(&As[s][rA0][cA0], A + (rowBase + rA0) * K + k0 + cA0);
            cp_async16(&As[s][rA1][cA0], A + (rowBase + rA1) * K + k0 + cA0);
            cp_async16(&Bs[s][rA0][cA0], B + (size_t)(colBase + rA0) * K + k0 + cA0);
            if (tid < 128)
                cp_async16(&Bs[s][rA1][cA0], B + (size_t)(colBase + rA1) * K + k0 + cA0);
            cp_commit();
            cp_wait<1>();
        } else {
            cp_wait<0>();
        }
        __syncthreads();

        const int s = it & 1;
        #pragma unroll
        for (int kb = 0; kb < BK; kb += 16) {
            unsigned a[2][4];
            #pragma unroll
            for (int mt = 0; mt < 2; mt++) {
                int r0 = wm * 32 + mt * 16 + lr;
                a[mt][0] = *reinterpret_cast<const unsigned*>(&As[s][r0][kb + 2 * lc]);
                a[mt][1] = *reinterpret_cast<const unsigned*>(&As[s][r0 + 8][kb + 2 * lc]);
                a[mt][2] = *reinterpret_cast<const unsigned*>(&As[s][r0][kb + 2 * lc + 8]);
                a[mt][3] = *reinterpret_cast<const unsigned*>(&As[s][r0 + 8][kb + 2 * lc + 8]);
            }
            unsigned bf[6][2];
            #pragma unroll
            for (int nt = 0; nt < 6; nt++) {
                int n0 = wn * 48 + nt * 8 + lr;
                bf[nt][0] = *reinterpret_cast<const unsigned*>(&Bs[s][n0][kb + 2 * lc]);
                bf[nt][1] = *reinterpret_cast<const unsigned*>(&Bs[s][n0][kb + 2 * lc + 8]);
            }
            #pragma unroll
            for (int mt = 0; mt < 2; mt++)
                #pragma unroll
                for (int nt = 0; nt < 6; nt++)
                    mma_bf16(acc[mt][nt][0], acc[mt][nt][1],
                             acc[mt][nt][2], acc[mt][nt][3],
                             a[mt][0], a[mt][1], a[mt][2], a[mt][3],
                             bf[nt][0], bf[nt][1]);
        }
        __syncthreads();
    }

    __nv_bfloat16* Cb = reinterpret_cast<__nv_bfloat16*>(Cv);
    float*         Cf = reinterpret_cast<float*>(Cv);

    if constexpr (EPI == 2) {
        // proj: x1 = res(scatter) + v, then fused LN2 over the 96-wide row.
        __shared__ float2 red[2][128];     // [wn][local row] -> (sum, sumsq)
        float rsum[2][2] = {{0.f,0.f},{0.f,0.f}};
        float rsq [2][2] = {{0.f,0.f},{0.f,0.f}};
        size_t dpx[2][2];

        #pragma unroll
        for (int mt = 0; mt < 2; mt++) {
            long long row0 = rowBase + wm * 32 + mt * 16 + lr;
            dpx[mt][0] = dest_pixel((int)row0) * 96;
            dpx[mt][1] = dest_pixel((int)(row0 + 8)) * 96;
            #pragma unroll
            for (int nt = 0; nt < 6; nt++) {
                int col = wn * 48 + nt * 8 + 2 * lc;
                float2 bb = *reinterpret_cast<const float2*>(&bias[col]);
                float2 r0v = *reinterpret_cast<const float2*>(&res[dpx[mt][0] + col]);
                float2 r1v = *reinterpret_cast<const float2*>(&res[dpx[mt][1] + col]);
                float x00 = r0v.x + acc[mt][nt][0] + bb.x;
                float x01 = r0v.y + acc[mt][nt][1] + bb.y;
                float x10 = r1v.x + acc[mt][nt][2] + bb.x;
                float x11 = r1v.y + acc[mt][nt][3] + bb.y;
                *reinterpret_cast<float2*>(&Cf[dpx[mt][0] + col]) = make_float2(x00, x01);
                *reinterpret_cast<float2*>(&Cf[dpx[mt][1] + col]) = make_float2(x10, x11);
                acc[mt][nt][0] = x00; acc[mt][nt][1] = x01;
                acc[mt][nt][2] = x10; acc[mt][nt][3] = x11;
                rsum[mt][0] += x00 + x01;  rsq[mt][0] += x00*x00 + x01*x01;
                rsum[mt][1] += x10 + x11;  rsq[mt][1] += x10*x10 + x11*x11;
            }
        }
        #pragma unroll
        for (int mt = 0; mt < 2; mt++)
            #pragma unroll
            for (int rr = 0; rr < 2; rr++) {
                rsum[mt][rr] += __shfl_xor_sync(0xffffffffu, rsum[mt][rr], 1);
                rsum[mt][rr] += __shfl_xor_sync(0xffffffffu, rsum[mt][rr], 2);
                rsq [mt][rr] += __shfl_xor_sync(0xffffffffu, rsq [mt][rr], 1);
                rsq [mt][rr] += __shfl_xor_sync(0xffffffffu, rsq [mt][rr], 2);
            }
        if (lc == 0) {
            #pragma unroll
            for (int mt = 0; mt < 2; mt++)
                #pragma unroll
                for (int rr = 0; rr < 2; rr++)
                    red[wn][wm * 32 + mt * 16 + lr + rr * 8] =
                        make_float2(rsum[mt][rr], rsq[mt][rr]);
        }
        __syncthreads();
        #pragma unroll
        for (int mt = 0; mt < 2; mt++) {
            #pragma unroll
            for (int rr = 0; rr < 2; rr++) {
                int rl = wm * 32 + mt * 16 + lr + rr * 8;
                float2 p0 = red[0][rl], p1 = red[1][rl];
                float mean = (p0.x + p1.x) * (1.0f / 96.0f);
                float var  = (p0.y + p1.y) * (1.0f / 96.0f) - mean * mean;
                float rstd = rsqrtf(var + 1e-5f);
                #pragma unroll
                for (int nt = 0; nt < 6; nt++) {
                    int col = wn * 48 + nt * 8 + 2 * lc;
                    float w0 = lnw[col], w1v = lnw[col + 1];
                    float b0 = lnb[col], b1v = lnb[col + 1];
                    float y0 = (acc[mt][nt][2 * rr]     - mean) * rstd * w0 + b0;
                    float y1 = (acc[mt][nt][2 * rr + 1] - mean) * rstd * w1v + b1v;
                    __nv_bfloat162 h = __floats2bfloat162_rn(y0, y1);
                    *reinterpret_cast<__nv_bfloat162*>(&lnout[dpx[mt][rr] + col]) = h;
                }
            }
        }
    } else {
        #pragma unroll
        for (int mt = 0; mt < 2; mt++) {
            long long row0 = rowBase + wm * 32 + mt * 16 + lr;
            long long row1 = row0 + 8;
            #pragma unroll
            for (int nt = 0; nt < 6; nt++) {
                int col = colBase + wn * 48 + nt * 8 + 2 * lc;
                float2 bb = *reinterpret_cast<const float2*>(&bias[col]);
                float v00 = acc[mt][nt][0] + bb.x;
                float v01 = acc[mt][nt][1] + bb.y;
                float v10 = acc[mt][nt][2] + bb.x;
                float v11 = acc[mt][nt][3] + bb.y;
                if (EPI == 0) {
                    *reinterpret_cast<__nv_bfloat162*>(&Cb[row0 * N + col]) =
                        __floats2bfloat162_rn(v00, v01);
                    *reinterpret_cast<__nv_bfloat162*>(&Cb[row1 * N + col]) =
                        __floats2bfloat162_rn(v10, v11);
                } else if (EPI == 1) {
                    *reinterpret_cast<__nv_bfloat162*>(&Cb[row0 * N + col]) =
                        __floats2bfloat162_rn(gelu_exact(v00), gelu_exact(v01));
                    *reinterpret_cast<__nv_bfloat162*>(&Cb[row1 * N + col]) =
                        __floats2bfloat162_rn(gelu_exact(v10), gelu_exact(v11));
                } else {
                    float2 r0v = *reinterpret_cast<const float2*>(&res[row0 * 96 + col]);
                    float2 r1v = *reinterpret_cast<const float2*>(&res[row1 * 96 + col]);
                    *reinterpret_cast<float2*>(&Cf[row0 * 96 + col]) =
                        make_float2(r0v.x + v00, r0v.y + v01);
                    *reinterpret_cast<float2*>(&Cf[row1 * 96 + col]) =
                        make_float2(r1v.x + v10, r1v.y + v11);
                }
            }
        }
    }
}

// ---------------------------------------------------------------------------
// Tensorized window attention: one block per window, 384 threads = 12 warps
// (3 heads x 4 warps x 16 rows). bf16 m16n8k16, FA-style S->P fragment reuse,
// FMA-only exp. fp32 softmax stats.
// ---------------------------------------------------------------------------
__device__ __forceinline__ int regid(int g)
{
    return g < 248 ? 0 : (g < 252 ? 1 : 2);
}

__global__ void __launch_bounds__(384) attn_kernel(
    const __nv_bfloat16* __restrict__ qkv, const float* __restrict__ rpb,
    __nv_bfloat16* __restrict__ ow)
{
    __shared__ __align__(16) __nv_bfloat16 Qs[3][64][40];   // 15360 B
    __shared__ __align__(16) __nv_bfloat16 Ks[3][64][40];   // 15360 B
    __shared__ __align__(16) __nv_bfloat16 Vt[3][32][72];   // 13824 B (V^T)
    __shared__ float rpbs[3][225];                          //  2700 B
    __shared__ int   ids[64];                               //   256 B

    const int b_  = blockIdx.x;
    const int tid = threadIdx.x;
    const int wid = tid >> 5, lane = tid & 31;
    const int hg  = wid >> 2, ww = wid & 3;
    const int lr  = lane >> 2, lc = lane & 3;

    // FIX (round 13): strided loop — 384 threads must cover all 675 entries.
    for (int t = tid; t < 675; t += 384)
        rpbs[t / 225][t % 225] = rpb[(t % 225) * 3 + t / 225];
    const int whc = (b_ >> 5) & 31, wwc = b_ & 31;
    if (tid < 64) {
        int i = tid >> 3, j = tid & 7;
        ids[tid] = regid(whc * 8 + i) * 3 + regid(wwc * 8 + j);
    }

    const __nv_bfloat16* base = qkv + (size_t)b_ * 64 * 288;

    // Q/K via cp.async: 1536 16B chunks over 384 threads
    #pragma unroll
    for (int i = 0; i < 4; i++) {
        int c = i * 384 + tid;
        int qk = (c >= 768) ? 1 : 0;
        int rem = c - qk * 768;
        int h = rem >> 8, rr = rem & 255;
        int row = rr >> 2, off = (rr & 3) * 8;
        const __nv_bfloat16* src = base + row * 288 + qk * 96 + h * 32 + off;
        __nv_bfloat16* dst = qk ? &Ks[h][row][off] : &Qs[h][row][off];
        cp_async16(dst, src);
    }
    cp_commit();

    // V load + transpose (scalar scatter, one-time)
    {
        int h = tid >> 7;               // 0..2
        int r = (tid & 127) >> 1;       // 0..63
        int cg = tid & 1;               // 16-col group
        const uint4* src = reinterpret_cast<const uint4*>(
            base + r * 288 + 192 + h * 32 + cg * 16);
        uint4 u0 = src[0], u1 = src[1];
        unsigned w8[8] = {u0.x, u0.y, u0.z, u0.w, u1.x, u1.y, u1.z, u1.w};
        #pragma unroll
        for (int e = 0; e < 8; e++) {
            __nv_bfloat162 h2 = *reinterpret_cast<__nv_bfloat162*>(&w8[e]);
            Vt[h][cg * 16 + 2 * e][r]     = __low2bfloat16(h2);
            Vt[h][cg * 16 + 2 * e + 1][r] = __high2bfloat16(h2);
        }
    }
    cp_wait<0>();
    __syncthreads();

    const int r0 = ww * 16;
    const int ra = r0 + lr, rb = ra + 8;
    const float scale = 0.17677669529663687f;   // 1/sqrt(32)

    // Q fragments (both k-chunks)
    unsigned qf[2][4];
    #pragma unroll
    for (int kc = 0; kc < 2; kc++) {
        int kb = kc * 16;
        qf[kc][0] = *reinterpret_cast<const unsigned*>(&Qs[hg][ra][kb + 2 * lc]);
        qf[kc][1] = *reinterpret_cast<const unsigned*>(&Qs[hg][rb][kb + 2 * lc]);
        qf[kc][2] = *reinterpret_cast<const unsigned*>(&Qs[hg][ra][kb + 2 * lc + 8]);
        qf[kc][3] = *reinterpret_cast<const unsigned*>(&Qs[hg][rb][kb + 2 * lc + 8]);
    }

    // S = Q K^T : 8 n-tiles x 2 k-chunks
    float S[8][4];
    #pragma unroll
    for (int nt = 0; nt < 8; nt++) { S[nt][0]=S[nt][1]=S[nt][2]=S[nt][3]=0.f; }
    #pragma unroll
    for (int nt = 0; nt < 8; nt++) {
        int n0 = nt * 8;
        #pragma unroll
        for (int kc = 0; kc < 2; kc++) {
            int kb = kc * 16;
            unsigned b0 = *reinterpret_cast<const unsigned*>(&Ks[hg][n0 + lr][kb + 2 * lc]);
            unsigned b1 = *reinterpret_cast<const unsigned*>(&Ks[hg][n0 + lr][kb + 2 * lc + 8]);
            mma_bf16(S[nt][0], S[nt][1], S[nt][2], S[nt][3],
                     qf[kc][0], qf[kc][1], qf[kc][2], qf[kc][3], b0, b1);
        }
    }

    // bias + mask + scale, then row max
    const int i_a = ra >> 3, j_a = ra & 7;
    const int i_b = rb >> 3, j_b = rb & 7;
    const int id_a = ids[ra], id_b = ids[rb];
    float mxa = -1e30f, mxb = -1e30f;
    #pragma unroll
    for (int nt = 0; nt < 8; nt++) {
        #pragma unroll
        for (int e = 0; e < 2; e++) {
            int c = nt * 8 + 2 * lc + e;
            int ic = c >> 3, jc = c & 7;
            int idc = ids[c];
            float ba = rpbs[hg][(i_a - ic + 7) * 15 + (j_a - jc + 7)]
                     + (id_a == idc ? 0.0f : -100.0f);
            float bb = rpbs[hg][(i_b - ic + 7) * 15 + (j_b - jc + 7)]
                     + (id_b == idc ? 0.0f : -100.0f);
            S[nt][e]     = fmaf(S[nt][e],     scale, ba);
            S[nt][2 + e] = fmaf(S[nt][2 + e], scale, bb);
            mxa = fmaxf(mxa, S[nt][e]);
            mxb = fmaxf(mxb, S[nt][2 + e]);
        }
    }
    mxa = fmaxf(mxa, __shfl_xor_sync(0xffffffffu, mxa, 1));
    mxa = fmaxf(mxa, __shfl_xor_sync(0xffffffffu, mxa, 2));
    mxb = fmaxf(mxb, __shfl_xor_sync(0xffffffffu, mxb, 1));
    mxb = fmaxf(mxb, __shfl_xor_sync(0xffffffffu, mxb, 2));

    float sa = 0.0f, sb = 0.0f;
    #pragma unroll
    for (int nt = 0; nt < 8; nt++) {
        #pragma unroll
        for (int e = 0; e < 2; e++) {
            float pa = fast_exp(S[nt][e] - mxa);
            float pb = fast_exp(S[nt][2 + e] - mxb);
            S[nt][e] = pa;  S[nt][2 + e] = pb;
            sa += pa;  sb += pb;
        }
    }
    sa += __shfl_xor_sync(0xffffffffu, sa, 1);
    sa += __shfl_xor_sync(0xffffffffu, sa, 2);
    sb += __shfl_xor_sync(0xffffffffu, sb, 1);
    sb += __shfl_xor_sync(0xffffffffu, sb, 2);
    float inva = 1.0f / sa, invb = 1.0f / sb;

    // repack P into A-fragments (C-frag layout == A-frag layout pairing)
    unsigned P[4][4];
    #pragma unroll
    for (int kc = 0; kc < 4; kc++) {
        P[kc][0] = pack_bf162(S[2 * kc][0],     S[2 * kc][1]);
        P[kc][1] = pack_bf162(S[2 * kc][2],     S[2 * kc][3]);
        P[kc][2] = pack_bf162(S[2 * kc + 1][0], S[2 * kc + 1][1]);
        P[kc][3] = pack_bf162(S[2 * kc + 1][2], S[2 * kc + 1][3]);
    }

    // O = P V : 4 k-chunks x 4 d-tiles
    float O[4][4];
    #pragma unroll
    for (int dt = 0; dt < 4; dt++) { O[dt][0]=O[dt][1]=O[dt][2]=O[dt][3]=0.f; }
    #pragma unroll
    for (int kc = 0; kc < 4; kc++) {
        int j0 = kc * 16;
        #pragma unroll
        for (int dt = 0; dt < 4; dt++) {
            int d0 = dt * 8;
            unsigned b0 = *reinterpret_cast<const unsigned*>(&Vt[hg][d0 + lr][j0 + 2 * lc]);
            unsigned b1 = *reinterpret_cast<const unsigned*>(&Vt[hg][d0 + lr][j0 + 2 * lc + 8]);
            mma_bf16(O[dt][0], O[dt][1], O[dt][2], O[dt][3],
                     P[kc][0], P[kc][1], P[kc][2], P[kc][3], b0, b1);
        }
    }

    // store
    size_t obase = (size_t)b_ * 64 * 96 + hg * 32;
    #pragma unroll
    for (int dt = 0; dt < 4; dt++) {
        int d = dt * 8 + 2 * lc;
        *reinterpret_cast<__nv_bfloat162*>(&ow[obase + (size_t)ra * 96 + d]) =
            __floats2bfloat162_rn(O[dt][0] * inva, O[dt][1] * inva);
        *reinterpret_cast<__nv_bfloat162*>(&ow[obase + (size_t)rb * 96 + d]) =
            __floats2bfloat162_rn(O[dt][2] * invb, O[dt][3] * invb);
    }
}

// ---------------------------------------------------------------------------
// launch
// ---------------------------------------------------------------------------
extern "C" void kernel_launch(void* const* d_in, const int* in_sizes, int n_in,
                              void* d_out, int out_size)
{
    const float* x      = (const float*)d_in[0];
    const float* n1w    = (const float*)d_in[1];
    const float* n1b    = (const float*)d_in[2];
    const float* qkv_w  = (const float*)d_in[3];
    const float* qkv_b  = (const float*)d_in[4];
    const float* rpb    = (const float*)d_in[5];
    const float* proj_w = (const float*)d_in[6];
    const float* proj_b = (const float*)d_in[7];
    const float* n2w    = (const float*)d_in[8];
    const float* n2b    = (const float*)d_in[9];
    const float* w1     = (const float*)d_in[10];
    const float* b1     = (const float*)d_in[11];
    const float* w2     = (const float*)d_in[12];
    const float* b2     = (const float*)d_in[13];
    float* out = (float*)d_out;

    __nv_bfloat16 *qkvp, *ap, *bp, *h1p, *wq, *wp, *w1b, *w2b;
    float *x1p;
    cudaGetSymbolAddress((void**)&qkvp, g_qkv);
    cudaGetSymbolAddress((void**)&ap,   g_a);
    cudaGetSymbolAddress((void**)&bp,   g_b);
    cudaGetSymbolAddress((void**)&h1p,  g_h1);
    cudaGetSymbolAddress((void**)&x1p,  g_x1);
    cudaGetSymbolAddress((void**)&wq,   g_wq);
    cudaGetSymbolAddress((void**)&wp,   g_wp);
    cudaGetSymbolAddress((void**)&w1b,  g_w1);
    cudaGetSymbolAddress((void**)&w2b,  g_w2);

    // 0. weights -> bf16 (single launch)
    cvt_all<<<144, 256>>>(qkv_w, proj_w, w1, w2);
    // 1. LN1 + shift + window partition           -> g_a (bf16)
    ln1_kernel<<<65536, 256>>>(x, n1w, n1b, ap);
    // 2. QKV projection                           g_a -> g_qkv (bf16)
    hgemm_kernel<0><<<dim3(4096, 3), 256>>>(ap, wq, qkv_b, qkvp, nullptr, 96, 288,
                                            nullptr, nullptr, nullptr);
    // 3. tensorized windowed attention            g_qkv -> g_b (bf16)
    attn_kernel<<<8192, 384>>>(qkvp, rpb, bp);
    // 4. proj + scatter + residual -> x1 (fp32), fused LN2 -> g_a (bf16)
    hgemm_kernel<2><<<dim3(4096, 1), 256>>>(bp, wp, proj_b, x1p, x, 96, 96,
                                            n2w, n2b, ap);
    // 5. fc1 + gelu                               g_a -> g_h1 (bf16)
    hgemm_kernel<1><<<dim3(4096, 4), 256>>>(ap, w1b, b1, h1p, nullptr, 96, 384,
                                            nullptr, nullptr, nullptr);
    // 6. fc2 + residual                           g_h1 + g_x1 -> out (fp32)
    hgemm_kernel<3><<<dim3(4096, 1), 256>>>(h1p, w2b, b2, out, x1p, 384, 96,
                                            nullptr, nullptr, nullptr);
}

// round 14
// speedup vs baseline: 5.1440x; 1.1542x over previous
#include <cuda_runtime.h>
#include <cuda_bf16.h>
#include <math.h>

// ---------------------------------------------------------------------------
// SwinBlock: B=8, H=W=256, C=96, WS=8, SS=4, NH=3, hd=32, DFF=384
// M = 524288 window-order token rows.
// Round 14 = round 13 + fused MLP: fc1+gelu+fc2 in ONE kernel, h1 never hits
// DRAM (-805MB traffic). Dynamic smem 73.2KB (As/Hs/Ws), 2 blocks/SM.
// Rest of pipeline byte-identical to the passing round-13 source.
// ---------------------------------------------------------------------------

#define MROWS 524288

__device__ __nv_bfloat16 g_qkv[MROWS * 288];
__device__ __nv_bfloat16 g_a  [MROWS *  96];
__device__ __nv_bfloat16 g_b  [MROWS *  96];
__device__ float         g_x1 [MROWS *  96];

__device__ __nv_bfloat16 g_wq[288 * 96];
__device__ __nv_bfloat16 g_wp[ 96 * 96];
__device__ __nv_bfloat16 g_w1[384 * 96];
__device__ __nv_bfloat16 g_w2[ 96 * 384];

// ---------------------------------------------------------------------------
// helpers
// ---------------------------------------------------------------------------
__device__ __forceinline__ void cp_async16(void* smem_dst, const void* gmem_src)
{
    unsigned s = (unsigned)__cvta_generic_to_shared(smem_dst);
    asm volatile("cp.async.cg.shared.global [%0], [%1], 16;\n" :: "r"(s), "l"(gmem_src));
}
__device__ __forceinline__ void cp_commit()
{
    asm volatile("cp.async.commit_group;\n");
}
template<int N>
__device__ __forceinline__ void cp_wait()
{
    asm volatile("cp.async.wait_group %0;\n" :: "n"(N));
}

__device__ __forceinline__ void mma_bf16(
    float& c0, float& c1, float& c2, float& c3,
    unsigned a0, unsigned a1, unsigned a2, unsigned a3,
    unsigned b0, unsigned b1)
{
    asm volatile(
        "mma.sync.aligned.m16n8k16.row.col.f32.bf16.bf16.f32 "
        "{%0,%1,%2,%3}, {%4,%5,%6,%7}, {%8,%9}, {%0,%1,%2,%3};\n"
        : "+f"(c0), "+f"(c1), "+f"(c2), "+f"(c3)
        : "r"(a0), "r"(a1), "r"(a2), "r"(a3), "r"(b0), "r"(b1));
}

__device__ __forceinline__ unsigned pack_bf162(float lo, float hi)
{
    __nv_bfloat162 h = __floats2bfloat162_rn(lo, hi);
    return *reinterpret_cast<unsigned*>(&h);
}

// e^x for x <= 0 (down to ~-120), FMA-only (no MUFU).
__device__ __forceinline__ float fast_exp(float x)
{
    float t = fmaxf(x * 1.44269504089f, -124.0f);
    float ti = rintf(t);
    float tf = t - ti;                       // [-0.5, 0.5]
    float p = fmaf(tf, 0.00961812911f, 0.0555041087f);
    p = fmaf(tf, p, 0.240226507f);
    p = fmaf(tf, p, 0.693147181f);
    p = fmaf(tf, p, 1.0f);
    return __int_as_float(__float_as_int(p) + (((int)ti) << 23));
}

// one-shot fp32 -> bf16 weight convert (all four weight mats)
__global__ void __launch_bounds__(256) cvt_all(
    const float* __restrict__ a, const float* __restrict__ b,
    const float* __restrict__ c, const float* __restrict__ d)
{
    int i = blockIdx.x * 256 + threadIdx.x;
    if (i < 288 * 96) g_wq[i] = __float2bfloat16(a[i]);
    if (i <  96 * 96) g_wp[i] = __float2bfloat16(b[i]);
    if (i < 384 * 96) { g_w1[i] = __float2bfloat16(c[i]);
                        g_w2[i] = __float2bfloat16(d[i]); }
}

// ---------------------------------------------------------------------------
// LN1 over C=96: one warp per row; bf16 out; shift+window-partition gather.
// ---------------------------------------------------------------------------
__global__ void __launch_bounds__(256) ln1_kernel(
    const float* __restrict__ x, const float* __restrict__ w,
    const float* __restrict__ b, __nv_bfloat16* __restrict__ out)
{
    int row  = blockIdx.x * 8 + (threadIdx.x >> 5);
    int lane = threadIdx.x & 31;

    int b_ = row >> 6, n = row & 63;
    int bb = b_ >> 10, wh = (b_ >> 5) & 31, ww = b_ & 31;
    int i = n >> 3, j = n & 7;
    int hh = (wh * 8 + i + 4) & 255;
    int wp = (ww * 8 + j + 4) & 255;
    size_t src = ((size_t)bb * 65536 + (size_t)hh * 256 + wp) * 96;

    float v0 = x[src + lane], v1 = x[src + lane + 32], v2 = x[src + lane + 64];
    float s = v0 + v1 + v2;
    #pragma unroll
    for (int o = 16; o > 0; o >>= 1) s += __shfl_xor_sync(0xffffffffu, s, o);
    float mean = s * (1.0f / 96.0f);
    float d0 = v0 - mean, d1 = v1 - mean, d2 = v2 - mean;
    float vv = d0 * d0 + d1 * d1 + d2 * d2;
    #pragma unroll
    for (int o = 16; o > 0; o >>= 1) vv += __shfl_xor_sync(0xffffffffu, vv, o);
    float rstd = rsqrtf(vv * (1.0f / 96.0f) + 1e-5f);

    size_t dst = (size_t)row * 96;
    out[dst + lane]      = __float2bfloat16(d0 * rstd * w[lane]      + b[lane]);
    out[dst + lane + 32] = __float2bfloat16(d1 * rstd * w[lane + 32] + b[lane + 32]);
    out[dst + lane + 64] = __float2bfloat16(d2 * rstd * w[lane + 64] + b[lane + 64]);
}

// ---------------------------------------------------------------------------
// bf16 GEMM with fused epilogues.
// EPI 0: store bf16 (qkv)
// EPI 2 (proj): scatter + residual -> x1 fp32, PLUS fused LN2 -> bf16 lnout.
// ---------------------------------------------------------------------------
constexpr int BM = 128, BN = 96, BK = 32;
constexpr int KS = BK + 8;   // 40 halves

__device__ __forceinline__ size_t dest_pixel(int r)
{
    int b_ = r >> 6, n = r & 63;
    int bb = b_ >> 10, wh = (b_ >> 5) & 31, ww = b_ & 31;
    int i = n >> 3, j = n & 7;
    int hh = (wh * 8 + i + 4) & 255;
    int wp = (ww * 8 + j + 4) & 255;
    return (size_t)bb * 65536 + (size_t)hh * 256 + wp;
}

__device__ __forceinline__ float gelu_exact(float v)
{
    return 0.5f * v * (1.0f + erff(v * 0.70710678118654752f));
}

template<int EPI>
__global__ void __launch_bounds__(256, 2) hgemm_kernel(
    const __nv_bfloat16* __restrict__ A, const __nv_bfloat16* __restrict__ B,
    const float* __restrict__ bias, void* __restrict__ Cv,
    const float* __restrict__ res, int K, int N,
    const float* __restrict__ lnw, const float* __restrict__ lnb,
    __nv_bfloat16* __restrict__ lnout)
{
    __shared__ __align__(16) __nv_bfloat16 As[2][BM][KS];
    __shared__ __align__(16) __nv_bfloat16 Bs[2][BN][KS];

    const int tid  = threadIdx.x;
    const int wid  = tid >> 5;
    const int lane = tid & 31;
    const int wm   = wid >> 1;
    const int wn   = wid & 1;
    const int lr   = lane >> 2;
    const int lc   = lane & 3;

    const long long rowBase = (long long)blockIdx.x * BM;
    const int colBase = blockIdx.y * BN;

    const int rA0 = tid >> 2,         cA0 = (tid & 3) * 8;
    const int rA1 = (tid + 256) >> 2;
    const int nK = K / BK;

    float acc[2][6][4];
    #pragma unroll
    for (int mt = 0; mt < 2; mt++)
        #pragma unroll
        for (int nt = 0; nt < 6; nt++)
            #pragma unroll
            for (int e = 0; e < 4; e++) acc[mt][nt][e] = 0.0f;

    {
        cp_async16(&As[0][rA0][cA0], A + (rowBase + rA0) * K + cA0);
        cp_async16(&As[0][rA1][cA0], A + (rowBase + rA1) * K + cA0);
        cp_async16(&Bs[0][rA0][cA0], B + (size_t)(colBase + rA0) * K + cA0);
        if (tid < 128)
            cp_async16(&Bs[0][rA1][cA0], B + (size_t)(colBase + rA1) * K + cA0);
        cp_commit();
    }

    for (int it = 0; it < nK; it++) {
        if (it + 1 < nK) {
            const int s = (it + 1) & 1;
            const int k0 = (it + 1) * BK;
            cp_async16(&As[s][rA0][cA0], A + (rowBase + rA0) * K + k0 + cA0);
            cp_async16(&As[s][rA1][cA0], A + (rowBase + rA1) * K + k0 + cA0);
            cp_async16(&Bs[s][rA0][cA0], B + (size_t)(colBase + rA0) * K + k0 + cA0);
            if (tid < 128)
                cp_async16(&Bs[s][rA1][cA0], B + (size_t)(colBase + rA1) * K + k0 + cA0);
            cp_commit();
            cp_wait<1>();
        } else {
            cp_wait<0>();
        }
        __syncthreads();

        const int s = it & 1;
        #pragma unroll
        for (int kb = 0; kb < BK; kb += 16) {
            unsigned a[2][4];
            #pragma unroll
            for (int mt = 0; mt < 2; mt++) {
                int r0 = wm * 32 + mt * 16 + lr;
                a[mt][0] = *reinterpret_cast<const unsigned*>(&As[s][r0][kb + 2 * lc]);
                a[mt][1] = *reinterpret_cast<const unsigned*>(&As[s][r0 + 8][kb + 2 * lc]);
                a[mt][2] = *reinterpret_cast<const unsigned*>(&As[s][r0][kb + 2 * lc + 8]);
                a[mt][3] = *reinterpret_cast<const unsigned*>(&As[s][r0 + 8][kb + 2 * lc + 8]);
            }
            unsigned bf[6][2];
            #pragma unroll
            for (int nt = 0; nt < 6; nt++) {
                int n0 = wn * 48 + nt * 8 + lr;
                bf[nt][0] = *reinterpret_cast<const unsigned*>(&Bs[s][n0][kb + 2 * lc]);
                bf[nt][1] = *reinterpret_cast<const unsigned*>(&Bs[s][n0][kb + 2 * lc + 8]);
            }
            #pragma unroll
            for (int mt = 0; mt < 2; mt++)
                #pragma unroll
                for (int nt = 0; nt < 6; nt++)
                    mma_bf16(acc[mt][nt][0], acc[mt][nt][1],
                             acc[mt][nt][2], acc[mt][nt][3],
                             a[mt][0], a[mt][1], a[mt][2], a[mt][3],
                             bf[nt][0], bf[nt][1]);
        }
        __syncthreads();
    }

    __nv_bfloat16* Cb = reinterpret_cast<__nv_bfloat16*>(Cv);
    float*         Cf = reinterpret_cast<float*>(Cv);

    if constexpr (EPI == 2) {
        // proj: x1 = res(scatter) + v, then fused LN2 over the 96-wide row.
        __shared__ float2 red[2][128];
        float rsum[2][2] = {{0.f,0.f},{0.f,0.f}};
        float rsq [2][2] = {{0.f,0.f},{0.f,0.f}};
        size_t dpx[2][2];

        #pragma unroll
        for (int mt = 0; mt < 2; mt++) {
            long long row0 = rowBase + wm * 32 + mt * 16 + lr;
            dpx[mt][0] = dest_pixel((int)row0) * 96;
            dpx[mt][1] = dest_pixel((int)(row0 + 8)) * 96;
            #pragma unroll
            for (int nt = 0; nt < 6; nt++) {
                int col = wn * 48 + nt * 8 + 2 * lc;
                float2 bb = *reinterpret_cast<const float2*>(&bias[col]);
                float2 r0v = *reinterpret_cast<const float2*>(&res[dpx[mt][0] + col]);
                float2 r1v = *reinterpret_cast<const float2*>(&res[dpx[mt][1] + col]);
                float x00 = r0v.x + acc[mt][nt][0] + bb.x;
                float x01 = r0v.y + acc[mt][nt][1] + bb.y;
                float x10 = r1v.x + acc[mt][nt][2] + bb.x;
                float x11 = r1v.y + acc[mt][nt][3] + bb.y;
                *reinterpret_cast<float2*>(&Cf[dpx[mt][0] + col]) = make_float2(x00, x01);
                *reinterpret_cast<float2*>(&Cf[dpx[mt][1] + col]) = make_float2(x10, x11);
                acc[mt][nt][0] = x00; acc[mt][nt][1] = x01;
                acc[mt][nt][2] = x10; acc[mt][nt][3] = x11;
                rsum[mt][0] += x00 + x01;  rsq[mt][0] += x00*x00 + x01*x01;
                rsum[mt][1] += x10 + x11;  rsq[mt][1] += x10*x10 + x11*x11;
            }
        }
        #pragma unroll
        for (int mt = 0; mt < 2; mt++)
            #pragma unroll
            for (int rr = 0; rr < 2; rr++) {
                rsum[mt][rr] += __shfl_xor_sync(0xffffffffu, rsum[mt][rr], 1);
                rsum[mt][rr] += __shfl_xor_sync(0xffffffffu, rsum[mt][rr], 2);
                rsq [mt][rr] += __shfl_xor_sync(0xffffffffu, rsq [mt][rr], 1);
                rsq [mt][rr] += __shfl_xor_sync(0xffffffffu, rsq [mt][rr], 2);
            }
        if (lc == 0) {
            #pragma unroll
            for (int mt = 0; mt < 2; mt++)
                #pragma unroll
                for (int rr = 0; rr < 2; rr++)
                    red[wn][wm * 32 + mt * 16 + lr + rr * 8] =
                        make_float2(rsum[mt][rr], rsq[mt][rr]);
        }
        __syncthreads();
        #pragma unroll
        for (int mt = 0; mt < 2; mt++) {
            #pragma unroll
            for (int rr = 0; rr < 2; rr++) {
                int rl = wm * 32 + mt * 16 + lr + rr * 8;
                float2 p0 = red[0][rl], p1 = red[1][rl];
                float mean = (p0.x + p1.x) * (1.0f / 96.0f);
                float var  = (p0.y + p1.y) * (1.0f / 96.0f) - mean * mean;
                float rstd = rsqrtf(var + 1e-5f);
                #pragma unroll
                for (int nt = 0; nt < 6; nt++) {
                    int col = wn * 48 + nt * 8 + 2 * lc;
                    float w0 = lnw[col], w1v = lnw[col + 1];
                    float b0 = lnb[col], b1v = lnb[col + 1];
                    float y0 = (acc[mt][nt][2 * rr]     - mean) * rstd * w0 + b0;
                    float y1 = (acc[mt][nt][2 * rr + 1] - mean) * rstd * w1v + b1v;
                    __nv_bfloat162 h = __floats2bfloat162_rn(y0, y1);
                    *reinterpret_cast<__nv_bfloat162*>(&lnout[dpx[mt][rr] + col]) = h;
                }
            }
        }
    } else {
        #pragma unroll
        for (int mt = 0; mt < 2; mt++) {
            long long row0 = rowBase + wm * 32 + mt * 16 + lr;
            long long row1 = row0 + 8;
            #pragma unroll
            for (int nt = 0; nt < 6; nt++) {
                int col = colBase + wn * 48 + nt * 8 + 2 * lc;
                float2 bb = *reinterpret_cast<const float2*>(&bias[col]);
                float v00 = acc[mt][nt][0] + bb.x;
                float v01 = acc[mt][nt][1] + bb.y;
                float v10 = acc[mt][nt][2] + bb.x;
                float v11 = acc[mt][nt][3] + bb.y;
                *reinterpret_cast<__nv_bfloat162*>(&Cb[row0 * N + col]) =
                    __floats2bfloat162_rn(v00, v01);
                *reinterpret_cast<__nv_bfloat162*>(&Cb[row1 * N + col]) =
                    __floats2bfloat162_rn(v10, v11);
            }
        }
    }
}

// ---------------------------------------------------------------------------
// Fused MLP: out = x1 + gelu(ln2 @ W1^T + b1) @ W2^T + b2, h1 stays in smem.
// 128 rows/block, 256 threads (8 warps, 4m x 2n). 4 DFF-chunks of 96:
//   GEMM1 (K=96) -> gelu -> Hs (bf16), GEMM2 (K=96) accumulates into acc_out.
// Dynamic smem: As 128x104 + Hs 128x104 + Ws 96x104 halves = 73216 B.
// ---------------------------------------------------------------------------
constexpr int MKS = 104;   // 52 words: fragment loads verified conflict-free

__global__ void __launch_bounds__(256, 2) mlp_kernel(
    const __nv_bfloat16* __restrict__ A, const float* __restrict__ b1,
    const float* __restrict__ b2, const float* __restrict__ x1,
    float* __restrict__ out)
{
    extern __shared__ __align__(16) __nv_bfloat16 dsm[];
    __nv_bfloat16* As = dsm;                 // [128][MKS]
    __nv_bfloat16* Hs = dsm + 128 * MKS;     // [128][MKS]
    __nv_bfloat16* Ws = dsm + 256 * MKS;     // [96][MKS]

    const int tid  = threadIdx.x;
    const int wid  = tid >> 5;
    const int lane = tid & 31;
    const int wm   = wid >> 1;
    const int wn   = wid & 1;
    const int lr   = lane >> 2;
    const int lc   = lane & 3;
    const long long rowBase = (long long)blockIdx.x * 128;

    float acc_out[2][6][4];
    #pragma unroll
    for (int mt = 0; mt < 2; mt++)
        #pragma unroll
        for (int nt = 0; nt < 6; nt++)
            #pragma unroll
            for (int e = 0; e < 4; e++) acc_out[mt][nt][e] = 0.0f;

    // prologue: stage the whole A tile (128 x 96 halves = 1536 16B chunks)
    #pragma unroll
    for (int i = 0; i < 6; i++) {
        int ch = i * 256 + tid;
        int r = ch / 12, ck = ch % 12;
        cp_async16(&As[r * MKS + ck * 8], A + (rowBase + r) * 96 + ck * 8);
    }
    cp_commit();

    for (int c = 0; c < 4; c++) {
        __syncthreads();                       // Ws free (prev GEMM2 done)
        // load W1 chunk: rows c*96..+95 of w1[384][96] (96x12 = 1152 chunks)
        for (int ch = tid; ch < 1152; ch += 256) {
            int r = ch / 12, ck = ch % 12;
            cp_async16(&Ws[r * MKS + ck * 8], g_w1 + (c * 96 + r) * 96 + ck * 8);
        }
        cp_commit();
        cp_wait<0>();
        __syncthreads();                       // As + W1c visible

        // GEMM1: acc1 = A @ W1c^T
        float acc1[2][6][4];
        #pragma unroll
        for (int mt = 0; mt < 2; mt++)
            #pragma unroll
            for (int nt = 0; nt < 6; nt++)
                #pragma unroll
                for (int e = 0; e < 4; e++) acc1[mt][nt][e] = 0.0f;
        #pragma unroll
        for (int kb = 0; kb < 96; kb += 16) {
            unsigned a[2][4];
            #pragma unroll
            for (int mt = 0; mt < 2; mt++) {
                int r0 = wm * 32 + mt * 16 + lr;
                a[mt][0] = *reinterpret_cast<const unsigned*>(&As[r0 * MKS + kb + 2 * lc]);
                a[mt][1] = *reinterpret_cast<const unsigned*>(&As[(r0 + 8) * MKS + kb + 2 * lc]);
                a[mt][2] = *reinterpret_cast<const unsigned*>(&As[r0 * MKS + kb + 2 * lc + 8]);
                a[mt][3] = *reinterpret_cast<const unsigned*>(&As[(r0 + 8) * MKS + kb + 2 * lc + 8]);
            }
            unsigned bf[6][2];
            #pragma unroll
            for (int nt = 0; nt < 6; nt++) {
                int n0 = wn * 48 + nt * 8 + lr;
                bf[nt][0] = *reinterpret_cast<const unsigned*>(&Ws[n0 * MKS + kb + 2 * lc]);
                bf[nt][1] = *reinterpret_cast<const unsigned*>(&Ws[n0 * MKS + kb + 2 * lc + 8]);
            }
            #pragma unroll
            for (int mt = 0; mt < 2; mt++)
                #pragma unroll
                for (int nt = 0; nt < 6; nt++)
                    mma_bf16(acc1[mt][nt][0], acc1[mt][nt][1],
                             acc1[mt][nt][2], acc1[mt][nt][3],
                             a[mt][0], a[mt][1], a[mt][2], a[mt][3],
                             bf[nt][0], bf[nt][1]);
        }

        // gelu + bias -> Hs (bf16)
        #pragma unroll
        for (int mt = 0; mt < 2; mt++) {
            int r0 = wm * 32 + mt * 16 + lr;
            #pragma unroll
            for (int nt = 0; nt < 6; nt++) {
                int col = wn * 48 + nt * 8 + 2 * lc;
                float2 bb = *reinterpret_cast<const float2*>(&b1[c * 96 + col]);
                *reinterpret_cast<__nv_bfloat162*>(&Hs[r0 * MKS + col]) =
                    __floats2bfloat162_rn(gelu_exact(acc1[mt][nt][0] + bb.x),
                                          gelu_exact(acc1[mt][nt][1] + bb.y));
                *reinterpret_cast<__nv_bfloat162*>(&Hs[(r0 + 8) * MKS + col]) =
                    __floats2bfloat162_rn(gelu_exact(acc1[mt][nt][2] + bb.x),
                                          gelu_exact(acc1[mt][nt][3] + bb.y));
            }
        }
        __syncthreads();                       // Hs visible, Ws free

        // load W2 chunk: w2[96][384], k-slice c*96..+95 (96x12 = 1152 chunks)
        for (int ch = tid; ch < 1152; ch += 256) {
            int r = ch / 12, ck = ch % 12;
            cp_async16(&Ws[r * MKS + ck * 8], g_w2 + r * 384 + c * 96 + ck * 8);
        }
        cp_commit();
        cp_wait<0>();
        __syncthreads();                       // W2c visible

        // GEMM2: acc_out += Hs @ W2c^T
        #pragma unroll
        for (int kb = 0; kb < 96; kb += 16) {
            unsigned a[2][4];
            #pragma unroll
            for (int mt = 0; mt < 2; mt++) {
                int r0 = wm * 32 + mt * 16 + lr;
                a[mt][0] = *reinterpret_cast<const unsigned*>(&Hs[r0 * MKS + kb + 2 * lc]);
                a[mt][1] = *reinterpret_cast<const unsigned*>(&Hs[(r0 + 8) * MKS + kb + 2 * lc]);
                a[mt][2] = *reinterpret_cast<const unsigned*>(&Hs[r0 * MKS + kb + 2 * lc + 8]);
                a[mt][3] = *reinterpret_cast<const unsigned*>(&Hs[(r0 + 8) * MKS + kb + 2 * lc + 8]);
            }
            unsigned bf[6][2];
            #pragma unroll
            for (int nt = 0; nt < 6; nt++) {
                int n0 = wn * 48 + nt * 8 + lr;
                bf[nt][0] = *reinterpret_cast<const unsigned*>(&Ws[n0 * MKS + kb + 2 * lc]);
                bf[nt][1] = *reinterpret_cast<const unsigned*>(&Ws[n0 * MKS + kb + 2 * lc + 8]);
            }
            #pragma unroll
            for (int mt = 0; mt < 2; mt++)
                #pragma unroll
                for (int nt = 0; nt < 6; nt++)
                    mma_bf16(acc_out[mt][nt][0], acc_out[mt][nt][1],
                             acc_out[mt][nt][2], acc_out[mt][nt][3],
                             a[mt][0], a[mt][1], a[mt][2], a[mt][3],
                             bf[nt][0], bf[nt][1]);
        }
    }

    // epilogue: out = acc_out + b2 + x1 (fp32)
    #pragma unroll
    for (int mt = 0; mt < 2; mt++) {
        long long row0 = rowBase + wm * 32 + mt * 16 + lr;
        long long row1 = row0 + 8;
        #pragma unroll
        for (int nt = 0; nt < 6; nt++) {
            int col = wn * 48 + nt * 8 + 2 * lc;
            float2 bb = *reinterpret_cast<const float2*>(&b2[col]);
            float2 r0v = *reinterpret_cast<const float2*>(&x1[row0 * 96 + col]);
            float2 r1v = *reinterpret_cast<const float2*>(&x1[row1 * 96 + col]);
            *reinterpret_cast<float2*>(&out[row0 * 96 + col]) =
                make_float2(r0v.x + acc_out[mt][nt][0] + bb.x,
                            r0v.y + acc_out[mt][nt][1] + bb.y);
            *reinterpret_cast<float2*>(&out[row1 * 96 + col]) =
                make_float2(r1v.x + acc_out[mt][nt][2] + bb.x,
                            r1v.y + acc_out[mt][nt][3] + bb.y);
        }
    }
}

// ---------------------------------------------------------------------------
// Tensorized window attention (unchanged from passing round 13).
// ---------------------------------------------------------------------------
__device__ __forceinline__ int regid(int g)
{
    return g < 248 ? 0 : (g < 252 ? 1 : 2);
}

__global__ void __launch_bounds__(384) attn_kernel(
    const __nv_bfloat16* __restrict__ qkv, const float* __restrict__ rpb,
    __nv_bfloat16* __restrict__ ow)
{
    __shared__ __align__(16) __nv_bfloat16 Qs[3][64][40];
    __shared__ __align__(16) __nv_bfloat16 Ks[3][64][40];
    __shared__ __align__(16) __nv_bfloat16 Vt[3][32][72];
    __shared__ float rpbs[3][225];
    __shared__ int   ids[64];

    const int b_  = blockIdx.x;
    const int tid = threadIdx.x;
    const int wid = tid >> 5, lane = tid & 31;
    const int hg  = wid >> 2, ww = wid & 3;
    const int lr  = lane >> 2, lc = lane & 3;

    for (int t = tid; t < 675; t += 384)
        rpbs[t / 225][t % 225] = rpb[(t % 225) * 3 + t / 225];
    const int whc = (b_ >> 5) & 31, wwc = b_ & 31;
    if (tid < 64) {
        int i = tid >> 3, j = tid & 7;
        ids[tid] = regid(whc * 8 + i) * 3 + regid(wwc * 8 + j);
    }

    const __nv_bfloat16* base = qkv + (size_t)b_ * 64 * 288;

    #pragma unroll
    for (int i = 0; i < 4; i++) {
        int c = i * 384 + tid;
        int qk = (c >= 768) ? 1 : 0;
        int rem = c - qk * 768;
        int h = rem >> 8, rr = rem & 255;
        int row = rr >> 2, off = (rr & 3) * 8;
        const __nv_bfloat16* src = base + row * 288 + qk * 96 + h * 32 + off;
        __nv_bfloat16* dst = qk ? &Ks[h][row][off] : &Qs[h][row][off];
        cp_async16(dst, src);
    }
    cp_commit();

    {
        int h = tid >> 7;
        int r = (tid & 127) >> 1;
        int cg = tid & 1;
        const uint4* src = reinterpret_cast<const uint4*>(
            base + r * 288 + 192 + h * 32 + cg * 16);
        uint4 u0 = src[0], u1 = src[1];
        unsigned w8[8] = {u0.x, u0.y, u0.z, u0.w, u1.x, u1.y, u1.z, u1.w};
        #pragma unroll
        for (int e = 0; e < 8; e++) {
            __nv_bfloat162 h2 = *reinterpret_cast<__nv_bfloat162*>(&w8[e]);
            Vt[h][cg * 16 + 2 * e][r]     = __low2bfloat16(h2);
            Vt[h][cg * 16 + 2 * e + 1][r] = __high2bfloat16(h2);
        }
    }
    cp_wait<0>();
    __syncthreads();

    const int r0 = ww * 16;
    const int ra = r0 + lr, rb = ra + 8;
    const float scale = 0.17677669529663687f;

    unsigned qf[2][4];
    #pragma unroll
    for (int kc = 0; kc < 2; kc++) {
        int kb = kc * 16;
        qf[kc][0] = *reinterpret_cast<const unsigned*>(&Qs[hg][ra][kb + 2 * lc]);
        qf[kc][1] = *reinterpret_cast<const unsigned*>(&Qs[hg][rb][kb + 2 * lc]);
        qf[kc][2] = *reinterpret_cast<const unsigned*>(&Qs[hg][ra][kb + 2 * lc + 8]);
        qf[kc][3] = *reinterpret_cast<const unsigned*>(&Qs[hg][rb][kb + 2 * lc + 8]);
    }

    float S[8][4];
    #pragma unroll
    for (int nt = 0; nt < 8; nt++) { S[nt][0]=S[nt][1]=S[nt][2]=S[nt][3]=0.f; }
    #pragma unroll
    for (int nt = 0; nt < 8; nt++) {
        int n0 = nt * 8;
        #pragma unroll
        for (int kc = 0; kc < 2; kc++) {
            int kb = kc * 16;
            unsigned b0 = *reinterpret_cast<const unsigned*>(&Ks[hg][n0 + lr][kb + 2 * lc]);
            unsigned b1 = *reinterpret_cast<const unsigned*>(&Ks[hg][n0 + lr][kb + 2 * lc + 8]);
            mma_bf16(S[nt][0], S[nt][1], S[nt][2], S[nt][3],
                     qf[kc][0], qf[kc][1], qf[kc][2], qf[kc][3], b0, b1);
        }
    }

    const int i_a = ra >> 3, j_a = ra & 7;
    const int i_b = rb >> 3, j_b = rb & 7;
    const int id_a = ids[ra], id_b = ids[rb];
    float mxa = -1e30f, mxb = -1e30f;
    #pragma unroll
    for (int nt = 0; nt < 8; nt++) {
        #pragma unroll
        for (int e = 0; e < 2; e++) {
            int c = nt * 8 + 2 * lc + e;
            int ic = c >> 3, jc = c & 7;
            int idc = ids[c];
            float ba = rpbs[hg][(i_a - ic + 7) * 15 + (j_a - jc + 7)]
                     + (id_a == idc ? 0.0f : -100.0f);
            float bb = rpbs[hg][(i_b - ic + 7) * 15 + (j_b - jc + 7)]
                     + (id_b == idc ? 0.0f : -100.0f);
            S[nt][e]     = fmaf(S[nt][e],     scale, ba);
            S[nt][2 + e] = fmaf(S[nt][2 + e], scale, bb);
            mxa = fmaxf(mxa, S[nt][e]);
            mxb = fmaxf(mxb, S[nt][2 + e]);
        }
    }
    mxa = fmaxf(mxa, __shfl_xor_sync(0xffffffffu, mxa, 1));
    mxa = fmaxf(mxa, __shfl_xor_sync(0xffffffffu, mxa, 2));
    mxb = fmaxf(mxb, __shfl_xor_sync(0xffffffffu, mxb, 1));
    mxb = fmaxf(mxb, __shfl_xor_sync(0xffffffffu, mxb, 2));

    float sa = 0.0f, sb = 0.0f;
    #pragma unroll
    for (int nt = 0; nt < 8; nt++) {
        #pragma unroll
        for (int e = 0; e < 2; e++) {
            float pa = fast_exp(S[nt][e] - mxa);
            float pb = fast_exp(S[nt][2 + e] - mxb);
            S[nt][e] = pa;  S[nt][2 + e] = pb;
            sa += pa;  sb += pb;
        }
    }
    sa += __shfl_xor_sync(0xffffffffu, sa, 1);
    sa += __shfl_xor_sync(0xffffffffu, sa, 2);
    sb += __shfl_xor_sync(0xffffffffu, sb, 1);
    sb += __shfl_xor_sync(0xffffffffu, sb, 2);
    float inva = 1.0f / sa, invb = 1.0f / sb;

    unsigned P[4][4];
    #pragma unroll
    for (int kc = 0; kc < 4; kc++) {
        P[kc][0] = pack_bf162(S[2 * kc][0],     S[2 * kc][1]);
        P[kc][1] = pack_bf162(S[2 * kc][2],     S[2 * kc][3]);
        P[kc][2] = pack_bf162(S[2 * kc + 1][0], S[2 * kc + 1][1]);
        P[kc][3] = pack_bf162(S[2 * kc + 1][2], S[2 * kc + 1][3]);
    }

    float O[4][4];
    #pragma unroll
    for (int dt = 0; dt < 4; dt++) { O[dt][0]=O[dt][1]=O[dt][2]=O[dt][3]=0.f; }
    #pragma unroll
    for (int kc = 0; kc < 4; kc++) {
        int j0 = kc * 16;
        #pragma unroll
        for (int dt = 0; dt < 4; dt++) {
            int d0 = dt * 8;
            unsigned b0 = *reinterpret_cast<const unsigned*>(&Vt[hg][d0 + lr][j0 + 2 * lc]);
            unsigned b1 = *reinterpret_cast<const unsigned*>(&Vt[hg][d0 + lr][j0 + 2 * lc + 8]);
            mma_bf16(O[dt][0], O[dt][1], O[dt][2], O[dt][3],
                     P[kc][0], P[kc][1], P[kc][2], P[kc][3], b0, b1);
        }
    }

    size_t obase = (size_t)b_ * 64 * 96 + hg * 32;
    #pragma unroll
    for (int dt = 0; dt < 4; dt++) {
        int d = dt * 8 + 2 * lc;
        *reinterpret_cast<__nv_bfloat162*>(&ow[obase + (size_t)ra * 96 + d]) =
            __floats2bfloat162_rn(O[dt][0] * inva, O[dt][1] * inva);
        *reinterpret_cast<__nv_bfloat162*>(&ow[obase + (size_t)rb * 96 + d]) =
            __floats2bfloat162_rn(O[dt][2] * invb, O[dt][3] * invb);
    }
}

// ---------------------------------------------------------------------------
// launch
// ---------------------------------------------------------------------------
extern "C" void kernel_launch(void* const* d_in, const int* in_sizes, int n_in,
                              void* d_out, int out_size)
{
    const float* x      = (const float*)d_in[0];
    const float* n1w    = (const float*)d_in[1];
    const float* n1b    = (const float*)d_in[2];
    const float* qkv_w  = (const float*)d_in[3];
    const float* qkv_b  = (const float*)d_in[4];
    const float* rpb    = (const float*)d_in[5];
    const float* proj_w = (const float*)d_in[6];
    const float* proj_b = (const float*)d_in[7];
    const float* n2w    = (const float*)d_in[8];
    const float* n2b    = (const float*)d_in[9];
    const float* w1     = (const float*)d_in[10];
    const float* b1     = (const float*)d_in[11];
    const float* w2     = (const float*)d_in[12];
    const float* b2     = (const float*)d_in[13];
    float* out = (float*)d_out;

    __nv_bfloat16 *qkvp, *ap, *bp, *wq, *wp;
    float *x1p;
    cudaGetSymbolAddress((void**)&qkvp, g_qkv);
    cudaGetSymbolAddress((void**)&ap,   g_a);
    cudaGetSymbolAddress((void**)&bp,   g_b);
    cudaGetSymbolAddress((void**)&x1p,  g_x1);
    cudaGetSymbolAddress((void**)&wq,   g_wq);
    cudaGetSymbolAddress((void**)&wp,   g_wp);

    const int mlp_smem = 352 * 104 * (int)sizeof(__nv_bfloat16);   // 73216 B
    cudaFuncSetAttribute(mlp_kernel,
                         cudaFuncAttributeMaxDynamicSharedMemorySize, mlp_smem);

    // 0. weights -> bf16 (single launch)
    cvt_all<<<144, 256>>>(qkv_w, proj_w, w1, w2);
    // 1. LN1 + shift + window partition           -> g_a (bf16)
    ln1_kernel<<<65536, 256>>>(x, n1w, n1b, ap);
    // 2. QKV projection                           g_a -> g_qkv (bf16)
    hgemm_kernel<0><<<dim3(4096, 3), 256>>>(ap, wq, qkv_b, qkvp, nullptr, 96, 288,
                                            nullptr, nullptr, nullptr);
    // 3. tensorized windowed attention            g_qkv -> g_b (bf16)
    attn_kernel<<<8192, 384>>>(qkvp, rpb, bp);
    // 4. proj + scatter + residual -> x1 (fp32), fused LN2 -> g_a (bf16)
    hgemm_kernel<2><<<dim3(4096, 1), 256>>>(bp, wp, proj_b, x1p, x, 96, 96,
                                            n2w, n2b, ap);
    // 5. fused MLP: out = x1 + gelu(g_a @ W1^T + b1) @ W2^T + b2
    mlp_kernel<<<4096, 256, mlp_smem>>>(ap, b1, b2, x1p, out);
}

// round 15
// speedup vs baseline: 5.3621x; 1.0424x over previous
#include <cuda_runtime.h>
#include <cuda_bf16.h>
#include <math.h>

// ---------------------------------------------------------------------------
// SwinBlock: B=8, H=W=256, C=96, WS=8, SS=4, NH=3, hd=32, DFF=384
// M = 524288 window-order token rows.
// Round 15 = round 14 + front-half mega-fusion: LN1 + QKV-GEMM + attention in
// ONE kernel (g_a/g_qkv round-trips deleted: front-half DRAM 1.2GB -> 301MB).
// proj(+LN2) and fused MLP stay byte-identical to the passing round-14 source.
// ---------------------------------------------------------------------------

#define MROWS 524288

__device__ __nv_bfloat16 g_a  [MROWS *  96];   // LN2 output (proj epilogue)
__device__ __nv_bfloat16 g_b  [MROWS *  96];   // attention output
__device__ float         g_x1 [MROWS *  96];

__device__ __nv_bfloat16 g_wq[288 * 96];
__device__ __nv_bfloat16 g_wp[ 96 * 96];
__device__ __nv_bfloat16 g_w1[384 * 96];
__device__ __nv_bfloat16 g_w2[ 96 * 384];

// ---------------------------------------------------------------------------
// helpers
// ---------------------------------------------------------------------------
__device__ __forceinline__ void cp_async16(void* smem_dst, const void* gmem_src)
{
    unsigned s = (unsigned)__cvta_generic_to_shared(smem_dst);
    asm volatile("cp.async.cg.shared.global [%0], [%1], 16;\n" :: "r"(s), "l"(gmem_src));
}
__device__ __forceinline__ void cp_commit()
{
    asm volatile("cp.async.commit_group;\n");
}
template<int N>
__device__ __forceinline__ void cp_wait()
{
    asm volatile("cp.async.wait_group %0;\n" :: "n"(N));
}

__device__ __forceinline__ void mma_bf16(
    float& c0, float& c1, float& c2, float& c3,
    unsigned a0, unsigned a1, unsigned a2, unsigned a3,
    unsigned b0, unsigned b1)
{
    asm volatile(
        "mma.sync.aligned.m16n8k16.row.col.f32.bf16.bf16.f32 "
        "{%0,%1,%2,%3}, {%4,%5,%6,%7}, {%8,%9}, {%0,%1,%2,%3};\n"
        : "+f"(c0), "+f"(c1), "+f"(c2), "+f"(c3)
        : "r"(a0), "r"(a1), "r"(a2), "r"(a3), "r"(b0), "r"(b1));
}

__device__ __forceinline__ unsigned pack_bf162(float lo, float hi)
{
    __nv_bfloat162 h = __floats2bfloat162_rn(lo, hi);
    return *reinterpret_cast<unsigned*>(&h);
}

// e^x for x <= 0 (down to ~-120), FMA-only (no MUFU).
__device__ __forceinline__ float fast_exp(float x)
{
    float t = fmaxf(x * 1.44269504089f, -124.0f);
    float ti = rintf(t);
    float tf = t - ti;                       // [-0.5, 0.5]
    float p = fmaf(tf, 0.00961812911f, 0.0555041087f);
    p = fmaf(tf, p, 0.240226507f);
    p = fmaf(tf, p, 0.693147181f);
    p = fmaf(tf, p, 1.0f);
    return __int_as_float(__float_as_int(p) + (((int)ti) << 23));
}

// one-shot fp32 -> bf16 weight convert (all four weight mats)
__global__ void __launch_bounds__(256) cvt_all(
    const float* __restrict__ a, const float* __restrict__ b,
    const float* __restrict__ c, const float* __restrict__ d)
{
    int i = blockIdx.x * 256 + threadIdx.x;
    if (i < 288 * 96) g_wq[i] = __float2bfloat16(a[i]);
    if (i <  96 * 96) g_wp[i] = __float2bfloat16(b[i]);
    if (i < 384 * 96) { g_w1[i] = __float2bfloat16(c[i]);
                        g_w2[i] = __float2bfloat16(d[i]); }
}

// ---------------------------------------------------------------------------
// bf16 GEMM, EPI 2 (proj): scatter+residual -> x1 fp32, fused LN2 -> lnout.
// (unchanged from passing round 14; only EPI 2 is launched)
// ---------------------------------------------------------------------------
constexpr int BM = 128, BN = 96, BK = 32;
constexpr int KS = BK + 8;   // 40 halves

__device__ __forceinline__ size_t dest_pixel(int r)
{
    int b_ = r >> 6, n = r & 63;
    int bb = b_ >> 10, wh = (b_ >> 5) & 31, ww = b_ & 31;
    int i = n >> 3, j = n & 7;
    int hh = (wh * 8 + i + 4) & 255;
    int wp = (ww * 8 + j + 4) & 255;
    return (size_t)bb * 65536 + (size_t)hh * 256 + wp;
}

__device__ __forceinline__ float gelu_exact(float v)
{
    return 0.5f * v * (1.0f + erff(v * 0.70710678118654752f));
}

template<int EPI>
__global__ void __launch_bounds__(256, 2) hgemm_kernel(
    const __nv_bfloat16* __restrict__ A, const __nv_bfloat16* __restrict__ B,
    const float* __restrict__ bias, void* __restrict__ Cv,
    const float* __restrict__ res, int K, int N,
    const float* __restrict__ lnw, const float* __restrict__ lnb,
    __nv_bfloat16* __restrict__ lnout)
{
    __shared__ __align__(16) __nv_bfloat16 As[2][BM][KS];
    __shared__ __align__(16) __nv_bfloat16 Bs[2][BN][KS];

    const int tid  = threadIdx.x;
    const int wid  = tid >> 5;
    const int lane = tid & 31;
    const int wm   = wid >> 1;
    const int wn   = wid & 1;
    const int lr   = lane >> 2;
    const int lc   = lane & 3;

    const long long rowBase = (long long)blockIdx.x * BM;
    const int colBase = blockIdx.y * BN;

    const int rA0 = tid >> 2,         cA0 = (tid & 3) * 8;
    const int rA1 = (tid + 256) >> 2;
    const int nK = K / BK;

    float acc[2][6][4];
    #pragma unroll
    for (int mt = 0; mt < 2; mt++)
        #pragma unroll
        for (int nt = 0; nt < 6; nt++)
            #pragma unroll
            for (int e = 0; e < 4; e++) acc[mt][nt][e] = 0.0f;

    {
        cp_async16(&As[0][rA0][cA0], A + (rowBase + rA0) * K + cA0);
        cp_async16(&As[0][rA1][cA0], A + (rowBase + rA1) * K + cA0);
        cp_async16(&Bs[0][rA0][cA0], B + (size_t)(colBase + rA0) * K + cA0);
        if (tid < 128)
            cp_async16(&Bs[0][rA1][cA0], B + (size_t)(colBase + rA1) * K + cA0);
        cp_commit();
    }

    for (int it = 0; it < nK; it++) {
        if (it + 1 < nK) {
            const int s = (it + 1) & 1;
            const int k0 = (it + 1) * BK;
            cp_async16(&As[s][rA0][cA0], A + (rowBase + rA0) * K + k0 + cA0);
            cp_async16(&As[s][rA1][cA0], A + (rowBase + rA1) * K + k0 + cA0);
            cp_async16(&Bs[s][rA0][cA0], B + (size_t)(colBase + rA0) * K + k0 + cA0);
            if (tid < 128)
                cp_async16(&Bs[s][rA1][cA0], B + (size_t)(colBase + rA1) * K + k0 + cA0);
            cp_commit();
            cp_wait<1>();
        } else {
            cp_wait<0>();
        }
        __syncthreads();

        const int s = it & 1;
        #pragma unroll
        for (int kb = 0; kb < BK; kb += 16) {
            unsigned a[2][4];
            #pragma unroll
            for (int mt = 0; mt < 2; mt++) {
                int r0 = wm * 32 + mt * 16 + lr;
                a[mt][0] = *reinterpret_cast<const unsigned*>(&As[s][r0][kb + 2 * lc]);
                a[mt][1] = *reinterpret_cast<const unsigned*>(&As[s][r0 + 8][kb + 2 * lc]);
                a[mt][2] = *reinterpret_cast<const unsigned*>(&As[s][r0][kb + 2 * lc + 8]);
                a[mt][3] = *reinterpret_cast<const unsigned*>(&As[s][r0 + 8][kb + 2 * lc + 8]);
            }
            unsigned bf[6][2];
            #pragma unroll
            for (int nt = 0; nt < 6; nt++) {
                int n0 = wn * 48 + nt * 8 + lr;
                bf[nt][0] = *reinterpret_cast<const unsigned*>(&Bs[s][n0][kb + 2 * lc]);
                bf[nt][1] = *reinterpret_cast<const unsigned*>(&Bs[s][n0][kb + 2 * lc + 8]);
            }
            #pragma unroll
            for (int mt = 0; mt < 2; mt++)
                #pragma unroll
                for (int nt = 0; nt < 6; nt++)
                    mma_bf16(acc[mt][nt][0], acc[mt][nt][1],
                             acc[mt][nt][2], acc[mt][nt][3],
                             a[mt][0], a[mt][1], a[mt][2], a[mt][3],
                             bf[nt][0], bf[nt][1]);
        }
        __syncthreads();
    }

    float* Cf = reinterpret_cast<float*>(Cv);

    if constexpr (EPI == 2) {
        __shared__ float2 red[2][128];
        float rsum[2][2] = {{0.f,0.f},{0.f,0.f}};
        float rsq [2][2] = {{0.f,0.f},{0.f,0.f}};
        size_t dpx[2][2];

        #pragma unroll
        for (int mt = 0; mt < 2; mt++) {
            long long row0 = rowBase + wm * 32 + mt * 16 + lr;
            dpx[mt][0] = dest_pixel((int)row0) * 96;
            dpx[mt][1] = dest_pixel((int)(row0 + 8)) * 96;
            #pragma unroll
            for (int nt = 0; nt < 6; nt++) {
                int col = wn * 48 + nt * 8 + 2 * lc;
                float2 bb = *reinterpret_cast<const float2*>(&bias[col]);
                float2 r0v = *reinterpret_cast<const float2*>(&res[dpx[mt][0] + col]);
                float2 r1v = *reinterpret_cast<const float2*>(&res[dpx[mt][1] + col]);
                float x00 = r0v.x + acc[mt][nt][0] + bb.x;
                float x01 = r0v.y + acc[mt][nt][1] + bb.y;
                float x10 = r1v.x + acc[mt][nt][2] + bb.x;
                float x11 = r1v.y + acc[mt][nt][3] + bb.y;
                *reinterpret_cast<float2*>(&Cf[dpx[mt][0] + col]) = make_float2(x00, x01);
                *reinterpret_cast<float2*>(&Cf[dpx[mt][1] + col]) = make_float2(x10, x11);
                acc[mt][nt][0] = x00; acc[mt][nt][1] = x01;
                acc[mt][nt][2] = x10; acc[mt][nt][3] = x11;
                rsum[mt][0] += x00 + x01;  rsq[mt][0] += x00*x00 + x01*x01;
                rsum[mt][1] += x10 + x11;  rsq[mt][1] += x10*x10 + x11*x11;
            }
        }
        #pragma unroll
        for (int mt = 0; mt < 2; mt++)
            #pragma unroll
            for (int rr = 0; rr < 2; rr++) {
                rsum[mt][rr] += __shfl_xor_sync(0xffffffffu, rsum[mt][rr], 1);
                rsum[mt][rr] += __shfl_xor_sync(0xffffffffu, rsum[mt][rr], 2);
                rsq [mt][rr] += __shfl_xor_sync(0xffffffffu, rsq [mt][rr], 1);
                rsq [mt][rr] += __shfl_xor_sync(0xffffffffu, rsq [mt][rr], 2);
            }
        if (lc == 0) {
            #pragma unroll
            for (int mt = 0; mt < 2; mt++)
                #pragma unroll
                for (int rr = 0; rr < 2; rr++)
                    red[wn][wm * 32 + mt * 16 + lr + rr * 8] =
                        make_float2(rsum[mt][rr], rsq[mt][rr]);
        }
        __syncthreads();
        #pragma unroll
        for (int mt = 0; mt < 2; mt++) {
            #pragma unroll
            for (int rr = 0; rr < 2; rr++) {
                int rl = wm * 32 + mt * 16 + lr + rr * 8;
                float2 p0 = red[0][rl], p1 = red[1][rl];
                float mean = (p0.x + p1.x) * (1.0f / 96.0f);
                float var  = (p0.y + p1.y) * (1.0f / 96.0f) - mean * mean;
                float rstd = rsqrtf(var + 1e-5f);
                #pragma unroll
                for (int nt = 0; nt < 6; nt++) {
                    int col = wn * 48 + nt * 8 + 2 * lc;
                    float w0 = lnw[col], w1v = lnw[col + 1];
                    float b0 = lnb[col], b1v = lnb[col + 1];
                    float y0 = (acc[mt][nt][2 * rr]     - mean) * rstd * w0 + b0;
                    float y1 = (acc[mt][nt][2 * rr + 1] - mean) * rstd * w1v + b1v;
                    __nv_bfloat162 h = __floats2bfloat162_rn(y0, y1);
                    *reinterpret_cast<__nv_bfloat162*>(&lnout[dpx[mt][rr] + col]) = h;
                }
            }
        }
    }
}

// ---------------------------------------------------------------------------
// Fused MLP (unchanged from passing round 14).
// ---------------------------------------------------------------------------
constexpr int MKS = 104;

__global__ void __launch_bounds__(256, 2) mlp_kernel(
    const __nv_bfloat16* __restrict__ A, const float* __restrict__ b1,
    const float* __restrict__ b2, const float* __restrict__ x1,
    float* __restrict__ out)
{
    extern __shared__ __align__(16) __nv_bfloat16 dsm[];
    __nv_bfloat16* As = dsm;
    __nv_bfloat16* Hs = dsm + 128 * MKS;
    __nv_bfloat16* Ws = dsm + 256 * MKS;

    const int tid  = threadIdx.x;
    const int wid  = tid >> 5;
    const int lane = tid & 31;
    const int wm   = wid >> 1;
    const int wn   = wid & 1;
    const int lr   = lane >> 2;
    const int lc   = lane & 3;
    const long long rowBase = (long long)blockIdx.x * 128;

    float acc_out[2][6][4];
    #pragma unroll
    for (int mt = 0; mt < 2; mt++)
        #pragma unroll
        for (int nt = 0; nt < 6; nt++)
            #pragma unroll
            for (int e = 0; e < 4; e++) acc_out[mt][nt][e] = 0.0f;

    #pragma unroll
    for (int i = 0; i < 6; i++) {
        int ch = i * 256 + tid;
        int r = ch / 12, ck = ch % 12;
        cp_async16(&As[r * MKS + ck * 8], A + (rowBase + r) * 96 + ck * 8);
    }
    cp_commit();

    for (int c = 0; c < 4; c++) {
        __syncthreads();
        for (int ch = tid; ch < 1152; ch += 256) {
            int r = ch / 12, ck = ch % 12;
            cp_async16(&Ws[r * MKS + ck * 8], g_w1 + (c * 96 + r) * 96 + ck * 8);
        }
        cp_commit();
        cp_wait<0>();
        __syncthreads();

        float acc1[2][6][4];
        #pragma unroll
        for (int mt = 0; mt < 2; mt++)
            #pragma unroll
            for (int nt = 0; nt < 6; nt++)
                #pragma unroll
                for (int e = 0; e < 4; e++) acc1[mt][nt][e] = 0.0f;
        #pragma unroll
        for (int kb = 0; kb < 96; kb += 16) {
            unsigned a[2][4];
            #pragma unroll
            for (int mt = 0; mt < 2; mt++) {
                int r0 = wm * 32 + mt * 16 + lr;
                a[mt][0] = *reinterpret_cast<const unsigned*>(&As[r0 * MKS + kb + 2 * lc]);
                a[mt][1] = *reinterpret_cast<const unsigned*>(&As[(r0 + 8) * MKS + kb + 2 * lc]);
                a[mt][2] = *reinterpret_cast<const unsigned*>(&As[r0 * MKS + kb + 2 * lc + 8]);
                a[mt][3] = *reinterpret_cast<const unsigned*>(&As[(r0 + 8) * MKS + kb + 2 * lc + 8]);
            }
            unsigned bf[6][2];
            #pragma unroll
            for (int nt = 0; nt < 6; nt++) {
                int n0 = wn * 48 + nt * 8 + lr;
                bf[nt][0] = *reinterpret_cast<const unsigned*>(&Ws[n0 * MKS + kb + 2 * lc]);
                bf[nt][1] = *reinterpret_cast<const unsigned*>(&Ws[n0 * MKS + kb + 2 * lc + 8]);
            }
            #pragma unroll
            for (int mt = 0; mt < 2; mt++)
                #pragma unroll
                for (int nt = 0; nt < 6; nt++)
                    mma_bf16(acc1[mt][nt][0], acc1[mt][nt][1],
                             acc1[mt][nt][2], acc1[mt][nt][3],
                             a[mt][0], a[mt][1], a[mt][2], a[mt][3],
                             bf[nt][0], bf[nt][1]);
        }

        #pragma unroll
        for (int mt = 0; mt < 2; mt++) {
            int r0 = wm * 32 + mt * 16 + lr;
            #pragma unroll
            for (int nt = 0; nt < 6; nt++) {
                int col = wn * 48 + nt * 8 + 2 * lc;
                float2 bb = *reinterpret_cast<const float2*>(&b1[c * 96 + col]);
                *reinterpret_cast<__nv_bfloat162*>(&Hs[r0 * MKS + col]) =
                    __floats2bfloat162_rn(gelu_exact(acc1[mt][nt][0] + bb.x),
                                          gelu_exact(acc1[mt][nt][1] + bb.y));
                *reinterpret_cast<__nv_bfloat162*>(&Hs[(r0 + 8) * MKS + col]) =
                    __floats2bfloat162_rn(gelu_exact(acc1[mt][nt][2] + bb.x),
                                          gelu_exact(acc1[mt][nt][3] + bb.y));
            }
        }
        __syncthreads();

        for (int ch = tid; ch < 1152; ch += 256) {
            int r = ch / 12, ck = ch % 12;
            cp_async16(&Ws[r * MKS + ck * 8], g_w2 + r * 384 + c * 96 + ck * 8);
        }
        cp_commit();
        cp_wait<0>();
        __syncthreads();

        #pragma unroll
        for (int kb = 0; kb < 96; kb += 16) {
            unsigned a[2][4];
            #pragma unroll
            for (int mt = 0; mt < 2; mt++) {
                int r0 = wm * 32 + mt * 16 + lr;
                a[mt][0] = *reinterpret_cast<const unsigned*>(&Hs[r0 * MKS + kb + 2 * lc]);
                a[mt][1] = *reinterpret_cast<const unsigned*>(&Hs[(r0 + 8) * MKS + kb + 2 * lc]);
                a[mt][2] = *reinterpret_cast<const unsigned*>(&Hs[r0 * MKS + kb + 2 * lc + 8]);
                a[mt][3] = *reinterpret_cast<const unsigned*>(&Hs[(r0 + 8) * MKS + kb + 2 * lc + 8]);
            }
            unsigned bf[6][2];
            #pragma unroll
            for (int nt = 0; nt < 6; nt++) {
                int n0 = wn * 48 + nt * 8 + lr;
                bf[nt][0] = *reinterpret_cast<const unsigned*>(&Ws[n0 * MKS + kb + 2 * lc]);
                bf[nt][1] = *reinterpret_cast<const unsigned*>(&Ws[n0 * MKS + kb + 2 * lc + 8]);
            }
            #pragma unroll
            for (int mt = 0; mt < 2; mt++)
                #pragma unroll
                for (int nt = 0; nt < 6; nt++)
                    mma_bf16(acc_out[mt][nt][0], acc_out[mt][nt][1],
                             acc_out[mt][nt][2], acc_out[mt][nt][3],
                             a[mt][0], a[mt][1], a[mt][2], a[mt][3],
                             bf[nt][0], bf[nt][1]);
        }
    }

    #pragma unroll
    for (int mt = 0; mt < 2; mt++) {
        long long row0 = rowBase + wm * 32 + mt * 16 + lr;
        long long row1 = row0 + 8;
        #pragma unroll
        for (int nt = 0; nt < 6; nt++) {
            int col = wn * 48 + nt * 8 + 2 * lc;
            float2 bb = *reinterpret_cast<const float2*>(&b2[col]);
            float2 r0v = *reinterpret_cast<const float2*>(&x1[row0 * 96 + col]);
            float2 r1v = *reinterpret_cast<const float2*>(&x1[row1 * 96 + col]);
            *reinterpret_cast<float2*>(&out[row0 * 96 + col]) =
                make_float2(r0v.x + acc_out[mt][nt][0] + bb.x,
                            r0v.y + acc_out[mt][nt][1] + bb.y);
            *reinterpret_cast<float2*>(&out[row1 * 96 + col]) =
                make_float2(r1v.x + acc_out[mt][nt][2] + bb.x,
                            r1v.y + acc_out[mt][nt][3] + bb.y);
        }
    }
}

// ---------------------------------------------------------------------------
// MEGA front half: LN1 + QKV GEMM + windowed attention, one block per window.
// 384 threads = 12 warps. Phases:
//  (1) LN1: warp-per-row gathered fp32 reads of x -> As (64x96 bf16)
//  (2) QKV GEMM, 3 weight chunks (Q/K/V): As @ Wc^T + qkv_b -> Qs/Ks/Vt smem
//  (3) attention (identical logic to the passing round-13/14 kernel)
// Dynamic smem halves: As 6656 | Ws 9984 | Qs 7680 | Ks 7680 | Vt 6912
//                      + rpbs 675 f32 + ids 64 i32  = 80780 B.
// ---------------------------------------------------------------------------
__device__ __forceinline__ int regid(int g)
{
    return g < 248 ? 0 : (g < 252 ? 1 : 2);
}

constexpr int ATT_SMEM = 80896;

__global__ void __launch_bounds__(384, 2) attn_kernel(
    const float* __restrict__ x, const float* __restrict__ n1w,
    const float* __restrict__ n1b, const float* __restrict__ qkv_b,
    const float* __restrict__ rpb, __nv_bfloat16* __restrict__ ow)
{
    extern __shared__ __align__(16) __nv_bfloat16 dsm[];
    __nv_bfloat16* As = dsm;                    // [64][104]
    __nv_bfloat16* Ws = As + 6656;              // [96][104]
    __nv_bfloat16* Qs = Ws + 9984;              // [3][64][40]
    __nv_bfloat16* Ks = Qs + 7680;              // [3][64][40]
    __nv_bfloat16* Vt = Ks + 7680;              // [3][32][72]
    float*         rpbs = reinterpret_cast<float*>(Vt + 6912);   // [3][225]
    int*           ids  = reinterpret_cast<int*>(rpbs + 675);    // [64]

    const int b_  = blockIdx.x;
    const int tid = threadIdx.x;
    const int wid = tid >> 5, lane = tid & 31;
    const int lr  = lane >> 2, lc = lane & 3;

    // ---- rpb table + region ids
    for (int t = tid; t < 675; t += 384)
        rpbs[t] = rpb[(t % 225) * 3 + t / 225];
    const int whc = (b_ >> 5) & 31, wwc = b_ & 31;
    if (tid < 64) {
        int i = tid >> 3, j = tid & 7;
        ids[tid] = regid(whc * 8 + i) * 3 + regid(wwc * 8 + j);
    }

    // ---- phase 1: LN1 (warp per row, gathered from pixel order)
    const int bb_ = b_ >> 10;
    for (int r = wid; r < 64; r += 12) {
        int i = r >> 3, j = r & 7;
        int hh = (whc * 8 + i + 4) & 255;
        int wp = (wwc * 8 + j + 4) & 255;
        size_t src = ((size_t)bb_ * 65536 + (size_t)hh * 256 + wp) * 96;
        float v0 = x[src + lane], v1 = x[src + lane + 32], v2 = x[src + lane + 64];
        float s = v0 + v1 + v2;
        #pragma unroll
        for (int o = 16; o > 0; o >>= 1) s += __shfl_xor_sync(0xffffffffu, s, o);
        float mean = s * (1.0f / 96.0f);
        float d0 = v0 - mean, d1 = v1 - mean, d2 = v2 - mean;
        float vv = d0 * d0 + d1 * d1 + d2 * d2;
        #pragma unroll
        for (int o = 16; o > 0; o >>= 1) vv += __shfl_xor_sync(0xffffffffu, vv, o);
        float rstd = rsqrtf(vv * (1.0f / 96.0f) + 1e-5f);
        As[r * 104 + lane]      = __float2bfloat16(d0 * rstd * n1w[lane]      + n1b[lane]);
        As[r * 104 + lane + 32] = __float2bfloat16(d1 * rstd * n1w[lane + 32] + n1b[lane + 32]);
        As[r * 104 + lane + 64] = __float2bfloat16(d2 * rstd * n1w[lane + 64] + n1b[lane + 64]);
    }

    // ---- phase 2: QKV GEMM, 3 chunks (c=0 Q, 1 K, 2 V)
    const int gm = (wid & 3) * 16;     // m-tile base row
    const int gh = wid >> 2;           // n-group == head
    const int rA = gm + lr, rB = rA + 8;

    for (int c = 0; c < 3; c++) {
        __syncthreads();               // c=0: As/rpbs/ids visible; c>0: Ws free
        for (int ch = tid; ch < 1152; ch += 384) {
            int r = ch / 12, ck = ch % 12;
            cp_async16(&Ws[r * 104 + ck * 8], g_wq + (c * 96 + r) * 96 + ck * 8);
        }
        cp_commit();
        cp_wait<0>();
        __syncthreads();               // Ws chunk visible

        float acc[4][4];
        #pragma unroll
        for (int nt = 0; nt < 4; nt++) { acc[nt][0]=acc[nt][1]=acc[nt][2]=acc[nt][3]=0.f; }
        #pragma unroll
        for (int kb = 0; kb < 96; kb += 16) {
            unsigned a0 = *reinterpret_cast<const unsigned*>(&As[rA * 104 + kb + 2 * lc]);
            unsigned a1 = *reinterpret_cast<const unsigned*>(&As[rB * 104 + kb + 2 * lc]);
            unsigned a2 = *reinterpret_cast<const unsigned*>(&As[rA * 104 + kb + 2 * lc + 8]);
            unsigned a3 = *reinterpret_cast<const unsigned*>(&As[rB * 104 + kb + 2 * lc + 8]);
            #pragma unroll
            for (int nt = 0; nt < 4; nt++) {
                int n0 = gh * 32 + nt * 8 + lr;
                unsigned b0 = *reinterpret_cast<const unsigned*>(&Ws[n0 * 104 + kb + 2 * lc]);
                unsigned b1 = *reinterpret_cast<const unsigned*>(&Ws[n0 * 104 + kb + 2 * lc + 8]);
                mma_bf16(acc[nt][0], acc[nt][1], acc[nt][2], acc[nt][3],
                         a0, a1, a2, a3, b0, b1);
            }
        }

        // store chunk output + bias into attention layouts
        #pragma unroll
        for (int nt = 0; nt < 4; nt++) {
            int d = nt * 8 + 2 * lc;                  // 0..31 within head
            float2 bb = *reinterpret_cast<const float2*>(&qkv_b[c * 96 + gh * 32 + d]);
            float v00 = acc[nt][0] + bb.x, v01 = acc[nt][1] + bb.y;
            float v10 = acc[nt][2] + bb.x, v11 = acc[nt][3] + bb.y;
            if (c == 0) {
                *reinterpret_cast<__nv_bfloat162*>(&Qs[gh * 2560 + rA * 40 + d]) =
                    __floats2bfloat162_rn(v00, v01);
                *reinterpret_cast<__nv_bfloat162*>(&Qs[gh * 2560 + rB * 40 + d]) =
                    __floats2bfloat162_rn(v10, v11);
            } else if (c == 1) {
                *reinterpret_cast<__nv_bfloat162*>(&Ks[gh * 2560 + rA * 40 + d]) =
                    __floats2bfloat162_rn(v00, v01);
                *reinterpret_cast<__nv_bfloat162*>(&Ks[gh * 2560 + rB * 40 + d]) =
                    __floats2bfloat162_rn(v10, v11);
            } else {                                   // V transposed: Vt[h][d][r]
                Vt[gh * 2304 + d * 72 + rA]       = __float2bfloat16(v00);
                Vt[gh * 2304 + (d + 1) * 72 + rA] = __float2bfloat16(v01);
                Vt[gh * 2304 + d * 72 + rB]       = __float2bfloat16(v10);
                Vt[gh * 2304 + (d + 1) * 72 + rB] = __float2bfloat16(v11);
            }
        }
    }
    __syncthreads();                   // all Q/K/V visible

    // ---- phase 3: attention (identical logic to round-13/14)
    const int hg = wid >> 2, ww = wid & 3;
    const int r0 = ww * 16;
    const int ra = r0 + lr, rb = ra + 8;
    const float scale = 0.17677669529663687f;

    unsigned qf[2][4];
    #pragma unroll
    for (int kc = 0; kc < 2; kc++) {
        int kb = kc * 16;
        qf[kc][0] = *reinterpret_cast<const unsigned*>(&Qs[hg * 2560 + ra * 40 + kb + 2 * lc]);
        qf[kc][1] = *reinterpret_cast<const unsigned*>(&Qs[hg * 2560 + rb * 40 + kb + 2 * lc]);
        qf[kc][2] = *reinterpret_cast<const unsigned*>(&Qs[hg * 2560 + ra * 40 + kb + 2 * lc + 8]);
        qf[kc][3] = *reinterpret_cast<const unsigned*>(&Qs[hg * 2560 + rb * 40 + kb + 2 * lc + 8]);
    }

    float S[8][4];
    #pragma unroll
    for (int nt = 0; nt < 8; nt++) { S[nt][0]=S[nt][1]=S[nt][2]=S[nt][3]=0.f; }
    #pragma unroll
    for (int nt = 0; nt < 8; nt++) {
        int n0 = nt * 8;
        #pragma unroll
        for (int kc = 0; kc < 2; kc++) {
            int kb = kc * 16;
            unsigned b0 = *reinterpret_cast<const unsigned*>(&Ks[hg * 2560 + (n0 + lr) * 40 + kb + 2 * lc]);
            unsigned b1 = *reinterpret_cast<const unsigned*>(&Ks[hg * 2560 + (n0 + lr) * 40 + kb + 2 * lc + 8]);
            mma_bf16(S[nt][0], S[nt][1], S[nt][2], S[nt][3],
                     qf[kc][0], qf[kc][1], qf[kc][2], qf[kc][3], b0, b1);
        }
    }

    const int i_a = ra >> 3, j_a = ra & 7;
    const int i_b = rb >> 3, j_b = rb & 7;
    const int id_a = ids[ra], id_b = ids[rb];
    float mxa = -1e30f, mxb = -1e30f;
    #pragma unroll
    for (int nt = 0; nt < 8; nt++) {
        #pragma unroll
        for (int e = 0; e < 2; e++) {
            int cc = nt * 8 + 2 * lc + e;
            int ic = cc >> 3, jc = cc & 7;
            int idc = ids[cc];
            float ba = rpbs[hg * 225 + (i_a - ic + 7) * 15 + (j_a - jc + 7)]
                     + (id_a == idc ? 0.0f : -100.0f);
            float bb = rpbs[hg * 225 + (i_b - ic + 7) * 15 + (j_b - jc + 7)]
                     + (id_b == idc ? 0.0f : -100.0f);
            S[nt][e]     = fmaf(S[nt][e],     scale, ba);
            S[nt][2 + e] = fmaf(S[nt][2 + e], scale, bb);
            mxa = fmaxf(mxa, S[nt][e]);
            mxb = fmaxf(mxb, S[nt][2 + e]);
        }
    }
    mxa = fmaxf(mxa, __shfl_xor_sync(0xffffffffu, mxa, 1));
    mxa = fmaxf(mxa, __shfl_xor_sync(0xffffffffu, mxa, 2));
    mxb = fmaxf(mxb, __shfl_xor_sync(0xffffffffu, mxb, 1));
    mxb = fmaxf(mxb, __shfl_xor_sync(0xffffffffu, mxb, 2));

    float sa = 0.0f, sb = 0.0f;
    #pragma unroll
    for (int nt = 0; nt < 8; nt++) {
        #pragma unroll
        for (int e = 0; e < 2; e++) {
            float pa = fast_exp(S[nt][e] - mxa);
            float pb = fast_exp(S[nt][2 + e] - mxb);
            S[nt][e] = pa;  S[nt][2 + e] = pb;
            sa += pa;  sb += pb;
        }
    }
    sa += __shfl_xor_sync(0xffffffffu, sa, 1);
    sa += __shfl_xor_sync(0xffffffffu, sa, 2);
    sb += __shfl_xor_sync(0xffffffffu, sb, 1);
    sb += __shfl_xor_sync(0xffffffffu, sb, 2);
    float inva = 1.0f / sa, invb = 1.0f / sb;

    unsigned P[4][4];
    #pragma unroll
    for (int kc = 0; kc < 4; kc++) {
        P[kc][0] = pack_bf162(S[2 * kc][0],     S[2 * kc][1]);
        P[kc][1] = pack_bf162(S[2 * kc][2],     S[2 * kc][3]);
        P[kc][2] = pack_bf162(S[2 * kc + 1][0], S[2 * kc + 1][1]);
        P[kc][3] = pack_bf162(S[2 * kc + 1][2], S[2 * kc + 1][3]);
    }

    float O[4][4];
    #pragma unroll
    for (int dt = 0; dt < 4; dt++) { O[dt][0]=O[dt][1]=O[dt][2]=O[dt][3]=0.f; }
    #pragma unroll
    for (int kc = 0; kc < 4; kc++) {
        int j0 = kc * 16;
        #pragma unroll
        for (int dt = 0; dt < 4; dt++) {
            int d0 = dt * 8;
            unsigned b0 = *reinterpret_cast<const unsigned*>(&Vt[hg * 2304 + (d0 + lr) * 72 + j0 + 2 * lc]);
            unsigned b1 = *reinterpret_cast<const unsigned*>(&Vt[hg * 2304 + (d0 + lr) * 72 + j0 + 2 * lc + 8]);
            mma_bf16(O[dt][0], O[dt][1], O[dt][2], O[dt][3],
                     P[kc][0], P[kc][1], P[kc][2], P[kc][3], b0, b1);
        }
    }

    size_t obase = (size_t)b_ * 64 * 96 + hg * 32;
    #pragma unroll
    for (int dt = 0; dt < 4; dt++) {
        int d = dt * 8 + 2 * lc;
        *reinterpret_cast<__nv_bfloat162*>(&ow[obase + (size_t)ra * 96 + d]) =
            __floats2bfloat162_rn(O[dt][0] * inva, O[dt][1] * inva);
        *reinterpret_cast<__nv_bfloat162*>(&ow[obase + (size_t)rb * 96 + d]) =
            __floats2bfloat162_rn(O[dt][2] * invb, O[dt][3] * invb);
    }
}

// ---------------------------------------------------------------------------
// launch
// ---------------------------------------------------------------------------
extern "C" void kernel_launch(void* const* d_in, const int* in_sizes, int n_in,
                              void* d_out, int out_size)
{
    const float* x      = (const float*)d_in[0];
    const float* n1w    = (const float*)d_in[1];
    const float* n1b    = (const float*)d_in[2];
    const float* qkv_w  = (const float*)d_in[3];
    const float* qkv_b  = (const float*)d_in[4];
    const float* rpb    = (const float*)d_in[5];
    const float* proj_w = (const float*)d_in[6];
    const float* proj_b = (const float*)d_in[7];
    const float* n2w    = (const float*)d_in[8];
    const float* n2b    = (const float*)d_in[9];
    const float* w1     = (const float*)d_in[10];
    const float* b1     = (const float*)d_in[11];
    const float* w2     = (const float*)d_in[12];
    const float* b2     = (const float*)d_in[13];
    float* out = (float*)d_out;

    __nv_bfloat16 *ap, *bp, *wp;
    float *x1p;
    cudaGetSymbolAddress((void**)&ap,  g_a);
    cudaGetSymbolAddress((void**)&bp,  g_b);
    cudaGetSymbolAddress((void**)&x1p, g_x1);
    cudaGetSymbolAddress((void**)&wp,  g_wp);

    const int mlp_smem = 352 * 104 * (int)sizeof(__nv_bfloat16);   // 73216 B
    cudaFuncSetAttribute(mlp_kernel,
                         cudaFuncAttributeMaxDynamicSharedMemorySize, mlp_smem);
    cudaFuncSetAttribute(attn_kernel,
                         cudaFuncAttributeMaxDynamicSharedMemorySize, ATT_SMEM);

    // 0. weights -> bf16
    cvt_all<<<144, 256>>>(qkv_w, proj_w, w1, w2);
    // 1. MEGA front half: LN1 + QKV + attention   x -> g_b (bf16)
    attn_kernel<<<8192, 384, ATT_SMEM>>>(x, n1w, n1b, qkv_b, rpb, bp);
    // 2. proj + scatter + residual -> x1 (fp32), fused LN2 -> g_a (bf16)
    hgemm_kernel<2><<<dim3(4096, 1), 256>>>(bp, wp, proj_b, x1p, x, 96, 96,
                                            n2w, n2b, ap);
    // 3. fused MLP: out = x1 + gelu(g_a @ W1^T + b1) @ W2^T + b2
    mlp_kernel<<<4096, 256, mlp_smem>>>(ap, b1, b2, x1p, out);
}

// round 16
// speedup vs baseline: 5.4914x; 1.0241x over previous
#include <cuda_runtime.h>
#include <cuda_bf16.h>
#include <math.h>

// ---------------------------------------------------------------------------
// SwinBlock: B=8, H=W=256, C=96, WS=8, SS=4, NH=3, hd=32, DFF=384
// Round 16 = round 15 + latency surgery on the two dominant kernels:
//  * mlp: 16x96 warp tiles, GEMM1 C-frags repacked in-register to GEMM2
//    A-frags (Hs smem deleted), ping-pong weight prefetch.
//  * mega-attn: double-buffered QKV weight chunks, W0 prefetch hidden under LN1.
// proj(+LN2) and cvt stay byte-identical to the passing round-15 source.
// ---------------------------------------------------------------------------

#define MROWS 524288

__device__ __nv_bfloat16 g_a  [MROWS *  96];   // LN2 output (proj epilogue)
__device__ __nv_bfloat16 g_b  [MROWS *  96];   // attention output
__device__ float         g_x1 [MROWS *  96];

__device__ __nv_bfloat16 g_wq[288 * 96];
__device__ __nv_bfloat16 g_wp[ 96 * 96];
__device__ __nv_bfloat16 g_w1[384 * 96];
__device__ __nv_bfloat16 g_w2[ 96 * 384];

// ---------------------------------------------------------------------------
// helpers
// ---------------------------------------------------------------------------
__device__ __forceinline__ void cp_async16(void* smem_dst, const void* gmem_src)
{
    unsigned s = (unsigned)__cvta_generic_to_shared(smem_dst);
    asm volatile("cp.async.cg.shared.global [%0], [%1], 16;\n" :: "r"(s), "l"(gmem_src));
}
__device__ __forceinline__ void cp_commit()
{
    asm volatile("cp.async.commit_group;\n");
}
template<int N>
__device__ __forceinline__ void cp_wait()
{
    asm volatile("cp.async.wait_group %0;\n" :: "n"(N));
}

__device__ __forceinline__ void mma_bf16(
    float& c0, float& c1, float& c2, float& c3,
    unsigned a0, unsigned a1, unsigned a2, unsigned a3,
    unsigned b0, unsigned b1)
{
    asm volatile(
        "mma.sync.aligned.m16n8k16.row.col.f32.bf16.bf16.f32 "
        "{%0,%1,%2,%3}, {%4,%5,%6,%7}, {%8,%9}, {%0,%1,%2,%3};\n"
        : "+f"(c0), "+f"(c1), "+f"(c2), "+f"(c3)
        : "r"(a0), "r"(a1), "r"(a2), "r"(a3), "r"(b0), "r"(b1));
}

__device__ __forceinline__ unsigned pack_bf162(float lo, float hi)
{
    __nv_bfloat162 h = __floats2bfloat162_rn(lo, hi);
    return *reinterpret_cast<unsigned*>(&h);
}

// e^x for x <= 0 (down to ~-120), FMA-only (no MUFU).
__device__ __forceinline__ float fast_exp(float x)
{
    float t = fmaxf(x * 1.44269504089f, -124.0f);
    float ti = rintf(t);
    float tf = t - ti;                       // [-0.5, 0.5]
    float p = fmaf(tf, 0.00961812911f, 0.0555041087f);
    p = fmaf(tf, p, 0.240226507f);
    p = fmaf(tf, p, 0.693147181f);
    p = fmaf(tf, p, 1.0f);
    return __int_as_float(__float_as_int(p) + (((int)ti) << 23));
}

// one-shot fp32 -> bf16 weight convert (all four weight mats)
__global__ void __launch_bounds__(256) cvt_all(
    const float* __restrict__ a, const float* __restrict__ b,
    const float* __restrict__ c, const float* __restrict__ d)
{
    int i = blockIdx.x * 256 + threadIdx.x;
    if (i < 288 * 96) g_wq[i] = __float2bfloat16(a[i]);
    if (i <  96 * 96) g_wp[i] = __float2bfloat16(b[i]);
    if (i < 384 * 96) { g_w1[i] = __float2bfloat16(c[i]);
                        g_w2[i] = __float2bfloat16(d[i]); }
}

// ---------------------------------------------------------------------------
// bf16 GEMM, EPI 2 (proj): scatter+residual -> x1 fp32, fused LN2 -> lnout.
// (byte-identical to passing round 15)
// ---------------------------------------------------------------------------
constexpr int BM = 128, BN = 96, BK = 32;
constexpr int KS = BK + 8;   // 40 halves

__device__ __forceinline__ size_t dest_pixel(int r)
{
    int b_ = r >> 6, n = r & 63;
    int bb = b_ >> 10, wh = (b_ >> 5) & 31, ww = b_ & 31;
    int i = n >> 3, j = n & 7;
    int hh = (wh * 8 + i + 4) & 255;
    int wp = (ww * 8 + j + 4) & 255;
    return (size_t)bb * 65536 + (size_t)hh * 256 + wp;
}

__device__ __forceinline__ float gelu_exact(float v)
{
    return 0.5f * v * (1.0f + erff(v * 0.70710678118654752f));
}

template<int EPI>
__global__ void __launch_bounds__(256, 2) hgemm_kernel(
    const __nv_bfloat16* __restrict__ A, const __nv_bfloat16* __restrict__ B,
    const float* __restrict__ bias, void* __restrict__ Cv,
    const float* __restrict__ res, int K, int N,
    const float* __restrict__ lnw, const float* __restrict__ lnb,
    __nv_bfloat16* __restrict__ lnout)
{
    __shared__ __align__(16) __nv_bfloat16 As[2][BM][KS];
    __shared__ __align__(16) __nv_bfloat16 Bs[2][BN][KS];

    const int tid  = threadIdx.x;
    const int wid  = tid >> 5;
    const int lane = tid & 31;
    const int wm   = wid >> 1;
    const int wn   = wid & 1;
    const int lr   = lane >> 2;
    const int lc   = lane & 3;

    const long long rowBase = (long long)blockIdx.x * BM;
    const int colBase = blockIdx.y * BN;

    const int rA0 = tid >> 2,         cA0 = (tid & 3) * 8;
    const int rA1 = (tid + 256) >> 2;
    const int nK = K / BK;

    float acc[2][6][4];
    #pragma unroll
    for (int mt = 0; mt < 2; mt++)
        #pragma unroll
        for (int nt = 0; nt < 6; nt++)
            #pragma unroll
            for (int e = 0; e < 4; e++) acc[mt][nt][e] = 0.0f;

    {
        cp_async16(&As[0][rA0][cA0], A + (rowBase + rA0) * K + cA0);
        cp_async16(&As[0][rA1][cA0], A + (rowBase + rA1) * K + cA0);
        cp_async16(&Bs[0][rA0][cA0], B + (size_t)(colBase + rA0) * K + cA0);
        if (tid < 128)
            cp_async16(&Bs[0][rA1][cA0], B + (size_t)(colBase + rA1) * K + cA0);
        cp_commit();
    }

    for (int it = 0; it < nK; it++) {
        if (it + 1 < nK) {
            const int s = (it + 1) & 1;
            const int k0 = (it + 1) * BK;
            cp_async16(&As[s][rA0][cA0], A + (rowBase + rA0) * K + k0 + cA0);
            cp_async16(&As[s][rA1][cA0], A + (rowBase + rA1) * K + k0 + cA0);
            cp_async16(&Bs[s][rA0][cA0], B + (size_t)(colBase + rA0) * K + k0 + cA0);
            if (tid < 128)
                cp_async16(&Bs[s][rA1][cA0], B + (size_t)(colBase + rA1) * K + k0 + cA0);
            cp_commit();
            cp_wait<1>();
        } else {
            cp_wait<0>();
        }
        __syncthreads();

        const int s = it & 1;
        #pragma unroll
        for (int kb = 0; kb < BK; kb += 16) {
            unsigned a[2][4];
            #pragma unroll
            for (int mt = 0; mt < 2; mt++) {
                int r0 = wm * 32 + mt * 16 + lr;
                a[mt][0] = *reinterpret_cast<const unsigned*>(&As[s][r0][kb + 2 * lc]);
                a[mt][1] = *reinterpret_cast<const unsigned*>(&As[s][r0 + 8][kb + 2 * lc]);
                a[mt][2] = *reinterpret_cast<const unsigned*>(&As[s][r0][kb + 2 * lc + 8]);
                a[mt][3] = *reinterpret_cast<const unsigned*>(&As[s][r0 + 8][kb + 2 * lc + 8]);
            }
            unsigned bf[6][2];
            #pragma unroll
            for (int nt = 0; nt < 6; nt++) {
                int n0 = wn * 48 + nt * 8 + lr;
                bf[nt][0] = *reinterpret_cast<const unsigned*>(&Bs[s][n0][kb + 2 * lc]);
                bf[nt][1] = *reinterpret_cast<const unsigned*>(&Bs[s][n0][kb + 2 * lc + 8]);
            }
            #pragma unroll
            for (int mt = 0; mt < 2; mt++)
                #pragma unroll
                for (int nt = 0; nt < 6; nt++)
                    mma_bf16(acc[mt][nt][0], acc[mt][nt][1],
                             acc[mt][nt][2], acc[mt][nt][3],
                             a[mt][0], a[mt][1], a[mt][2], a[mt][3],
                             bf[nt][0], bf[nt][1]);
        }
        __syncthreads();
    }

    float* Cf = reinterpret_cast<float*>(Cv);

    if constexpr (EPI == 2) {
        __shared__ float2 red[2][128];
        float rsum[2][2] = {{0.f,0.f},{0.f,0.f}};
        float rsq [2][2] = {{0.f,0.f},{0.f,0.f}};
        size_t dpx[2][2];

        #pragma unroll
        for (int mt = 0; mt < 2; mt++) {
            long long row0 = rowBase + wm * 32 + mt * 16 + lr;
            dpx[mt][0] = dest_pixel((int)row0) * 96;
            dpx[mt][1] = dest_pixel((int)(row0 + 8)) * 96;
            #pragma unroll
            for (int nt = 0; nt < 6; nt++) {
                int col = wn * 48 + nt * 8 + 2 * lc;
                float2 bb = *reinterpret_cast<const float2*>(&bias[col]);
                float2 r0v = *reinterpret_cast<const float2*>(&res[dpx[mt][0] + col]);
                float2 r1v = *reinterpret_cast<const float2*>(&res[dpx[mt][1] + col]);
                float x00 = r0v.x + acc[mt][nt][0] + bb.x;
                float x01 = r0v.y + acc[mt][nt][1] + bb.y;
                float x10 = r1v.x + acc[mt][nt][2] + bb.x;
                float x11 = r1v.y + acc[mt][nt][3] + bb.y;
                *reinterpret_cast<float2*>(&Cf[dpx[mt][0] + col]) = make_float2(x00, x01);
                *reinterpret_cast<float2*>(&Cf[dpx[mt][1] + col]) = make_float2(x10, x11);
                acc[mt][nt][0] = x00; acc[mt][nt][1] = x01;
                acc[mt][nt][2] = x10; acc[mt][nt][3] = x11;
                rsum[mt][0] += x00 + x01;  rsq[mt][0] += x00*x00 + x01*x01;
                rsum[mt][1] += x10 + x11;  rsq[mt][1] += x10*x10 + x11*x11;
            }
        }
        #pragma unroll
        for (int mt = 0; mt < 2; mt++)
            #pragma unroll
            for (int rr = 0; rr < 2; rr++) {
                rsum[mt][rr] += __shfl_xor_sync(0xffffffffu, rsum[mt][rr], 1);
                rsum[mt][rr] += __shfl_xor_sync(0xffffffffu, rsum[mt][rr], 2);
                rsq [mt][rr] += __shfl_xor_sync(0xffffffffu, rsq [mt][rr], 1);
                rsq [mt][rr] += __shfl_xor_sync(0xffffffffu, rsq [mt][rr], 2);
            }
        if (lc == 0) {
            #pragma unroll
            for (int mt = 0; mt < 2; mt++)
                #pragma unroll
                for (int rr = 0; rr < 2; rr++)
                    red[wn][wm * 32 + mt * 16 + lr + rr * 8] =
                        make_float2(rsum[mt][rr], rsq[mt][rr]);
        }
        __syncthreads();
        #pragma unroll
        for (int mt = 0; mt < 2; mt++) {
            #pragma unroll
            for (int rr = 0; rr < 2; rr++) {
                int rl = wm * 32 + mt * 16 + lr + rr * 8;
                float2 p0 = red[0][rl], p1 = red[1][rl];
                float mean = (p0.x + p1.x) * (1.0f / 96.0f);
                float var  = (p0.y + p1.y) * (1.0f / 96.0f) - mean * mean;
                float rstd = rsqrtf(var + 1e-5f);
                #pragma unroll
                for (int nt = 0; nt < 6; nt++) {
                    int col = wn * 48 + nt * 8 + 2 * lc;
                    float w0 = lnw[col], w1v = lnw[col + 1];
                    float b0 = lnb[col], b1v = lnb[col + 1];
                    float y0 = (acc[mt][nt][2 * rr]     - mean) * rstd * w0 + b0;
                    float y1 = (acc[mt][nt][2 * rr + 1] - mean) * rstd * w1v + b1v;
                    __nv_bfloat162 h = __floats2bfloat162_rn(y0, y1);
                    *reinterpret_cast<__nv_bfloat162*>(&lnout[dpx[mt][rr] + col]) = h;
                }
            }
        }
    }
}

// ---------------------------------------------------------------------------
// Fused MLP v2: 16x96 warp tiles, in-register gelu+repack (no Hs), ping-pong
// weight prefetch. out = x1 + gelu(ln2 @ W1^T + b1) @ W2^T + b2.
// smem: As 128x104 + Ws0/Ws1 96x104 halves = 66560 B.
// ---------------------------------------------------------------------------
constexpr int MKS = 104;

__global__ void __launch_bounds__(256, 2) mlp_kernel(
    const __nv_bfloat16* __restrict__ A, const float* __restrict__ b1,
    const float* __restrict__ b2, const float* __restrict__ x1,
    float* __restrict__ out)
{
    extern __shared__ __align__(16) __nv_bfloat16 dsm[];
    __nv_bfloat16* As  = dsm;                 // [128][MKS]
    __nv_bfloat16* Ws0 = dsm + 128 * MKS;     // [96][MKS]  (W1 chunks)
    __nv_bfloat16* Ws1 = Ws0 + 96 * MKS;      // [96][MKS]  (W2 chunks)

    const int tid  = threadIdx.x;
    const int wid  = tid >> 5;                // 0..7 -> rows wid*16..+16
    const int lane = tid & 31;
    const int lr   = lane >> 2;
    const int lc   = lane & 3;
    const long long rowBase = (long long)blockIdx.x * 128;
    const int rA = wid * 16 + lr;             // local row
    const int rB = rA + 8;

    float acc_out[12][4];
    #pragma unroll
    for (int nt = 0; nt < 12; nt++)
        { acc_out[nt][0]=acc_out[nt][1]=acc_out[nt][2]=acc_out[nt][3]=0.f; }

    // group 0: A tile (128x96 halves = 1536 chunks)
    #pragma unroll
    for (int i = 0; i < 6; i++) {
        int ch = i * 256 + tid;
        int r = ch / 12, ck = ch % 12;
        cp_async16(&As[r * MKS + ck * 8], A + (rowBase + r) * 96 + ck * 8);
    }
    cp_commit();
    // group 1: W1 chunk 0
    for (int ch = tid; ch < 1152; ch += 256) {
        int r = ch / 12, ck = ch % 12;
        cp_async16(&Ws0[r * MKS + ck * 8], g_w1 + r * 96 + ck * 8);
    }
    cp_commit();

    for (int c = 0; c < 4; c++) {
        // prefetch W2 chunk c -> Ws1 (Ws1 free: GEMM2(c-1) synced below)
        for (int ch = tid; ch < 1152; ch += 256) {
            int r = ch / 12, ck = ch % 12;
            cp_async16(&Ws1[r * MKS + ck * 8], g_w2 + r * 384 + c * 96 + ck * 8);
        }
        cp_commit();
        cp_wait<1>();            // A + W1c done (W2c outstanding)
        __syncthreads();

        // GEMM1: acc1 = A @ W1c^T  (warp: 16 rows x 96 cols)
        float acc1[12][4];
        #pragma unroll
        for (int nt = 0; nt < 12; nt++)
            { acc1[nt][0]=acc1[nt][1]=acc1[nt][2]=acc1[nt][3]=0.f; }
        #pragma unroll
        for (int kb = 0; kb < 96; kb += 16) {
            unsigned a0 = *reinterpret_cast<const unsigned*>(&As[rA * MKS + kb + 2 * lc]);
            unsigned a1 = *reinterpret_cast<const unsigned*>(&As[rB * MKS + kb + 2 * lc]);
            unsigned a2 = *reinterpret_cast<const unsigned*>(&As[rA * MKS + kb + 2 * lc + 8]);
            unsigned a3 = *reinterpret_cast<const unsigned*>(&As[rB * MKS + kb + 2 * lc + 8]);
            #pragma unroll
            for (int nt = 0; nt < 12; nt++) {
                int n0 = nt * 8 + lr;
                unsigned b0 = *reinterpret_cast<const unsigned*>(&Ws0[n0 * MKS + kb + 2 * lc]);
                unsigned bb = *reinterpret_cast<const unsigned*>(&Ws0[n0 * MKS + kb + 2 * lc + 8]);
                mma_bf16(acc1[nt][0], acc1[nt][1], acc1[nt][2], acc1[nt][3],
                         a0, a1, a2, a3, b0, bb);
            }
        }

        // bias + gelu in registers, repack C-frags -> A-frags (P)
        unsigned P[6][4];
        #pragma unroll
        for (int nt = 0; nt < 12; nt++) {
            float2 bb = *reinterpret_cast<const float2*>(&b1[c * 96 + nt * 8 + 2 * lc]);
            acc1[nt][0] = gelu_exact(acc1[nt][0] + bb.x);
            acc1[nt][1] = gelu_exact(acc1[nt][1] + bb.y);
            acc1[nt][2] = gelu_exact(acc1[nt][2] + bb.x);
            acc1[nt][3] = gelu_exact(acc1[nt][3] + bb.y);
        }
        #pragma unroll
        for (int kc = 0; kc < 6; kc++) {
            P[kc][0] = pack_bf162(acc1[2 * kc][0],     acc1[2 * kc][1]);
            P[kc][1] = pack_bf162(acc1[2 * kc][2],     acc1[2 * kc][3]);
            P[kc][2] = pack_bf162(acc1[2 * kc + 1][0], acc1[2 * kc + 1][1]);
            P[kc][3] = pack_bf162(acc1[2 * kc + 1][2], acc1[2 * kc + 1][3]);
        }

        __syncthreads();         // all warps done with Ws0 (W1c)
        if (c < 3) {             // prefetch W1 chunk c+1 -> Ws0
            for (int ch = tid; ch < 1152; ch += 256) {
                int r = ch / 12, ck = ch % 12;
                cp_async16(&Ws0[r * MKS + ck * 8],
                           g_w1 + ((c + 1) * 96 + r) * 96 + ck * 8);
            }
            cp_commit();
            cp_wait<1>();        // W2c done (W1c+1 outstanding)
        } else {
            cp_wait<0>();
        }
        __syncthreads();         // W2c visible

        // GEMM2: acc_out += gelu(h) @ W2c^T
        #pragma unroll
        for (int kc = 0; kc < 6; kc++) {
            int kb = kc * 16;
            #pragma unroll
            for (int nt = 0; nt < 12; nt++) {
                int n0 = nt * 8 + lr;
                unsigned b0 = *reinterpret_cast<const unsigned*>(&Ws1[n0 * MKS + kb + 2 * lc]);
                unsigned bb = *reinterpret_cast<const unsigned*>(&Ws1[n0 * MKS + kb + 2 * lc + 8]);
                mma_bf16(acc_out[nt][0], acc_out[nt][1], acc_out[nt][2], acc_out[nt][3],
                         P[kc][0], P[kc][1], P[kc][2], P[kc][3], b0, bb);
            }
        }
        __syncthreads();         // Ws1 free for next chunk
    }

    // epilogue: out = acc_out + b2 + x1 (fp32)
    const long long row0 = rowBase + rA;
    const long long row1 = rowBase + rB;
    #pragma unroll
    for (int nt = 0; nt < 12; nt++) {
        int col = nt * 8 + 2 * lc;
        float2 bb = *reinterpret_cast<const float2*>(&b2[col]);
        float2 r0v = *reinterpret_cast<const float2*>(&x1[row0 * 96 + col]);
        float2 r1v = *reinterpret_cast<const float2*>(&x1[row1 * 96 + col]);
        *reinterpret_cast<float2*>(&out[row0 * 96 + col]) =
            make_float2(r0v.x + acc_out[nt][0] + bb.x,
                        r0v.y + acc_out[nt][1] + bb.y);
        *reinterpret_cast<float2*>(&out[row1 * 96 + col]) =
            make_float2(r1v.x + acc_out[nt][2] + bb.x,
                        r1v.y + acc_out[nt][3] + bb.y);
    }
}

// ---------------------------------------------------------------------------
// MEGA front half: LN1 + QKV GEMM (double-buffered weights) + attention.
// Dynamic smem halves: As 6656 | Ws0 9984 | Ws1 9984 | Qs 7680 | Ks 7680 |
//                      Vt 6912 + rpbs 675 f32 + ids 64 i32 = 100748 B.
// ---------------------------------------------------------------------------
__device__ __forceinline__ int regid(int g)
{
    return g < 248 ? 0 : (g < 252 ? 1 : 2);
}

constexpr int ATT_SMEM = 100864;

__global__ void __launch_bounds__(384, 2) attn_kernel(
    const float* __restrict__ x, const float* __restrict__ n1w,
    const float* __restrict__ n1b, const float* __restrict__ qkv_b,
    const float* __restrict__ rpb, __nv_bfloat16* __restrict__ ow)
{
    extern __shared__ __align__(16) __nv_bfloat16 dsm[];
    __nv_bfloat16* As  = dsm;                   // [64][104]
    __nv_bfloat16* Ws0 = As + 6656;             // [96][104]
    __nv_bfloat16* Ws1 = Ws0 + 9984;            // [96][104]
    __nv_bfloat16* Qs  = Ws1 + 9984;            // [3][64][40]
    __nv_bfloat16* Ks  = Qs + 7680;             // [3][64][40]
    __nv_bfloat16* Vt  = Ks + 7680;             // [3][32][72]
    float*         rpbs = reinterpret_cast<float*>(Vt + 6912);   // [3][225]
    int*           ids  = reinterpret_cast<int*>(rpbs + 675);    // [64]

    const int b_  = blockIdx.x;
    const int tid = threadIdx.x;
    const int wid = tid >> 5, lane = tid & 31;
    const int lr  = lane >> 2, lc = lane & 3;

    // prefetch W chunk 0 (Q weights) immediately -> hidden under LN1
    for (int ch = tid; ch < 1152; ch += 384) {
        int r = ch / 12, ck = ch % 12;
        cp_async16(&Ws0[r * 104 + ck * 8], g_wq + r * 96 + ck * 8);
    }
    cp_commit();

    // rpb table + region ids
    for (int t = tid; t < 675; t += 384)
        rpbs[t] = rpb[(t % 225) * 3 + t / 225];
    const int whc = (b_ >> 5) & 31, wwc = b_ & 31;
    if (tid < 64) {
        int i = tid >> 3, j = tid & 7;
        ids[tid] = regid(whc * 8 + i) * 3 + regid(wwc * 8 + j);
    }

    // ---- phase 1: LN1 (warp per row, gathered from pixel order)
    const int bb_ = b_ >> 10;
    for (int r = wid; r < 64; r += 12) {
        int i = r >> 3, j = r & 7;
        int hh = (whc * 8 + i + 4) & 255;
        int wp = (wwc * 8 + j + 4) & 255;
        size_t src = ((size_t)bb_ * 65536 + (size_t)hh * 256 + wp) * 96;
        float v0 = x[src + lane], v1 = x[src + lane + 32], v2 = x[src + lane + 64];
        float s = v0 + v1 + v2;
        #pragma unroll
        for (int o = 16; o > 0; o >>= 1) s += __shfl_xor_sync(0xffffffffu, s, o);
        float mean = s * (1.0f / 96.0f);
        float d0 = v0 - mean, d1 = v1 - mean, d2 = v2 - mean;
        float vv = d0 * d0 + d1 * d1 + d2 * d2;
        #pragma unroll
        for (int o = 16; o > 0; o >>= 1) vv += __shfl_xor_sync(0xffffffffu, vv, o);
        float rstd = rsqrtf(vv * (1.0f / 96.0f) + 1e-5f);
        As[r * 104 + lane]      = __float2bfloat16(d0 * rstd * n1w[lane]      + n1b[lane]);
        As[r * 104 + lane + 32] = __float2bfloat16(d1 * rstd * n1w[lane + 32] + n1b[lane + 32]);
        As[r * 104 + lane + 64] = __float2bfloat16(d2 * rstd * n1w[lane + 64] + n1b[lane + 64]);
    }
    __syncthreads();               // As / rpbs / ids visible

    // ---- phase 2: QKV GEMM, 3 chunks, ping-pong weight buffers
    const int gm = (wid & 3) * 16;
    const int gh = wid >> 2;
    const int rA = gm + lr, rB = rA + 8;

    for (int c = 0; c < 3; c++) {
        if (c < 2) {               // prefetch next chunk into the other buffer
            __nv_bfloat16* Wn = ((c + 1) & 1) ? Ws1 : Ws0;
            for (int ch = tid; ch < 1152; ch += 384) {
                int r = ch / 12, ck = ch % 12;
                cp_async16(&Wn[r * 104 + ck * 8],
                           g_wq + ((c + 1) * 96 + r) * 96 + ck * 8);
            }
            cp_commit();
            cp_wait<1>();
        } else {
            cp_wait<0>();
        }
        __syncthreads();           // chunk c visible

        const __nv_bfloat16* W = (c & 1) ? Ws1 : Ws0;
        float acc[4][4];
        #pragma unroll
        for (int nt = 0; nt < 4; nt++) { acc[nt][0]=acc[nt][1]=acc[nt][2]=acc[nt][3]=0.f; }
        #pragma unroll
        for (int kb = 0; kb < 96; kb += 16) {
            unsigned a0 = *reinterpret_cast<const unsigned*>(&As[rA * 104 + kb + 2 * lc]);
            unsigned a1 = *reinterpret_cast<const unsigned*>(&As[rB * 104 + kb + 2 * lc]);
            unsigned a2 = *reinterpret_cast<const unsigned*>(&As[rA * 104 + kb + 2 * lc + 8]);
            unsigned a3 = *reinterpret_cast<const unsigned*>(&As[rB * 104 + kb + 2 * lc + 8]);
            #pragma unroll
            for (int nt = 0; nt < 4; nt++) {
                int n0 = gh * 32 + nt * 8 + lr;
                unsigned b0 = *reinterpret_cast<const unsigned*>(&W[n0 * 104 + kb + 2 * lc]);
                unsigned b1 = *reinterpret_cast<const unsigned*>(&W[n0 * 104 + kb + 2 * lc + 8]);
                mma_bf16(acc[nt][0], acc[nt][1], acc[nt][2], acc[nt][3],
                         a0, a1, a2, a3, b0, b1);
            }
        }

        #pragma unroll
        for (int nt = 0; nt < 4; nt++) {
            int d = nt * 8 + 2 * lc;
            float2 bb = *reinterpret_cast<const float2*>(&qkv_b[c * 96 + gh * 32 + d]);
            float v00 = acc[nt][0] + bb.x, v01 = acc[nt][1] + bb.y;
            float v10 = acc[nt][2] + bb.x, v11 = acc[nt][3] + bb.y;
            if (c == 0) {
                *reinterpret_cast<__nv_bfloat162*>(&Qs[gh * 2560 + rA * 40 + d]) =
                    __floats2bfloat162_rn(v00, v01);
                *reinterpret_cast<__nv_bfloat162*>(&Qs[gh * 2560 + rB * 40 + d]) =
                    __floats2bfloat162_rn(v10, v11);
            } else if (c == 1) {
                *reinterpret_cast<__nv_bfloat162*>(&Ks[gh * 2560 + rA * 40 + d]) =
                    __floats2bfloat162_rn(v00, v01);
                *reinterpret_cast<__nv_bfloat162*>(&Ks[gh * 2560 + rB * 40 + d]) =
                    __floats2bfloat162_rn(v10, v11);
            } else {
                Vt[gh * 2304 + d * 72 + rA]       = __float2bfloat16(v00);
                Vt[gh * 2304 + (d + 1) * 72 + rA] = __float2bfloat16(v01);
                Vt[gh * 2304 + d * 72 + rB]       = __float2bfloat16(v10);
                Vt[gh * 2304 + (d + 1) * 72 + rB] = __float2bfloat16(v11);
            }
        }
        __syncthreads();           // GEMM(c) done -> its buffer safe to refill
    }

    // ---- phase 3: attention (identical logic to rounds 13-15)
    const int hg = wid >> 2, ww = wid & 3;
    const int r0 = ww * 16;
    const int ra = r0 + lr, rb = ra + 8;
    const float scale = 0.17677669529663687f;

    unsigned qf[2][4];
    #pragma unroll
    for (int kc = 0; kc < 2; kc++) {
        int kb = kc * 16;
        qf[kc][0] = *reinterpret_cast<const unsigned*>(&Qs[hg * 2560 + ra * 40 + kb + 2 * lc]);
        qf[kc][1] = *reinterpret_cast<const unsigned*>(&Qs[hg * 2560 + rb * 40 + kb + 2 * lc]);
        qf[kc][2] = *reinterpret_cast<const unsigned*>(&Qs[hg * 2560 + ra * 40 + kb + 2 * lc + 8]);
        qf[kc][3] = *reinterpret_cast<const unsigned*>(&Qs[hg * 2560 + rb * 40 + kb + 2 * lc + 8]);
    }

    float S[8][4];
    #pragma unroll
    for (int nt = 0; nt < 8; nt++) { S[nt][0]=S[nt][1]=S[nt][2]=S[nt][3]=0.f; }
    #pragma unroll
    for (int nt = 0; nt < 8; nt++) {
        int n0 = nt * 8;
        #pragma unroll
        for (int kc = 0; kc < 2; kc++) {
            int kb = kc * 16;
            unsigned b0 = *reinterpret_cast<const unsigned*>(&Ks[hg * 2560 + (n0 + lr) * 40 + kb + 2 * lc]);
            unsigned b1 = *reinterpret_cast<const unsigned*>(&Ks[hg * 2560 + (n0 + lr) * 40 + kb + 2 * lc + 8]);
            mma_bf16(S[nt][0], S[nt][1], S[nt][2], S[nt][3],
                     qf[kc][0], qf[kc][1], qf[kc][2], qf[kc][3], b0, b1);
        }
    }

    const int i_a = ra >> 3, j_a = ra & 7;
    const int i_b = rb >> 3, j_b = rb & 7;
    const int id_a = ids[ra], id_b = ids[rb];
    float mxa = -1e30f, mxb = -1e30f;
    #pragma unroll
    for (int nt = 0; nt < 8; nt++) {
        #pragma unroll
        for (int e = 0; e < 2; e++) {
            int cc = nt * 8 + 2 * lc + e;
            int ic = cc >> 3, jc = cc & 7;
            int idc = ids[cc];
            float ba = rpbs[hg * 225 + (i_a - ic + 7) * 15 + (j_a - jc + 7)]
                     + (id_a == idc ? 0.0f : -100.0f);
            float bb = rpbs[hg * 225 + (i_b - ic + 7) * 15 + (j_b - jc + 7)]
                     + (id_b == idc ? 0.0f : -100.0f);
            S[nt][e]     = fmaf(S[nt][e],     scale, ba);
            S[nt][2 + e] = fmaf(S[nt][2 + e], scale, bb);
            mxa = fmaxf(mxa, S[nt][e]);
            mxb = fmaxf(mxb, S[nt][2 + e]);
        }
    }
    mxa = fmaxf(mxa, __shfl_xor_sync(0xffffffffu, mxa, 1));
    mxa = fmaxf(mxa, __shfl_xor_sync(0xffffffffu, mxa, 2));
    mxb = fmaxf(mxb, __shfl_xor_sync(0xffffffffu, mxb, 1));
    mxb = fmaxf(mxb, __shfl_xor_sync(0xffffffffu, mxb, 2));

    float sa = 0.0f, sb = 0.0f;
    #pragma unroll
    for (int nt = 0; nt < 8; nt++) {
        #pragma unroll
        for (int e = 0; e < 2; e++) {
            float pa = fast_exp(S[nt][e] - mxa);
            float pb = fast_exp(S[nt][2 + e] - mxb);
            S[nt][e] = pa;  S[nt][2 + e] = pb;
            sa += pa;  sb += pb;
        }
    }
    sa += __shfl_xor_sync(0xffffffffu, sa, 1);
    sa += __shfl_xor_sync(0xffffffffu, sa, 2);
    sb += __shfl_xor_sync(0xffffffffu, sb, 1);
    sb += __shfl_xor_sync(0xffffffffu, sb, 2);
    float inva = 1.0f / sa, invb = 1.0f / sb;

    unsigned P[4][4];
    #pragma unroll
    for (int kc = 0; kc < 4; kc++) {
        P[kc][0] = pack_bf162(S[2 * kc][0],     S[2 * kc][1]);
        P[kc][1] = pack_bf162(S[2 * kc][2],     S[2 * kc][3]);
        P[kc][2] = pack_bf162(S[2 * kc + 1][0], S[2 * kc + 1][1]);
        P[kc][3] = pack_bf162(S[2 * kc + 1][2], S[2 * kc + 1][3]);
    }

    float O[4][4];
    #pragma unroll
    for (int dt = 0; dt < 4; dt++) { O[dt][0]=O[dt][1]=O[dt][2]=O[dt][3]=0.f; }
    #pragma unroll
    for (int kc = 0; kc < 4; kc++) {
        int j0 = kc * 16;
        #pragma unroll
        for (int dt = 0; dt < 4; dt++) {
            int d0 = dt * 8;
            unsigned b0 = *reinterpret_cast<const unsigned*>(&Vt[hg * 2304 + (d0 + lr) * 72 + j0 + 2 * lc]);
            unsigned b1 = *reinterpret_cast<const unsigned*>(&Vt[hg * 2304 + (d0 + lr) * 72 + j0 + 2 * lc + 8]);
            mma_bf16(O[dt][0], O[dt][1], O[dt][2], O[dt][3],
                     P[kc][0], P[kc][1], P[kc][2], P[kc][3], b0, b1);
        }
    }

    size_t obase = (size_t)b_ * 64 * 96 + hg * 32;
    #pragma unroll
    for (int dt = 0; dt < 4; dt++) {
        int d = dt * 8 + 2 * lc;
        *reinterpret_cast<__nv_bfloat162*>(&ow[obase + (size_t)ra * 96 + d]) =
            __floats2bfloat162_rn(O[dt][0] * inva, O[dt][1] * inva);
        *reinterpret_cast<__nv_bfloat162*>(&ow[obase + (size_t)rb * 96 + d]) =
            __floats2bfloat162_rn(O[dt][2] * invb, O[dt][3] * invb);
    }
}

// ---------------------------------------------------------------------------
// launch
// ---------------------------------------------------------------------------
extern "C" void kernel_launch(void* const* d_in, const int* in_sizes, int n_in,
                              void* d_out, int out_size)
{
    const float* x      = (const float*)d_in[0];
    const float* n1w    = (const float*)d_in[1];
    const float* n1b    = (const float*)d_in[2];
    const float* qkv_w  = (const float*)d_in[3];
    const float* qkv_b  = (const float*)d_in[4];
    const float* rpb    = (const float*)d_in[5];
    const float* proj_w = (const float*)d_in[6];
    const float* proj_b = (const float*)d_in[7];
    const float* n2w    = (const float*)d_in[8];
    const float* n2b    = (const float*)d_in[9];
    const float* w1     = (const float*)d_in[10];
    const float* b1     = (const float*)d_in[11];
    const float* w2     = (const float*)d_in[12];
    const float* b2     = (const float*)d_in[13];
    float* out = (float*)d_out;

    __nv_bfloat16 *ap, *bp, *wp;
    float *x1p;
    cudaGetSymbolAddress((void**)&ap,  g_a);
    cudaGetSymbolAddress((void**)&bp,  g_b);
    cudaGetSymbolAddress((void**)&x1p, g_x1);
    cudaGetSymbolAddress((void**)&wp,  g_wp);

    const int mlp_smem = (128 + 192) * MKS * (int)sizeof(__nv_bfloat16);  // 66560
    cudaFuncSetAttribute(mlp_kernel,
                         cudaFuncAttributeMaxDynamicSharedMemorySize, mlp_smem);
    cudaFuncSetAttribute(attn_kernel,
                         cudaFuncAttributeMaxDynamicSharedMemorySize, ATT_SMEM);

    // 0. weights -> bf16
    cvt_all<<<144, 256>>>(qkv_w, proj_w, w1, w2);
    // 1. MEGA front half: LN1 + QKV + attention   x -> g_b (bf16)
    attn_kernel<<<8192, 384, ATT_SMEM>>>(x, n1w, n1b, qkv_b, rpb, bp);
    // 2. proj + scatter + residual -> x1 (fp32), fused LN2 -> g_a (bf16)
    hgemm_kernel<2><<<dim3(4096, 1), 256>>>(bp, wp, proj_b, x1p, x, 96, 96,
                                            n2w, n2b, ap);
    // 3. fused MLP v2: out = x1 + gelu(g_a @ W1^T + b1) @ W2^T + b2
    mlp_kernel<<<4096, 256, mlp_smem>>>(ap, b1, b2, x1p, out);
}

// round 17
// speedup vs baseline: 5.5462x; 1.0100x over previous
#include <cuda_runtime.h>
#include <cuda_bf16.h>
#include <math.h>

// ---------------------------------------------------------------------------
// SwinBlock: B=8, H=W=256, C=96, WS=8, SS=4, NH=3, hd=32, DFF=384
// Round 17 = round 16 + ldmatrix: all per-fragment scalar LDS in mlp_kernel
// and attn_kernel replaced by ldmatrix.x4 (r16 ncu: alu 38% top pipe, tensor
// 30.7% -> issue-bound on scalar loads/addressing). Numerics bit-identical.
// proj(+LN2) and cvt stay byte-identical to the passing round-16 source.
// ---------------------------------------------------------------------------

#define MROWS 524288

__device__ __nv_bfloat16 g_a  [MROWS *  96];   // LN2 output (proj epilogue)
__device__ __nv_bfloat16 g_b  [MROWS *  96];   // attention output
__device__ float         g_x1 [MROWS *  96];

__device__ __nv_bfloat16 g_wq[288 * 96];
__device__ __nv_bfloat16 g_wp[ 96 * 96];
__device__ __nv_bfloat16 g_w1[384 * 96];
__device__ __nv_bfloat16 g_w2[ 96 * 384];

// ---------------------------------------------------------------------------
// helpers
// ---------------------------------------------------------------------------
__device__ __forceinline__ void cp_async16(void* smem_dst, const void* gmem_src)
{
    unsigned s = (unsigned)__cvta_generic_to_shared(smem_dst);
    asm volatile("cp.async.cg.shared.global [%0], [%1], 16;\n" :: "r"(s), "l"(gmem_src));
}
__device__ __forceinline__ void cp_commit()
{
    asm volatile("cp.async.commit_group;\n");
}
template<int N>
__device__ __forceinline__ void cp_wait()
{
    asm volatile("cp.async.wait_group %0;\n" :: "n"(N));
}

__device__ __forceinline__ void mma_bf16(
    float& c0, float& c1, float& c2, float& c3,
    unsigned a0, unsigned a1, unsigned a2, unsigned a3,
    unsigned b0, unsigned b1)
{
    asm volatile(
        "mma.sync.aligned.m16n8k16.row.col.f32.bf16.bf16.f32 "
        "{%0,%1,%2,%3}, {%4,%5,%6,%7}, {%8,%9}, {%0,%1,%2,%3};\n"
        : "+f"(c0), "+f"(c1), "+f"(c2), "+f"(c3)
        : "r"(a0), "r"(a1), "r"(a2), "r"(a3), "r"(b0), "r"(b1));
}

// ldmatrix.x4: loads four 8x8 b16 matrices; lane L supplies the row pointer
// for matrix L/8, row L%8.
__device__ __forceinline__ void ldsm_x4(
    unsigned& r0, unsigned& r1, unsigned& r2, unsigned& r3, const void* p)
{
    unsigned s = (unsigned)__cvta_generic_to_shared(p);
    asm volatile("ldmatrix.sync.aligned.m8n8.x4.shared.b16 {%0,%1,%2,%3}, [%4];"
        : "=r"(r0), "=r"(r1), "=r"(r2), "=r"(r3) : "r"(s));
}

__device__ __forceinline__ unsigned pack_bf162(float lo, float hi)
{
    __nv_bfloat162 h = __floats2bfloat162_rn(lo, hi);
    return *reinterpret_cast<unsigned*>(&h);
}

// e^x for x <= 0 (down to ~-120), FMA-only (no MUFU).
__device__ __forceinline__ float fast_exp(float x)
{
    float t = fmaxf(x * 1.44269504089f, -124.0f);
    float ti = rintf(t);
    float tf = t - ti;                       // [-0.5, 0.5]
    float p = fmaf(tf, 0.00961812911f, 0.0555041087f);
    p = fmaf(tf, p, 0.240226507f);
    p = fmaf(tf, p, 0.693147181f);
    p = fmaf(tf, p, 1.0f);
    return __int_as_float(__float_as_int(p) + (((int)ti) << 23));
}

// one-shot fp32 -> bf16 weight convert (all four weight mats)
__global__ void __launch_bounds__(256) cvt_all(
    const float* __restrict__ a, const float* __restrict__ b,
    const float* __restrict__ c, const float* __restrict__ d)
{
    int i = blockIdx.x * 256 + threadIdx.x;
    if (i < 288 * 96) g_wq[i] = __float2bfloat16(a[i]);
    if (i <  96 * 96) g_wp[i] = __float2bfloat16(b[i]);
    if (i < 384 * 96) { g_w1[i] = __float2bfloat16(c[i]);
                        g_w2[i] = __float2bfloat16(d[i]); }
}

// ---------------------------------------------------------------------------
// bf16 GEMM, EPI 2 (proj): scatter+residual -> x1 fp32, fused LN2 -> lnout.
// (byte-identical to passing round 16)
// ---------------------------------------------------------------------------
constexpr int BM = 128, BN = 96, BK = 32;
constexpr int KS = BK + 8;   // 40 halves

__device__ __forceinline__ size_t dest_pixel(int r)
{
    int b_ = r >> 6, n = r & 63;
    int bb = b_ >> 10, wh = (b_ >> 5) & 31, ww = b_ & 31;
    int i = n >> 3, j = n & 7;
    int hh = (wh * 8 + i + 4) & 255;
    int wp = (ww * 8 + j + 4) & 255;
    return (size_t)bb * 65536 + (size_t)hh * 256 + wp;
}

__device__ __forceinline__ float gelu_exact(float v)
{
    return 0.5f * v * (1.0f + erff(v * 0.70710678118654752f));
}

template<int EPI>
__global__ void __launch_bounds__(256, 2) hgemm_kernel(
    const __nv_bfloat16* __restrict__ A, const __nv_bfloat16* __restrict__ B,
    const float* __restrict__ bias, void* __restrict__ Cv,
    const float* __restrict__ res, int K, int N,
    const float* __restrict__ lnw, const float* __restrict__ lnb,
    __nv_bfloat16* __restrict__ lnout)
{
    __shared__ __align__(16) __nv_bfloat16 As[2][BM][KS];
    __shared__ __align__(16) __nv_bfloat16 Bs[2][BN][KS];

    const int tid  = threadIdx.x;
    const int wid  = tid >> 5;
    const int lane = tid & 31;
    const int wm   = wid >> 1;
    const int wn   = wid & 1;
    const int lr   = lane >> 2;
    const int lc   = lane & 3;

    const long long rowBase = (long long)blockIdx.x * BM;
    const int colBase = blockIdx.y * BN;

    const int rA0 = tid >> 2,         cA0 = (tid & 3) * 8;
    const int rA1 = (tid + 256) >> 2;
    const int nK = K / BK;

    float acc[2][6][4];
    #pragma unroll
    for (int mt = 0; mt < 2; mt++)
        #pragma unroll
        for (int nt = 0; nt < 6; nt++)
            #pragma unroll
            for (int e = 0; e < 4; e++) acc[mt][nt][e] = 0.0f;

    {
        cp_async16(&As[0][rA0][cA0], A + (rowBase + rA0) * K + cA0);
        cp_async16(&As[0][rA1][cA0], A + (rowBase + rA1) * K + cA0);
        cp_async16(&Bs[0][rA0][cA0], B + (size_t)(colBase + rA0) * K + cA0);
        if (tid < 128)
            cp_async16(&Bs[0][rA1][cA0], B + (size_t)(colBase + rA1) * K + cA0);
        cp_commit();
    }

    for (int it = 0; it < nK; it++) {
        if (it + 1 < nK) {
            const int s = (it + 1) & 1;
            const int k0 = (it + 1) * BK;
            cp_async16(&As[s][rA0][cA0], A + (rowBase + rA0) * K + k0 + cA0);
            cp_async16(&As[s][rA1][cA0], A + (rowBase + rA1) * K + k0 + cA0);
            cp_async16(&Bs[s][rA0][cA0], B + (size_t)(colBase + rA0) * K + k0 + cA0);
            if (tid < 128)
                cp_async16(&Bs[s][rA1][cA0], B + (size_t)(colBase + rA1) * K + k0 + cA0);
            cp_commit();
            cp_wait<1>();
        } else {
            cp_wait<0>();
        }
        __syncthreads();

        const int s = it & 1;
        #pragma unroll
        for (int kb = 0; kb < BK; kb += 16) {
            unsigned a[2][4];
            #pragma unroll
            for (int mt = 0; mt < 2; mt++) {
                int r0 = wm * 32 + mt * 16 + lr;
                a[mt][0] = *reinterpret_cast<const unsigned*>(&As[s][r0][kb + 2 * lc]);
                a[mt][1] = *reinterpret_cast<const unsigned*>(&As[s][r0 + 8][kb + 2 * lc]);
                a[mt][2] = *reinterpret_cast<const unsigned*>(&As[s][r0][kb + 2 * lc + 8]);
                a[mt][3] = *reinterpret_cast<const unsigned*>(&As[s][r0 + 8][kb + 2 * lc + 8]);
            }
            unsigned bf[6][2];
            #pragma unroll
            for (int nt = 0; nt < 6; nt++) {
                int n0 = wn * 48 + nt * 8 + lr;
                bf[nt][0] = *reinterpret_cast<const unsigned*>(&Bs[s][n0][kb + 2 * lc]);
                bf[nt][1] = *reinterpret_cast<const unsigned*>(&Bs[s][n0][kb + 2 * lc + 8]);
            }
            #pragma unroll
            for (int mt = 0; mt < 2; mt++)
                #pragma unroll
                for (int nt = 0; nt < 6; nt++)
                    mma_bf16(acc[mt][nt][0], acc[mt][nt][1],
                             acc[mt][nt][2], acc[mt][nt][3],
                             a[mt][0], a[mt][1], a[mt][2], a[mt][3],
                             bf[nt][0], bf[nt][1]);
        }
        __syncthreads();
    }

    float* Cf = reinterpret_cast<float*>(Cv);

    if constexpr (EPI == 2) {
        __shared__ float2 red[2][128];
        float rsum[2][2] = {{0.f,0.f},{0.f,0.f}};
        float rsq [2][2] = {{0.f,0.f},{0.f,0.f}};
        size_t dpx[2][2];

        #pragma unroll
        for (int mt = 0; mt < 2; mt++) {
            long long row0 = rowBase + wm * 32 + mt * 16 + lr;
            dpx[mt][0] = dest_pixel((int)row0) * 96;
            dpx[mt][1] = dest_pixel((int)(row0 + 8)) * 96;
            #pragma unroll
            for (int nt = 0; nt < 6; nt++) {
                int col = wn * 48 + nt * 8 + 2 * lc;
                float2 bb = *reinterpret_cast<const float2*>(&bias[col]);
                float2 r0v = *reinterpret_cast<const float2*>(&res[dpx[mt][0] + col]);
                float2 r1v = *reinterpret_cast<const float2*>(&res[dpx[mt][1] + col]);
                float x00 = r0v.x + acc[mt][nt][0] + bb.x;
                float x01 = r0v.y + acc[mt][nt][1] + bb.y;
                float x10 = r1v.x + acc[mt][nt][2] + bb.x;
                float x11 = r1v.y + acc[mt][nt][3] + bb.y;
                *reinterpret_cast<float2*>(&Cf[dpx[mt][0] + col]) = make_float2(x00, x01);
                *reinterpret_cast<float2*>(&Cf[dpx[mt][1] + col]) = make_float2(x10, x11);
                acc[mt][nt][0] = x00; acc[mt][nt][1] = x01;
                acc[mt][nt][2] = x10; acc[mt][nt][3] = x11;
                rsum[mt][0] += x00 + x01;  rsq[mt][0] += x00*x00 + x01*x01;
                rsum[mt][1] += x10 + x11;  rsq[mt][1] += x10*x10 + x11*x11;
            }
        }
        #pragma unroll
        for (int mt = 0; mt < 2; mt++)
            #pragma unroll
            for (int rr = 0; rr < 2; rr++) {
                rsum[mt][rr] += __shfl_xor_sync(0xffffffffu, rsum[mt][rr], 1);
                rsum[mt][rr] += __shfl_xor_sync(0xffffffffu, rsum[mt][rr], 2);
                rsq [mt][rr] += __shfl_xor_sync(0xffffffffu, rsq [mt][rr], 1);
                rsq [mt][rr] += __shfl_xor_sync(0xffffffffu, rsq [mt][rr], 2);
            }
        if (lc == 0) {
            #pragma unroll
            for (int mt = 0; mt < 2; mt++)
                #pragma unroll
                for (int rr = 0; rr < 2; rr++)
                    red[wn][wm * 32 + mt * 16 + lr + rr * 8] =
                        make_float2(rsum[mt][rr], rsq[mt][rr]);
        }
        __syncthreads();
        #pragma unroll
        for (int mt = 0; mt < 2; mt++) {
            #pragma unroll
            for (int rr = 0; rr < 2; rr++) {
                int rl = wm * 32 + mt * 16 + lr + rr * 8;
                float2 p0 = red[0][rl], p1 = red[1][rl];
                float mean = (p0.x + p1.x) * (1.0f / 96.0f);
                float var  = (p0.y + p1.y) * (1.0f / 96.0f) - mean * mean;
                float rstd = rsqrtf(var + 1e-5f);
                #pragma unroll
                for (int nt = 0; nt < 6; nt++) {
                    int col = wn * 48 + nt * 8 + 2 * lc;
                    float w0 = lnw[col], w1v = lnw[col + 1];
                    float b0 = lnb[col], b1v = lnb[col + 1];
                    float y0 = (acc[mt][nt][2 * rr]     - mean) * rstd * w0 + b0;
                    float y1 = (acc[mt][nt][2 * rr + 1] - mean) * rstd * w1v + b1v;
                    __nv_bfloat162 h = __floats2bfloat162_rn(y0, y1);
                    *reinterpret_cast<__nv_bfloat162*>(&lnout[dpx[mt][rr] + col]) = h;
                }
            }
        }
    }
}

// ---------------------------------------------------------------------------
// Fused MLP v3: 16x96 warp tiles, in-register gelu+repack, ping-pong weight
// prefetch, ldmatrix fragment loads.
// ---------------------------------------------------------------------------
constexpr int MKS = 104;

__global__ void __launch_bounds__(256, 2) mlp_kernel(
    const __nv_bfloat16* __restrict__ A, const float* __restrict__ b1,
    const float* __restrict__ b2, const float* __restrict__ x1,
    float* __restrict__ out)
{
    extern __shared__ __align__(16) __nv_bfloat16 dsm[];
    __nv_bfloat16* As  = dsm;                 // [128][MKS]
    __nv_bfloat16* Ws0 = dsm + 128 * MKS;     // [96][MKS]  (W1 chunks)
    __nv_bfloat16* Ws1 = Ws0 + 96 * MKS;      // [96][MKS]  (W2 chunks)

    const int tid  = threadIdx.x;
    const int wid  = tid >> 5;                // 0..7 -> rows wid*16..+16
    const int lane = tid & 31;
    const int lr   = lane >> 2;
    const int lc   = lane & 3;
    const long long rowBase = (long long)blockIdx.x * 128;
    const int r0w = wid * 16;
    const int rA = r0w + lr, rB = rA + 8;

    // ldmatrix per-lane offsets (in halves)
    const int aoff = ((lane & 7) + ((lane >> 3) & 1) * 8) * MKS + ((lane >> 4) & 1) * 8;
    const int boff = ((lane & 7) + ((lane >> 4) & 1) * 8) * MKS + ((lane >> 3) & 1) * 8;

    float acc_out[12][4];
    #pragma unroll
    for (int nt = 0; nt < 12; nt++)
        { acc_out[nt][0]=acc_out[nt][1]=acc_out[nt][2]=acc_out[nt][3]=0.f; }

    // group 0: A tile (128x96 halves = 1536 chunks)
    #pragma unroll
    for (int i = 0; i < 6; i++) {
        int ch = i * 256 + tid;
        int r = ch / 12, ck = ch % 12;
        cp_async16(&As[r * MKS + ck * 8], A + (rowBase + r) * 96 + ck * 8);
    }
    cp_commit();
    // group 1: W1 chunk 0
    for (int ch = tid; ch < 1152; ch += 256) {
        int r = ch / 12, ck = ch % 12;
        cp_async16(&Ws0[r * MKS + ck * 8], g_w1 + r * 96 + ck * 8);
    }
    cp_commit();

    for (int c = 0; c < 4; c++) {
        // prefetch W2 chunk c -> Ws1
        for (int ch = tid; ch < 1152; ch += 256) {
            int r = ch / 12, ck = ch % 12;
            cp_async16(&Ws1[r * MKS + ck * 8], g_w2 + r * 384 + c * 96 + ck * 8);
        }
        cp_commit();
        cp_wait<1>();            // A + W1c done (W2c outstanding)
        __syncthreads();

        // GEMM1: acc1 = A @ W1c^T  (warp: 16 rows x 96 cols, ldmatrix loads)
        float acc1[12][4];
        #pragma unroll
        for (int nt = 0; nt < 12; nt++)
            { acc1[nt][0]=acc1[nt][1]=acc1[nt][2]=acc1[nt][3]=0.f; }
        #pragma unroll
        for (int kb = 0; kb < 96; kb += 16) {
            unsigned a0, a1, a2, a3;
            ldsm_x4(a0, a1, a2, a3, &As[r0w * MKS + aoff + kb]);
            #pragma unroll
            for (int p = 0; p < 6; p++) {
                unsigned b0, b1, b2, b3;
                ldsm_x4(b0, b1, b2, b3, &Ws0[p * 16 * MKS + boff + kb]);
                mma_bf16(acc1[2*p][0], acc1[2*p][1], acc1[2*p][2], acc1[2*p][3],
                         a0, a1, a2, a3, b0, b1);
                mma_bf16(acc1[2*p+1][0], acc1[2*p+1][1], acc1[2*p+1][2], acc1[2*p+1][3],
                         a0, a1, a2, a3, b2, b3);
            }
        }

        // bias + gelu in registers, repack C-frags -> A-frags (P)
        unsigned P[6][4];
        #pragma unroll
        for (int nt = 0; nt < 12; nt++) {
            float2 bb = *reinterpret_cast<const float2*>(&b1[c * 96 + nt * 8 + 2 * lc]);
            acc1[nt][0] = gelu_exact(acc1[nt][0] + bb.x);
            acc1[nt][1] = gelu_exact(acc1[nt][1] + bb.y);
            acc1[nt][2] = gelu_exact(acc1[nt][2] + bb.x);
            acc1[nt][3] = gelu_exact(acc1[nt][3] + bb.y);
        }
        #pragma unroll
        for (int kc = 0; kc < 6; kc++) {
            P[kc][0] = pack_bf162(acc1[2 * kc][0],     acc1[2 * kc][1]);
            P[kc][1] = pack_bf162(acc1[2 * kc][2],     acc1[2 * kc][3]);
            P[kc][2] = pack_bf162(acc1[2 * kc + 1][0], acc1[2 * kc + 1][1]);
            P[kc][3] = pack_bf162(acc1[2 * kc + 1][2], acc1[2 * kc + 1][3]);
        }

        __syncthreads();         // all warps done with Ws0 (W1c)
        if (c < 3) {             // prefetch W1 chunk c+1 -> Ws0
            for (int ch = tid; ch < 1152; ch += 256) {
                int r = ch / 12, ck = ch % 12;
                cp_async16(&Ws0[r * MKS + ck * 8],
                           g_w1 + ((c + 1) * 96 + r) * 96 + ck * 8);
            }
            cp_commit();
            cp_wait<1>();        // W2c done (W1c+1 outstanding)
        } else {
            cp_wait<0>();
        }
        __syncthreads();         // W2c visible

        // GEMM2: acc_out += gelu(h) @ W2c^T (ldmatrix B loads)
        #pragma unroll
        for (int kc = 0; kc < 6; kc++) {
            int kb = kc * 16;
            #pragma unroll
            for (int p = 0; p < 6; p++) {
                unsigned b0, b1, b2, b3;
                ldsm_x4(b0, b1, b2, b3, &Ws1[p * 16 * MKS + boff + kb]);
                mma_bf16(acc_out[2*p][0], acc_out[2*p][1], acc_out[2*p][2], acc_out[2*p][3],
                         P[kc][0], P[kc][1], P[kc][2], P[kc][3], b0, b1);
                mma_bf16(acc_out[2*p+1][0], acc_out[2*p+1][1], acc_out[2*p+1][2], acc_out[2*p+1][3],
                         P[kc][0], P[kc][1], P[kc][2], P[kc][3], b2, b3);
            }
        }
        __syncthreads();         // Ws1 free for next chunk
    }

    // epilogue: out = acc_out + b2 + x1 (fp32)
    const long long row0 = rowBase + rA;
    const long long row1 = rowBase + rB;
    #pragma unroll
    for (int nt = 0; nt < 12; nt++) {
        int col = nt * 8 + 2 * lc;
        float2 bb = *reinterpret_cast<const float2*>(&b2[col]);
        float2 r0v = *reinterpret_cast<const float2*>(&x1[row0 * 96 + col]);
        float2 r1v = *reinterpret_cast<const float2*>(&x1[row1 * 96 + col]);
        *reinterpret_cast<float2*>(&out[row0 * 96 + col]) =
            make_float2(r0v.x + acc_out[nt][0] + bb.x,
                        r0v.y + acc_out[nt][1] + bb.y);
        *reinterpret_cast<float2*>(&out[row1 * 96 + col]) =
            make_float2(r1v.x + acc_out[nt][2] + bb.x,
                        r1v.y + acc_out[nt][3] + bb.y);
    }
}

// ---------------------------------------------------------------------------
// MEGA front half: LN1 + QKV GEMM (double-buffered weights, ldmatrix) +
// attention (ldmatrix). Same smem layout as passing round 16.
// ---------------------------------------------------------------------------
__device__ __forceinline__ int regid(int g)
{
    return g < 248 ? 0 : (g < 252 ? 1 : 2);
}

constexpr int ATT_SMEM = 100864;

__global__ void __launch_bounds__(384, 2) attn_kernel(
    const float* __restrict__ x, const float* __restrict__ n1w,
    const float* __restrict__ n1b, const float* __restrict__ qkv_b,
    const float* __restrict__ rpb, __nv_bfloat16* __restrict__ ow)
{
    extern __shared__ __align__(16) __nv_bfloat16 dsm[];
    __nv_bfloat16* As  = dsm;                   // [64][104]
    __nv_bfloat16* Ws0 = As + 6656;             // [96][104]
    __nv_bfloat16* Ws1 = Ws0 + 9984;            // [96][104]
    __nv_bfloat16* Qs  = Ws1 + 9984;            // [3][64][40]
    __nv_bfloat16* Ks  = Qs + 7680;             // [3][64][40]
    __nv_bfloat16* Vt  = Ks + 7680;             // [3][32][72]
    float*         rpbs = reinterpret_cast<float*>(Vt + 6912);   // [3][225]
    int*           ids  = reinterpret_cast<int*>(rpbs + 675);    // [64]

    const int b_  = blockIdx.x;
    const int tid = threadIdx.x;
    const int wid = tid >> 5, lane = tid & 31;
    const int lr  = lane >> 2, lc = lane & 3;

    // ldmatrix per-lane offsets (halves) for strides 104 / 40 / 72
    const int l7 = lane & 7, g3 = (lane >> 3) & 1, g4 = (lane >> 4) & 1;
    const int aoff104 = (l7 + g3 * 8) * 104 + g4 * 8;
    const int boff104 = (l7 + g4 * 8) * 104 + g3 * 8;
    const int aoff40  = (l7 + g3 * 8) * 40  + g4 * 8;
    const int boff40  = (l7 + g4 * 8) * 40  + g3 * 8;
    const int voff72  = (l7 + g4 * 8) * 72  + g3 * 8;

    // prefetch W chunk 0 (Q weights) immediately -> hidden under LN1
    for (int ch = tid; ch < 1152; ch += 384) {
        int r = ch / 12, ck = ch % 12;
        cp_async16(&Ws0[r * 104 + ck * 8], g_wq + r * 96 + ck * 8);
    }
    cp_commit();

    // rpb table + region ids
    for (int t = tid; t < 675; t += 384)
        rpbs[t] = rpb[(t % 225) * 3 + t / 225];
    const int whc = (b_ >> 5) & 31, wwc = b_ & 31;
    if (tid < 64) {
        int i = tid >> 3, j = tid & 7;
        ids[tid] = regid(whc * 8 + i) * 3 + regid(wwc * 8 + j);
    }

    // ---- phase 1: LN1 (warp per row, gathered from pixel order)
    const int bb_ = b_ >> 10;
    for (int r = wid; r < 64; r += 12) {
        int i = r >> 3, j = r & 7;
        int hh = (whc * 8 + i + 4) & 255;
        int wp = (wwc * 8 + j + 4) & 255;
        size_t src = ((size_t)bb_ * 65536 + (size_t)hh * 256 + wp) * 96;
        float v0 = x[src + lane], v1 = x[src + lane + 32], v2 = x[src + lane + 64];
        float s = v0 + v1 + v2;
        #pragma unroll
        for (int o = 16; o > 0; o >>= 1) s += __shfl_xor_sync(0xffffffffu, s, o);
        float mean = s * (1.0f / 96.0f);
        float d0 = v0 - mean, d1 = v1 - mean, d2 = v2 - mean;
        float vv = d0 * d0 + d1 * d1 + d2 * d2;
        #pragma unroll
        for (int o = 16; o > 0; o >>= 1) vv += __shfl_xor_sync(0xffffffffu, vv, o);
        float rstd = rsqrtf(vv * (1.0f / 96.0f) + 1e-5f);
        As[r * 104 + lane]      = __float2bfloat16(d0 * rstd * n1w[lane]      + n1b[lane]);
        As[r * 104 + lane + 32] = __float2bfloat16(d1 * rstd * n1w[lane + 32] + n1b[lane + 32]);
        As[r * 104 + lane + 64] = __float2bfloat16(d2 * rstd * n1w[lane + 64] + n1b[lane + 64]);
    }
    __syncthreads();               // As / rpbs / ids visible

    // ---- phase 2: QKV GEMM, 3 chunks, ping-pong weight buffers, ldmatrix
    const int gm = (wid & 3) * 16;
    const int gh = wid >> 2;
    const int rA = gm + lr, rB = rA + 8;

    for (int c = 0; c < 3; c++) {
        if (c < 2) {
            __nv_bfloat16* Wn = ((c + 1) & 1) ? Ws1 : Ws0;
            for (int ch = tid; ch < 1152; ch += 384) {
                int r = ch / 12, ck = ch % 12;
                cp_async16(&Wn[r * 104 + ck * 8],
                           g_wq + ((c + 1) * 96 + r) * 96 + ck * 8);
            }
            cp_commit();
            cp_wait<1>();
        } else {
            cp_wait<0>();
        }
        __syncthreads();           // chunk c visible

        const __nv_bfloat16* W = (c & 1) ? Ws1 : Ws0;
        float acc[4][4];
        #pragma unroll
        for (int nt = 0; nt < 4; nt++) { acc[nt][0]=acc[nt][1]=acc[nt][2]=acc[nt][3]=0.f; }
        #pragma unroll
        for (int kb = 0; kb < 96; kb += 16) {
            unsigned a0, a1, a2, a3;
            ldsm_x4(a0, a1, a2, a3, &As[gm * 104 + aoff104 + kb]);
            #pragma unroll
            for (int p = 0; p < 2; p++) {
                unsigned b0, b1, b2, b3;
                ldsm_x4(b0, b1, b2, b3, &W[(gh * 32 + p * 16) * 104 + boff104 + kb]);
                mma_bf16(acc[2*p][0], acc[2*p][1], acc[2*p][2], acc[2*p][3],
                         a0, a1, a2, a3, b0, b1);
                mma_bf16(acc[2*p+1][0], acc[2*p+1][1], acc[2*p+1][2], acc[2*p+1][3],
                         a0, a1, a2, a3, b2, b3);
            }
        }

        #pragma unroll
        for (int nt = 0; nt < 4; nt++) {
            int d = nt * 8 + 2 * lc;
            float2 bb = *reinterpret_cast<const float2*>(&qkv_b[c * 96 + gh * 32 + d]);
            float v00 = acc[nt][0] + bb.x, v01 = acc[nt][1] + bb.y;
            float v10 = acc[nt][2] + bb.x, v11 = acc[nt][3] + bb.y;
            if (c == 0) {
                *reinterpret_cast<__nv_bfloat162*>(&Qs[gh * 2560 + rA * 40 + d]) =
                    __floats2bfloat162_rn(v00, v01);
                *reinterpret_cast<__nv_bfloat162*>(&Qs[gh * 2560 + rB * 40 + d]) =
                    __floats2bfloat162_rn(v10, v11);
            } else if (c == 1) {
                *reinterpret_cast<__nv_bfloat162*>(&Ks[gh * 2560 + rA * 40 + d]) =
                    __floats2bfloat162_rn(v00, v01);
                *reinterpret_cast<__nv_bfloat162*>(&Ks[gh * 2560 + rB * 40 + d]) =
                    __floats2bfloat162_rn(v10, v11);
            } else {
                Vt[gh * 2304 + d * 72 + rA]       = __float2bfloat16(v00);
                Vt[gh * 2304 + (d + 1) * 72 + rA] = __float2bfloat16(v01);
                Vt[gh * 2304 + d * 72 + rB]       = __float2bfloat16(v10);
                Vt[gh * 2304 + (d + 1) * 72 + rB] = __float2bfloat16(v11);
            }
        }
        __syncthreads();           // GEMM(c) done -> its buffer safe to refill
    }

    // ---- phase 3: attention (ldmatrix loads; logic identical to r13-16)
    const int hg = wid >> 2, ww = wid & 3;
    const int r0 = ww * 16;
    const int ra = r0 + lr, rb = ra + 8;
    const float scale = 0.17677669529663687f;

    unsigned qf[2][4];
    ldsm_x4(qf[0][0], qf[0][1], qf[0][2], qf[0][3],
            &Qs[hg * 2560 + r0 * 40 + aoff40]);
    ldsm_x4(qf[1][0], qf[1][1], qf[1][2], qf[1][3],
            &Qs[hg * 2560 + r0 * 40 + aoff40 + 16]);

    float S[8][4];
    #pragma unroll
    for (int nt = 0; nt < 8; nt++) { S[nt][0]=S[nt][1]=S[nt][2]=S[nt][3]=0.f; }
    #pragma unroll
    for (int kc = 0; kc < 2; kc++) {
        int kb = kc * 16;
        #pragma unroll
        for (int p = 0; p < 4; p++) {
            unsigned b0, b1, b2, b3;
            ldsm_x4(b0, b1, b2, b3, &Ks[hg * 2560 + p * 16 * 40 + boff40 + kb]);
            mma_bf16(S[2*p][0], S[2*p][1], S[2*p][2], S[2*p][3],
                     qf[kc][0], qf[kc][1], qf[kc][2], qf[kc][3], b0, b1);
            mma_bf16(S[2*p+1][0], S[2*p+1][1], S[2*p+1][2], S[2*p+1][3],
                     qf[kc][0], qf[kc][1], qf[kc][2], qf[kc][3], b2, b3);
        }
    }

    const int i_a = ra >> 3, j_a = ra & 7;
    const int i_b = rb >> 3, j_b = rb & 7;
    const int id_a = ids[ra], id_b = ids[rb];
    float mxa = -1e30f, mxb = -1e30f;
    #pragma unroll
    for (int nt = 0; nt < 8; nt++) {
        #pragma unroll
        for (int e = 0; e < 2; e++) {
            int cc = nt * 8 + 2 * lc + e;
            int ic = cc >> 3, jc = cc & 7;
            int idc = ids[cc];
            float ba = rpbs[hg * 225 + (i_a - ic + 7) * 15 + (j_a - jc + 7)]
                     + (id_a == idc ? 0.0f : -100.0f);
            float bb = rpbs[hg * 225 + (i_b - ic + 7) * 15 + (j_b - jc + 7)]
                     + (id_b == idc ? 0.0f : -100.0f);
            S[nt][e]     = fmaf(S[nt][e],     scale, ba);
            S[nt][2 + e] = fmaf(S[nt][2 + e], scale, bb);
            mxa = fmaxf(mxa, S[nt][e]);
            mxb = fmaxf(mxb, S[nt][2 + e]);
        }
    }
    mxa = fmaxf(mxa, __shfl_xor_sync(0xffffffffu, mxa, 1));
    mxa = fmaxf(mxa, __shfl_xor_sync(0xffffffffu, mxa, 2));
    mxb = fmaxf(mxb, __shfl_xor_sync(0xffffffffu, mxb, 1));
    mxb = fmaxf(mxb, __shfl_xor_sync(0xffffffffu, mxb, 2));

    float sa = 0.0f, sb = 0.0f;
    #pragma unroll
    for (int nt = 0; nt < 8; nt++) {
        #pragma unroll
        for (int e = 0; e < 2; e++) {
            float pa = fast_exp(S[nt][e] - mxa);
            float pb = fast_exp(S[nt][2 + e] - mxb);
            S[nt][e] = pa;  S[nt][2 + e] = pb;
            sa += pa;  sb += pb;
        }
    }
    sa += __shfl_xor_sync(0xffffffffu, sa, 1);
    sa += __shfl_xor_sync(0xffffffffu, sa, 2);
    sb += __shfl_xor_sync(0xffffffffu, sb, 1);
    sb += __shfl_xor_sync(0xffffffffu, sb, 2);
    float inva = 1.0f / sa, invb = 1.0f / sb;

    unsigned P[4][4];
    #pragma unroll
    for (int kc = 0; kc < 4; kc++) {
        P[kc][0] = pack_bf162(S[2 * kc][0],     S[2 * kc][1]);
        P[kc][1] = pack_bf162(S[2 * kc][2],     S[2 * kc][3]);
        P[kc][2] = pack_bf162(S[2 * kc + 1][0], S[2 * kc + 1][1]);
        P[kc][3] = pack_bf162(S[2 * kc + 1][2], S[2 * kc + 1][3]);
    }

    float O[4][4];
    #pragma unroll
    for (int dt = 0; dt < 4; dt++) { O[dt][0]=O[dt][1]=O[dt][2]=O[dt][3]=0.f; }
    #pragma unroll
    for (int kc = 0; kc < 4; kc++) {
        int j0 = kc * 16;
        #pragma unroll
        for (int p = 0; p < 2; p++) {
            unsigned b0, b1, b2, b3;
            ldsm_x4(b0, b1, b2, b3, &Vt[hg * 2304 + p * 16 * 72 + voff72 + j0]);
            mma_bf16(O[2*p][0], O[2*p][1], O[2*p][2], O[2*p][3],
                     P[kc][0], P[kc][1], P[kc][2], P[kc][3], b0, b1);
            mma_bf16(O[2*p+1][0], O[2*p+1][1], O[2*p+1][2], O[2*p+1][3],
                     P[kc][0], P[kc][1], P[kc][2], P[kc][3], b2, b3);
        }
    }

    size_t obase = (size_t)b_ * 64 * 96 + hg * 32;
    #pragma unroll
    for (int dt = 0; dt < 4; dt++) {
        int d = dt * 8 + 2 * lc;
        *reinterpret_cast<__nv_bfloat162*>(&ow[obase + (size_t)ra * 96 + d]) =
            __floats2bfloat162_rn(O[dt][0] * inva, O[dt][1] * inva);
        *reinterpret_cast<__nv_bfloat162*>(&ow[obase + (size_t)rb * 96 + d]) =
            __floats2bfloat162_rn(O[dt][2] * invb, O[dt][3] * invb);
    }
}

// ---------------------------------------------------------------------------
// launch
// ---------------------------------------------------------------------------
extern "C" void kernel_launch(void* const* d_in, const int* in_sizes, int n_in,
                              void* d_out, int out_size)
{
    const float* x      = (const float*)d_in[0];
    const float* n1w    = (const float*)d_in[1];
    const float* n1b    = (const float*)d_in[2];
    const float* qkv_w  = (const float*)d_in[3];
    const float* qkv_b  = (const float*)d_in[4];
    const float* rpb    = (const float*)d_in[5];
    const float* proj_w = (const float*)d_in[6];
    const float* proj_b = (const float*)d_in[7];
    const float* n2w    = (const float*)d_in[8];
    const float* n2b    = (const float*)d_in[9];
    const float* w1     = (const float*)d_in[10];
    const float* b1     = (const float*)d_in[11];
    const float* w2     = (const float*)d_in[12];
    const float* b2     = (const float*)d_in[13];
    float* out = (float*)d_out;

    __nv_bfloat16 *ap, *bp, *wp;
    float *x1p;
    cudaGetSymbolAddress((void**)&ap,  g_a);
    cudaGetSymbolAddress((void**)&bp,  g_b);
    cudaGetSymbolAddress((void**)&x1p, g_x1);
    cudaGetSymbolAddress((void**)&wp,  g_wp);

    const int mlp_smem = (128 + 192) * MKS * (int)sizeof(__nv_bfloat16);  // 66560
    cudaFuncSetAttribute(mlp_kernel,
                         cudaFuncAttributeMaxDynamicSharedMemorySize, mlp_smem);
    cudaFuncSetAttribute(attn_kernel,
                         cudaFuncAttributeMaxDynamicSharedMemorySize, ATT_SMEM);

    // 0. weights -> bf16
    cvt_all<<<144, 256>>>(qkv_w, proj_w, w1, w2);
    // 1. MEGA front half: LN1 + QKV + attention   x -> g_b (bf16)
    attn_kernel<<<8192, 384, ATT_SMEM>>>(x, n1w, n1b, qkv_b, rpb, bp);
    // 2. proj + scatter + residual -> x1 (fp32), fused LN2 -> g_a (bf16)
    hgemm_kernel<2><<<dim3(4096, 1), 256>>>(bp, wp, proj_b, x1p, x, 96, 96,
                                            n2w, n2b, ap);
    // 3. fused MLP v3: out = x1 + gelu(g_a @ W1^T + b1) @ W2^T + b2
    mlp_kernel<<<4096, 256, mlp_smem>>>(ap, b1, b2, x1p, out);
}